// round 7
// baseline (speedup 1.0000x reference)
#include <cuda_runtime.h>
#include <cuda_bf16.h>

#define NTHREADS 256
#define ETHREADS 320
#define EWARPS   10
#define TILE_E   (EWARPS * 16)
#define NMAX 50000

// Scratch (device globals: allocation-free rule)
__device__ float g_A[NMAX * 128];    // h @ eW1[0:128]   gathered by row
__device__ float g_B[NMAX * 128];    // h @ eW1[128:256] gathered by col
__device__ float g_agg[NMAX * 128];  // segment_sum(m2, row)
__device__ int   g_is64;             // edge_index dtype flag

__device__ __forceinline__ float silu(float x) { return x / (1.0f + __expf(-x)); }
__device__ __forceinline__ unsigned smem_u32(const void* p) {
    unsigned a;
    asm("{ .reg .u64 t; cvta.to.shared.u64 t, %1; cvt.u32.u64 %0, t; }" : "=r"(a) : "l"(p));
    return a;
}
// packed fp32x2 FMA: d = a*b + d
__device__ __forceinline__ void ffma2(unsigned long long& d,
                                      unsigned long long a, unsigned long long b) {
    asm("fma.rn.f32x2 %0, %1, %2, %0;" : "+l"(d) : "l"(a), "l"(b));
}
__device__ __forceinline__ float hsum2(unsigned long long v) {
    float lo = __uint_as_float((unsigned)(v & 0xffffffffull));
    float hi = __uint_as_float((unsigned)(v >> 32));
    return lo + hi;
}
// pack two fp32 into bf16-hi pair / bf16-lo pair
__device__ __forceinline__ void hilo2(float v0, float v1, unsigned& hp, unsigned& lp) {
    __nv_bfloat16 h0 = __float2bfloat16(v0), h1 = __float2bfloat16(v1);
    __nv_bfloat16 l0 = __float2bfloat16(v0 - __bfloat162float(h0));
    __nv_bfloat16 l1 = __float2bfloat16(v1 - __bfloat162float(h1));
    hp = (unsigned)__bfloat16_as_ushort(h0) | ((unsigned)__bfloat16_as_ushort(h1) << 16);
    lp = (unsigned)__bfloat16_as_ushort(l0) | ((unsigned)__bfloat16_as_ushort(l1) << 16);
}
__device__ __forceinline__ void ldsm4(unsigned r[4], unsigned addr) {
    asm volatile("ldmatrix.sync.aligned.m8n8.x4.shared.b16 {%0,%1,%2,%3}, [%4];"
                 : "=r"(r[0]), "=r"(r[1]), "=r"(r[2]), "=r"(r[3]) : "r"(addr));
}
__device__ __forceinline__ void mma_bf16(float d[4], const unsigned a[4], unsigned b0, unsigned b1) {
    asm volatile("mma.sync.aligned.m16n8k16.row.col.f32.bf16.bf16.f32 "
                 "{%0,%1,%2,%3}, {%4,%5,%6,%7}, {%8,%9}, {%0,%1,%2,%3};"
                 : "+f"(d[0]), "+f"(d[1]), "+f"(d[2]), "+f"(d[3])
                 : "r"(a[0]), "r"(a[1]), "r"(a[2]), "r"(a[3]), "r"(b0), "r"(b1));
}
__device__ __forceinline__ void red2(float* p, float v0, float v1) {
    asm volatile("red.global.add.v2.f32 [%0], {%1, %2};" :: "l"(p), "f"(v0), "f"(v1) : "memory");
}

// warp-level 16x128x128 GEMM, bf16 hi/lo 3-term fp32 emulation.
// Term-major issue order: each accumulator is revisited only every 16 MMAs,
// eliminating HMMA RAW chains (the R5/R6 stall source).
__device__ __forceinline__ void warp_gemm(unsigned aHi, unsigned aLo,
                                          unsigned bHi, unsigned bLo,
                                          unsigned aoff, unsigned boff, float (*d)[4]) {
    #pragma unroll
    for (int ks = 0; ks < 8; ks++) {
        unsigned ah[4], al[4];
        ldsm4(ah, aHi + aoff + ks * 32);
        ldsm4(al, aLo + aoff + ks * 32);
        unsigned b[8][4];
        #pragma unroll
        for (int np = 0; np < 8; np++)
            ldsm4(b[np], bHi + boff + np * 4352 + ks * 32);
        #pragma unroll
        for (int np = 0; np < 8; np++) {           // Ahi * Bhi
            mma_bf16(d[np * 2],     ah, b[np][0], b[np][1]);
            mma_bf16(d[np * 2 + 1], ah, b[np][2], b[np][3]);
        }
        #pragma unroll
        for (int np = 0; np < 8; np++) {           // Alo * Bhi
            mma_bf16(d[np * 2],     al, b[np][0], b[np][1]);
            mma_bf16(d[np * 2 + 1], al, b[np][2], b[np][3]);
        }
        #pragma unroll
        for (int np = 0; np < 8; np++)
            ldsm4(b[np], bLo + boff + np * 4352 + ks * 32);
        #pragma unroll
        for (int np = 0; np < 8; np++) {           // Ahi * Blo
            mma_bf16(d[np * 2],     ah, b[np][0], b[np][1]);
            mma_bf16(d[np * 2 + 1], ah, b[np][2], b[np][3]);
        }
    }
}

// SMEM byte layout for edge kernel
#define W2HI_B 4096
#define W2LO_B 38912
#define C1HI_B 73728
#define C1LO_B 108544
#define AT_B   143360     // EWARPS x (hi 4352 + lo 4352)
#define EDGE_SMEM (AT_B + EWARPS * 8704)

// ---------------------------------------------------------------------------
__global__ void detect_kernel(const void* __restrict__ ei, int N, int E) {
    __shared__ int ok;
    if (threadIdx.x == 0) ok = 1;
    __syncthreads();
    int n = (E < 256) ? E : 256;
    if ((int)threadIdx.x < n) {
        long long v = ((const long long*)ei)[threadIdx.x];
        if (v < 0 || v >= (long long)N) atomicExch(&ok, 0);
    }
    __syncthreads();
    if (threadIdx.x == 0) g_is64 = ok;
}

__global__ void init_kernel(const float* __restrict__ pos, float* __restrict__ pos_out, int N) {
    int i = blockIdx.x * blockDim.x + threadIdx.x;
    if (i < N * 128) g_agg[i] = 0.0f;
    if (i < N * 3) pos_out[i] = pos[i];
}

// ---------------------------------------------------------------------------
// precompute: A = h @ eW1[0:128,:], B = h @ eW1[128:256,:]  (f32x2 microkernel)
// ---------------------------------------------------------------------------
#define PRE_SMEM ((64 * 132 + 16896) * 4)
__global__ __launch_bounds__(NTHREADS) void pre_kernel(
    const float* __restrict__ h, const float* __restrict__ eW1, int N)
{
    extern __shared__ float sm[];
    float* h_sm = sm;              // 64 * 132
    float* wt   = sm + 64 * 132;   // 128 * 132 transposed [out][k]

    int tid = threadIdx.x;
    int n0 = blockIdx.x * 64;
    for (int idx = tid; idx < 64 * 128; idx += NTHREADS) {
        int e = idx >> 7, k = idx & 127;
        int node = n0 + e;
        h_sm[e * 132 + k] = (node < N) ? h[node * 128 + k] : 0.0f;
    }
    int wid = tid >> 5, lane = tid & 31, ebase = wid * 8;
    const ulonglong2* Hu = (const ulonglong2*)h_sm;   // row stride 33
    const ulonglong2* Wu = (const ulonglong2*)wt;

    for (int half = 0; half < 2; half++) {
        __syncthreads();
        for (int i = tid; i < 16384; i += NTHREADS) {
            int k = i >> 7, o = i & 127;
            wt[o * 132 + k] = eW1[half * 16384 + i];
        }
        __syncthreads();
        unsigned long long acc[8][4];
        #pragma unroll
        for (int e = 0; e < 8; e++)
            #pragma unroll
            for (int j = 0; j < 4; j++) acc[e][j] = 0ull;
        #pragma unroll 4
        for (int c = 0; c < 32; c++) {
            ulonglong2 w0 = Wu[(0 * 32 + lane) * 33 + c];
            ulonglong2 w1 = Wu[(1 * 32 + lane) * 33 + c];
            ulonglong2 w2 = Wu[(2 * 32 + lane) * 33 + c];
            ulonglong2 w3 = Wu[(3 * 32 + lane) * 33 + c];
            #pragma unroll
            for (int e = 0; e < 8; e++) {
                ulonglong2 mv = Hu[(ebase + e) * 33 + c];
                ffma2(acc[e][0], mv.x, w0.x); ffma2(acc[e][0], mv.y, w0.y);
                ffma2(acc[e][1], mv.x, w1.x); ffma2(acc[e][1], mv.y, w1.y);
                ffma2(acc[e][2], mv.x, w2.x); ffma2(acc[e][2], mv.y, w2.y);
                ffma2(acc[e][3], mv.x, w3.x); ffma2(acc[e][3], mv.y, w3.y);
            }
        }
        float* dst = (half == 0) ? g_A : g_B;
        #pragma unroll
        for (int e = 0; e < 8; e++) {
            int node = n0 + ebase + e;
            if (node < N)
                #pragma unroll
                for (int j = 0; j < 4; j++)
                    dst[node * 128 + j * 32 + lane] = hsum2(acc[e][j]);
        }
    }
}

// ---------------------------------------------------------------------------
// fused edge kernel: warp-private mma.sync bf16 hi/lo pipeline, 160 edges/tile
// ---------------------------------------------------------------------------
__global__ __launch_bounds__(ETHREADS) void edge_kernel(
    const float* __restrict__ pos, const float* __restrict__ edge_attr,
    const void* __restrict__ ei_raw,
    const float* __restrict__ eW1, const float* __restrict__ eb1,
    const float* __restrict__ eW2, const float* __restrict__ eb2,
    const float* __restrict__ cW1, const float* __restrict__ cb1,
    const float* __restrict__ cW2, const float* __restrict__ cb2,
    float* __restrict__ pos_out, int N, int E)
{
    extern __shared__ float smf[];
    char* smc = (char*)smf;
    unsigned sbase = smem_u32(smf);
    int tid = threadIdx.x, wid = tid >> 5, lane = tid & 31;
    int g = lane >> 3, l = lane & 7;
    int qm = lane >> 2, qk = lane & 3;      // D-frag row / col-pair

    // sv: w_rn 0, w_ea 128, eb1 256, eb2 384, cb1 512, cw2 640, cb2 768
    float* sv = smf;
    for (int i = tid; i < 128; i += ETHREADS) {
        sv[i]       = eW1[256 * 128 + i];
        sv[128 + i] = eW1[257 * 128 + i];
        sv[256 + i] = eb1[i];
        sv[384 + i] = eb2[i];
        sv[512 + i] = cb1[i];
        sv[640 + i] = cW2[i];
    }
    if (tid == 0) sv[768] = cb2[0];

    // weights: B[o][k] = W[k][o], bf16 hi/lo, row stride 272B
    for (int idx = tid; idx < 16384; idx += ETHREADS) {
        int k = idx >> 7, o = idx & 127;
        unsigned off = (unsigned)(o * 272 + k * 2);
        float w = eW2[idx];
        __nv_bfloat16 hh = __float2bfloat16(w);
        *(__nv_bfloat16*)(smc + W2HI_B + off) = hh;
        *(__nv_bfloat16*)(smc + W2LO_B + off) = __float2bfloat16(w - __bfloat162float(hh));
        w = cW1[idx];
        hh = __float2bfloat16(w);
        *(__nv_bfloat16*)(smc + C1HI_B + off) = hh;
        *(__nv_bfloat16*)(smc + C1LO_B + off) = __float2bfloat16(w - __bfloat162float(hh));
    }
    __syncthreads();

    float cb2v = sv[768];
    int is64 = g_is64;
    const long long* ei64 = (const long long*)ei_raw;
    const int*       ei32 = (const int*)ei_raw;

    // per-lane phase1 constants (cols lane*4 .. +3)
    float4 wr = *(const float4*)&sv[lane * 4];
    float4 we = *(const float4*)&sv[128 + lane * 4];
    float4 bi = *(const float4*)&sv[256 + lane * 4];

    // per-warp A tile bases
    unsigned aHi = sbase + AT_B + wid * 8704;
    unsigned aLo = aHi + 4352;
    unsigned bW2h = sbase + W2HI_B, bW2l = sbase + W2LO_B;
    unsigned bC1h = sbase + C1HI_B, bC1l = sbase + C1LO_B;

    // ldmatrix lane offsets
    unsigned aoff = (unsigned)((l + ((g & 1) << 3)) * 272 + (g >> 1) * 16);
    unsigned boff = (unsigned)((l + ((g >> 1) << 3)) * 272 + (g & 1) * 16);

    int ntiles = (E + TILE_E - 1) / TILE_E;
    for (int t = blockIdx.x; t < ntiles; t += gridDim.x) {
        int e0w = t * TILE_E + wid * 16;     // this warp's first edge

        // --- meta (lanes 0..15 hold edge lane's data) ---
        int m_r = 0, m_c = 0;
        float m_rn = 1.0f, m_irn = 1.0f, m_ea = 0.0f, m_rx = 0.0f, m_ry = 0.0f, m_rz = 0.0f;
        if (lane < 16) {
            int e = e0w + lane;
            if (e < E) {
                int r, c;
                if (is64) { r = (int)ei64[e]; c = (int)ei64[E + e]; }
                else      { r = ei32[e];      c = ei32[E + e]; }
                r = min(max(r, 0), N - 1);
                c = min(max(c, 0), N - 1);
                float dx = pos[r * 3 + 0] - pos[c * 3 + 0];
                float dy = pos[r * 3 + 1] - pos[c * 3 + 1];
                float dz = pos[r * 3 + 2] - pos[c * 3 + 2];
                float nrm = sqrtf(dx * dx + dy * dy + dz * dz);
                float rn = fmaxf(nrm, 1e-8f);
                m_r = r; m_c = c; m_rn = rn; m_irn = 1.0f / rn;
                m_ea = edge_attr[e];
                m_rx = dx; m_ry = dy; m_rz = dz;
            }
        }

        // --- phase1: m = silu(A[row]+B[col]+rn*w_rn+ea*w_ea+eb1) -> hi/lo tile ---
        #pragma unroll
        for (int row = 0; row < 16; row++) {
            int rsrc = __shfl_sync(0xffffffffu, m_r, row);
            int csrc = __shfl_sync(0xffffffffu, m_c, row);
            float rn  = __shfl_sync(0xffffffffu, m_rn, row);
            float eav = __shfl_sync(0xffffffffu, m_ea, row);
            float4 a = *(const float4*)(g_A + rsrc * 128 + lane * 4);
            float4 b = *(const float4*)(g_B + csrc * 128 + lane * 4);
            float v0 = silu(fmaf(eav, we.x, fmaf(rn, wr.x, a.x + b.x)) + bi.x);
            float v1 = silu(fmaf(eav, we.y, fmaf(rn, wr.y, a.y + b.y)) + bi.y);
            float v2 = silu(fmaf(eav, we.z, fmaf(rn, wr.z, a.z + b.z)) + bi.z);
            float v3 = silu(fmaf(eav, we.w, fmaf(rn, wr.w, a.w + b.w)) + bi.w);
            unsigned hp0, hp1, lp0, lp1;
            hilo2(v0, v1, hp0, lp0); hilo2(v2, v3, hp1, lp1);
            unsigned off = (unsigned)(row * 272 + lane * 8);
            *(uint2*)(smc + (aHi - sbase) + off) = make_uint2(hp0, hp1);
            *(uint2*)(smc + (aLo - sbase) + off) = make_uint2(lp0, lp1);
        }
        __syncwarp();

        // --- GEMM2: D1 = m @ eW2 ---
        float d[16][4];
        #pragma unroll
        for (int i = 0; i < 16; i++) { d[i][0] = d[i][1] = d[i][2] = d[i][3] = 0.f; }
        warp_gemm(aHi, aLo, bW2h, bW2l, aoff, boff, d);

        // --- epilogue1: m2 = silu(D1 + eb2) -> tile (overwrite) + agg red.v2 ---
        int ri0 = __shfl_sync(0xffffffffu, m_r, qm);
        int ri8 = __shfl_sync(0xffffffffu, m_r, qm + 8);
        bool ok0 = (e0w + qm) < E, ok8 = (e0w + qm + 8) < E;
        float* ga0 = g_agg + ri0 * 128;
        float* ga8 = g_agg + ri8 * 128;
        #pragma unroll
        for (int nt = 0; nt < 16; nt++) {
            int o0 = nt * 8 + qk * 2;
            float e_0 = sv[384 + o0], e_1 = sv[384 + o0 + 1];
            float v0 = silu(d[nt][0] + e_0);
            float v1 = silu(d[nt][1] + e_1);
            float v2 = silu(d[nt][2] + e_0);
            float v3 = silu(d[nt][3] + e_1);
            unsigned hp, lp;
            hilo2(v0, v1, hp, lp);
            unsigned off = (unsigned)(qm * 272 + o0 * 2);
            *(unsigned*)(smc + (aHi - sbase) + off) = hp;
            *(unsigned*)(smc + (aLo - sbase) + off) = lp;
            hilo2(v2, v3, hp, lp);
            off = (unsigned)((qm + 8) * 272 + o0 * 2);
            *(unsigned*)(smc + (aHi - sbase) + off) = hp;
            *(unsigned*)(smc + (aLo - sbase) + off) = lp;
            if (ok0) red2(ga0 + o0, v0, v1);
            if (ok8) red2(ga8 + o0, v2, v3);
        }
        __syncwarp();

        // --- GEMM3: D2 = m2 @ cW1 ---
        #pragma unroll
        for (int i = 0; i < 16; i++) { d[i][0] = d[i][1] = d[i][2] = d[i][3] = 0.f; }
        warp_gemm(aHi, aLo, bC1h, bC1l, aoff, boff, d);

        // --- epilogue2: coord = silu(D2 + cb1) . cW2; pos atomics ---
        float pA = 0.0f, pB = 0.0f;
        #pragma unroll
        for (int nt = 0; nt < 16; nt++) {
            int o0 = nt * 8 + qk * 2;
            float c_0 = sv[512 + o0], c_1 = sv[512 + o0 + 1];
            float w_0 = sv[640 + o0], w_1 = sv[640 + o0 + 1];
            pA = fmaf(silu(d[nt][0] + c_0), w_0, pA);
            pA = fmaf(silu(d[nt][1] + c_1), w_1, pA);
            pB = fmaf(silu(d[nt][2] + c_0), w_0, pB);
            pB = fmaf(silu(d[nt][3] + c_1), w_1, pB);
        }
        pA += __shfl_xor_sync(0xffffffffu, pA, 1);
        pA += __shfl_xor_sync(0xffffffffu, pA, 2);
        pB += __shfl_xor_sync(0xffffffffu, pB, 1);
        pB += __shfl_xor_sync(0xffffffffu, pB, 2);
        float irn0 = __shfl_sync(0xffffffffu, m_irn, qm);
        float irn8 = __shfl_sync(0xffffffffu, m_irn, qm + 8);
        float rx0 = __shfl_sync(0xffffffffu, m_rx, qm), rx8 = __shfl_sync(0xffffffffu, m_rx, qm + 8);
        float ry0 = __shfl_sync(0xffffffffu, m_ry, qm), ry8 = __shfl_sync(0xffffffffu, m_ry, qm + 8);
        float rz0 = __shfl_sync(0xffffffffu, m_rz, qm), rz8 = __shfl_sync(0xffffffffu, m_rz, qm + 8);
        if (qk == 0) {
            if (ok0) {
                float s = (pA + cb2v) * irn0;
                atomicAdd(&pos_out[ri0 * 3 + 0], s * rx0);
                atomicAdd(&pos_out[ri0 * 3 + 1], s * ry0);
                atomicAdd(&pos_out[ri0 * 3 + 2], s * rz0);
            }
            if (ok8) {
                float s = (pB + cb2v) * irn8;
                atomicAdd(&pos_out[ri8 * 3 + 0], s * rx8);
                atomicAdd(&pos_out[ri8 * 3 + 1], s * ry8);
                atomicAdd(&pos_out[ri8 * 3 + 2], s * rz8);
            }
        }
        __syncwarp();
    }
}

// ---------------------------------------------------------------------------
// node MLP (f32x2): hn = silu([h,agg] @ nW1 + nb1); h_new = h + hn @ nW2 + nb2
// ---------------------------------------------------------------------------
#define NODE_SMEM ((64 * 260 + 128 * 132 + 64 * 132) * 4)
__global__ __launch_bounds__(NTHREADS) void node_kernel(
    const float* __restrict__ h,
    const float* __restrict__ nW1, const float* __restrict__ nb1,
    const float* __restrict__ nW2, const float* __restrict__ nb2,
    float* __restrict__ h_out, int N)
{
    extern __shared__ float sm[];
    float* x_sm  = sm;                       // 64*260 (0..127 h, 128..255 agg)
    float* wt    = sm + 64 * 260;            // 128*132 transposed [out][k]
    float* hn_sm = sm + 64 * 260 + 128 * 132;// 64*132

    int tid = threadIdx.x, wid = tid >> 5, lane = tid & 31, ebase = wid * 8;
    int n0 = blockIdx.x * 64;
    for (int idx = tid; idx < 64 * 256; idx += NTHREADS) {
        int e = idx >> 8, k = idx & 255;
        int node = n0 + e;
        float v = 0.0f;
        if (node < N) v = (k < 128) ? h[node * 128 + k] : g_agg[node * 128 + (k - 128)];
        x_sm[e * 260 + k] = v;
    }
    const ulonglong2* Xu  = (const ulonglong2*)x_sm;   // row stride 65
    const ulonglong2* Wu  = (const ulonglong2*)wt;     // row stride 33
    const ulonglong2* Hnu = (const ulonglong2*)hn_sm;  // row stride 33

    unsigned long long acc[8][4];
    #pragma unroll
    for (int e = 0; e < 8; e++)
        #pragma unroll
        for (int j = 0; j < 4; j++) acc[e][j] = 0ull;

    for (int half = 0; half < 2; half++) {
        __syncthreads();
        for (int i = tid; i < 16384; i += NTHREADS) {
            int k = i >> 7, o = i & 127;
            wt[o * 132 + k] = nW1[half * 16384 + i];
        }
        __syncthreads();
        #pragma unroll 4
        for (int c = 0; c < 32; c++) {
            ulonglong2 w0 = Wu[(0 * 32 + lane) * 33 + c];
            ulonglong2 w1 = Wu[(1 * 32 + lane) * 33 + c];
            ulonglong2 w2 = Wu[(2 * 32 + lane) * 33 + c];
            ulonglong2 w3 = Wu[(3 * 32 + lane) * 33 + c];
            #pragma unroll
            for (int e = 0; e < 8; e++) {
                ulonglong2 mv = Xu[(ebase + e) * 65 + half * 32 + c];
                ffma2(acc[e][0], mv.x, w0.x); ffma2(acc[e][0], mv.y, w0.y);
                ffma2(acc[e][1], mv.x, w1.x); ffma2(acc[e][1], mv.y, w1.y);
                ffma2(acc[e][2], mv.x, w2.x); ffma2(acc[e][2], mv.y, w2.y);
                ffma2(acc[e][3], mv.x, w3.x); ffma2(acc[e][3], mv.y, w3.y);
            }
        }
    }
    #pragma unroll
    for (int e = 0; e < 8; e++)
        #pragma unroll
        for (int j = 0; j < 4; j++)
            hn_sm[(ebase + e) * 132 + j * 32 + lane] = silu(hsum2(acc[e][j]) + nb1[j * 32 + lane]);
    __syncthreads();
    for (int i = tid; i < 16384; i += NTHREADS) {
        int k = i >> 7, o = i & 127;
        wt[o * 132 + k] = nW2[i];
    }
    __syncthreads();

    #pragma unroll
    for (int e = 0; e < 8; e++)
        #pragma unroll
        for (int j = 0; j < 4; j++) acc[e][j] = 0ull;
    #pragma unroll 4
    for (int c = 0; c < 32; c++) {
        ulonglong2 w0 = Wu[(0 * 32 + lane) * 33 + c];
        ulonglong2 w1 = Wu[(1 * 32 + lane) * 33 + c];
        ulonglong2 w2 = Wu[(2 * 32 + lane) * 33 + c];
        ulonglong2 w3 = Wu[(3 * 32 + lane) * 33 + c];
        #pragma unroll
        for (int e = 0; e < 8; e++) {
            ulonglong2 mv = Hnu[(ebase + e) * 33 + c];
            ffma2(acc[e][0], mv.x, w0.x); ffma2(acc[e][0], mv.y, w0.y);
            ffma2(acc[e][1], mv.x, w1.x); ffma2(acc[e][1], mv.y, w1.y);
            ffma2(acc[e][2], mv.x, w2.x); ffma2(acc[e][2], mv.y, w2.y);
            ffma2(acc[e][3], mv.x, w3.x); ffma2(acc[e][3], mv.y, w3.y);
        }
    }
    #pragma unroll
    for (int e = 0; e < 8; e++) {
        int node = n0 + ebase + e;
        if (node < N) {
            #pragma unroll
            for (int j = 0; j < 4; j++) {
                int o = j * 32 + lane;
                float res = x_sm[(ebase + e) * 260 + o];
                h_out[node * 128 + o] = hsum2(acc[e][j]) + nb2[o] + res;
            }
        }
    }
}

// ---------------------------------------------------------------------------
extern "C" void kernel_launch(void* const* d_in, const int* in_sizes, int n_in,
                              void* d_out, int out_size)
{
    const float* h   = (const float*)d_in[0];
    const float* pos = (const float*)d_in[1];
    const float* ea  = (const float*)d_in[2];
    const void*  ei  = d_in[3];
    const float* eW1 = (const float*)d_in[4];
    const float* eb1 = (const float*)d_in[5];
    const float* eW2 = (const float*)d_in[6];
    const float* eb2 = (const float*)d_in[7];
    const float* nW1 = (const float*)d_in[8];
    const float* nb1 = (const float*)d_in[9];
    const float* nW2 = (const float*)d_in[10];
    const float* nb2 = (const float*)d_in[11];
    const float* cW1 = (const float*)d_in[12];
    const float* cb1 = (const float*)d_in[13];
    const float* cW2 = (const float*)d_in[14];
    const float* cb2 = (const float*)d_in[15];

    int N = in_sizes[0] / 128;
    int E = in_sizes[2];
    float* h_out   = (float*)d_out;
    float* pos_out = h_out + (size_t)N * 128;

    cudaFuncSetAttribute(pre_kernel,  cudaFuncAttributeMaxDynamicSharedMemorySize, PRE_SMEM);
    cudaFuncSetAttribute(edge_kernel, cudaFuncAttributeMaxDynamicSharedMemorySize, EDGE_SMEM);
    cudaFuncSetAttribute(node_kernel, cudaFuncAttributeMaxDynamicSharedMemorySize, NODE_SMEM);

    int nsm = 148;
    cudaDeviceGetAttribute(&nsm, cudaDevAttrMultiProcessorCount, 0);

    detect_kernel<<<1, 256>>>(ei, N, E);
    init_kernel<<<(N * 128 + 255) / 256, 256>>>(pos, pos_out, N);
    pre_kernel<<<(N + 63) / 64, NTHREADS, PRE_SMEM>>>(h, eW1, N);
    edge_kernel<<<nsm, ETHREADS, EDGE_SMEM>>>(pos, ea, ei, eW1, eb1, eW2, eb2,
                                              cW1, cb1, cW2, cb2, pos_out, N, E);
    node_kernel<<<(N + 63) / 64, NTHREADS, NODE_SMEM>>>(h, nW1, nb1, nW2, nb2, h_out, N);
}

// round 8
// speedup vs baseline: 1.9657x; 1.9657x over previous
#include <cuda_runtime.h>
#include <cuda_fp16.h>

#define NTHREADS 256
#define ETHREADS 512
#define EWARPS   16
#define TILE_E   (EWARPS * 16)
#define NMAX 50000

// Scratch (device globals: allocation-free rule)
__device__ float g_A[NMAX * 128];    // h @ eW1[0:128]   gathered by row
__device__ float g_B[NMAX * 128];    // h @ eW1[128:256] gathered by col
__device__ float g_agg[NMAX * 128];  // segment_sum(m2, row)
__device__ int   g_is64;             // edge_index dtype flag

__device__ __forceinline__ float silu(float x) { return x / (1.0f + __expf(-x)); }
__device__ __forceinline__ unsigned smem_u32(const void* p) {
    unsigned a;
    asm("{ .reg .u64 t; cvta.to.shared.u64 t, %1; cvt.u32.u64 %0, t; }" : "=r"(a) : "l"(p));
    return a;
}
// packed fp32x2 FMA: d = a*b + d
__device__ __forceinline__ void ffma2(unsigned long long& d,
                                      unsigned long long a, unsigned long long b) {
    asm("fma.rn.f32x2 %0, %1, %2, %0;" : "+l"(d) : "l"(a), "l"(b));
}
__device__ __forceinline__ float hsum2(unsigned long long v) {
    float lo = __uint_as_float((unsigned)(v & 0xffffffffull));
    float hi = __uint_as_float((unsigned)(v >> 32));
    return lo + hi;
}
// pack two fp32 into fp16-hi pair / fp16-lo pair (hi exact to 2^-11, hi+lo to 2^-22)
__device__ __forceinline__ void hilo2h(float v0, float v1, unsigned& hp, unsigned& lp) {
    __half h0 = __float2half_rn(v0), h1 = __float2half_rn(v1);
    __half l0 = __float2half_rn(v0 - __half2float(h0));
    __half l1 = __float2half_rn(v1 - __half2float(h1));
    hp = (unsigned)__half_as_ushort(h0) | ((unsigned)__half_as_ushort(h1) << 16);
    lp = (unsigned)__half_as_ushort(l0) | ((unsigned)__half_as_ushort(l1) << 16);
}
__device__ __forceinline__ void ldsm4(unsigned r[4], unsigned addr) {
    asm volatile("ldmatrix.sync.aligned.m8n8.x4.shared.b16 {%0,%1,%2,%3}, [%4];"
                 : "=r"(r[0]), "=r"(r[1]), "=r"(r[2]), "=r"(r[3]) : "r"(addr));
}
__device__ __forceinline__ void mma_f16(float d[4], const unsigned a[4], unsigned b0, unsigned b1) {
    asm volatile("mma.sync.aligned.m16n8k16.row.col.f32.f16.f16.f32 "
                 "{%0,%1,%2,%3}, {%4,%5,%6,%7}, {%8,%9}, {%0,%1,%2,%3};"
                 : "+f"(d[0]), "+f"(d[1]), "+f"(d[2]), "+f"(d[3])
                 : "r"(a[0]), "r"(a[1]), "r"(a[2]), "r"(a[3]), "r"(b0), "r"(b1));
}
__device__ __forceinline__ void red2(float* p, float v0, float v1) {
    asm volatile("red.global.add.v2.f32 [%0], {%1, %2};" :: "l"(p), "f"(v0), "f"(v1) : "memory");
}

// warp-level 16x128x128 GEMM, fp16 2-term emulation: D = Ahi*Bhi + Alo*Bhi
// (R5 issue order — empirically best)
__device__ __forceinline__ void warp_gemm(unsigned aHi, unsigned aLo, unsigned bHi,
                                          unsigned aoff, unsigned boff, float (*d)[4]) {
    #pragma unroll
    for (int ks = 0; ks < 8; ks++) {
        unsigned ah[4], al[4];
        ldsm4(ah, aHi + aoff + ks * 32);
        ldsm4(al, aLo + aoff + ks * 32);
        #pragma unroll
        for (int np = 0; np < 8; np++) {
            unsigned bh[4];
            ldsm4(bh, bHi + boff + np * 4352 + ks * 32);
            mma_f16(d[np * 2],     ah, bh[0], bh[1]);
            mma_f16(d[np * 2 + 1], ah, bh[2], bh[3]);
            mma_f16(d[np * 2],     al, bh[0], bh[1]);
            mma_f16(d[np * 2 + 1], al, bh[2], bh[3]);
        }
    }
}

// SMEM byte layout for edge kernel
#define W2HI_B 4096
#define C1HI_B 38912
#define AT_B   73728      // EWARPS x (hi 4352 + lo 4352)
#define EDGE_SMEM (AT_B + EWARPS * 8704)   // 212992

// ---------------------------------------------------------------------------
__global__ void detect_kernel(const void* __restrict__ ei, int N, int E) {
    __shared__ int ok;
    if (threadIdx.x == 0) ok = 1;
    __syncthreads();
    int n = (E < 256) ? E : 256;
    if ((int)threadIdx.x < n) {
        long long v = ((const long long*)ei)[threadIdx.x];
        if (v < 0 || v >= (long long)N) atomicExch(&ok, 0);
    }
    __syncthreads();
    if (threadIdx.x == 0) g_is64 = ok;
}

__global__ void init_kernel(const float* __restrict__ pos, float* __restrict__ pos_out, int N) {
    int i = blockIdx.x * blockDim.x + threadIdx.x;
    if (i < N * 128) g_agg[i] = 0.0f;
    if (i < N * 3) pos_out[i] = pos[i];
}

// ---------------------------------------------------------------------------
// precompute: A = h @ eW1[0:128,:], B = h @ eW1[128:256,:]  (f32x2 microkernel)
// ---------------------------------------------------------------------------
#define PRE_SMEM ((64 * 132 + 16896) * 4)
__global__ __launch_bounds__(NTHREADS) void pre_kernel(
    const float* __restrict__ h, const float* __restrict__ eW1, int N)
{
    extern __shared__ float sm[];
    float* h_sm = sm;              // 64 * 132
    float* wt   = sm + 64 * 132;   // 128 * 132 transposed [out][k]

    int tid = threadIdx.x;
    int n0 = blockIdx.x * 64;
    for (int idx = tid; idx < 64 * 128; idx += NTHREADS) {
        int e = idx >> 7, k = idx & 127;
        int node = n0 + e;
        h_sm[e * 132 + k] = (node < N) ? h[node * 128 + k] : 0.0f;
    }
    int wid = tid >> 5, lane = tid & 31, ebase = wid * 8;
    const ulonglong2* Hu = (const ulonglong2*)h_sm;   // row stride 33
    const ulonglong2* Wu = (const ulonglong2*)wt;

    for (int half = 0; half < 2; half++) {
        __syncthreads();
        for (int i = tid; i < 16384; i += NTHREADS) {
            int k = i >> 7, o = i & 127;
            wt[o * 132 + k] = eW1[half * 16384 + i];
        }
        __syncthreads();
        unsigned long long acc[8][4];
        #pragma unroll
        for (int e = 0; e < 8; e++)
            #pragma unroll
            for (int j = 0; j < 4; j++) acc[e][j] = 0ull;
        #pragma unroll 4
        for (int c = 0; c < 32; c++) {
            ulonglong2 w0 = Wu[(0 * 32 + lane) * 33 + c];
            ulonglong2 w1 = Wu[(1 * 32 + lane) * 33 + c];
            ulonglong2 w2 = Wu[(2 * 32 + lane) * 33 + c];
            ulonglong2 w3 = Wu[(3 * 32 + lane) * 33 + c];
            #pragma unroll
            for (int e = 0; e < 8; e++) {
                ulonglong2 mv = Hu[(ebase + e) * 33 + c];
                ffma2(acc[e][0], mv.x, w0.x); ffma2(acc[e][0], mv.y, w0.y);
                ffma2(acc[e][1], mv.x, w1.x); ffma2(acc[e][1], mv.y, w1.y);
                ffma2(acc[e][2], mv.x, w2.x); ffma2(acc[e][2], mv.y, w2.y);
                ffma2(acc[e][3], mv.x, w3.x); ffma2(acc[e][3], mv.y, w3.y);
            }
        }
        float* dst = (half == 0) ? g_A : g_B;
        #pragma unroll
        for (int e = 0; e < 8; e++) {
            int node = n0 + ebase + e;
            if (node < N)
                #pragma unroll
                for (int j = 0; j < 4; j++)
                    dst[node * 128 + j * 32 + lane] = hsum2(acc[e][j]);
        }
    }
}

// ---------------------------------------------------------------------------
// fused edge kernel: warp-private mma.sync fp16 2-term pipeline, 256 edges/tile
// ---------------------------------------------------------------------------
__global__ __launch_bounds__(ETHREADS) void edge_kernel(
    const float* __restrict__ pos, const float* __restrict__ edge_attr,
    const void* __restrict__ ei_raw,
    const float* __restrict__ eW1, const float* __restrict__ eb1,
    const float* __restrict__ eW2, const float* __restrict__ eb2,
    const float* __restrict__ cW1, const float* __restrict__ cb1,
    const float* __restrict__ cW2, const float* __restrict__ cb2,
    float* __restrict__ pos_out, int N, int E)
{
    extern __shared__ float smf[];
    char* smc = (char*)smf;
    unsigned sbase = smem_u32(smf);
    int tid = threadIdx.x, wid = tid >> 5, lane = tid & 31;
    int g = lane >> 3, l = lane & 7;
    int qm = lane >> 2, qk = lane & 3;      // D-frag row / col-pair

    // sv: w_rn 0, w_ea 128, eb1 256, eb2 384, cb1 512, cw2 640, cb2 768
    float* sv = smf;
    for (int i = tid; i < 128; i += ETHREADS) {
        sv[i]       = eW1[256 * 128 + i];
        sv[128 + i] = eW1[257 * 128 + i];
        sv[256 + i] = eb1[i];
        sv[384 + i] = eb2[i];
        sv[512 + i] = cb1[i];
        sv[640 + i] = cW2[i];
    }
    if (tid == 0) sv[768] = cb2[0];

    // weights: B[o][k] = W[k][o], fp16 hi, row stride 272B
    for (int idx = tid; idx < 16384; idx += ETHREADS) {
        int k = idx >> 7, o = idx & 127;
        unsigned off = (unsigned)(o * 272 + k * 2);
        *(__half*)(smc + W2HI_B + off) = __float2half_rn(eW2[idx]);
        *(__half*)(smc + C1HI_B + off) = __float2half_rn(cW1[idx]);
    }
    __syncthreads();

    float cb2v = sv[768];
    int is64 = g_is64;
    const long long* ei64 = (const long long*)ei_raw;
    const int*       ei32 = (const int*)ei_raw;

    // per-lane phase1 constants (cols lane*4 .. +3)
    float4 wr = *(const float4*)&sv[lane * 4];
    float4 we = *(const float4*)&sv[128 + lane * 4];
    float4 bi = *(const float4*)&sv[256 + lane * 4];

    // per-warp A tile bases
    unsigned aHi = sbase + AT_B + wid * 8704;
    unsigned aLo = aHi + 4352;
    unsigned bW2h = sbase + W2HI_B;
    unsigned bC1h = sbase + C1HI_B;

    // ldmatrix lane offsets
    unsigned aoff = (unsigned)((l + ((g & 1) << 3)) * 272 + (g >> 1) * 16);
    unsigned boff = (unsigned)((l + ((g >> 1) << 3)) * 272 + (g & 1) * 16);

    int ntiles = (E + TILE_E - 1) / TILE_E;
    for (int t = blockIdx.x; t < ntiles; t += gridDim.x) {
        int e0w = t * TILE_E + wid * 16;     // this warp's first edge

        // --- meta (lanes 0..15 hold edge lane's data) ---
        int m_r = 0, m_c = 0;
        float m_rn = 1.0f, m_irn = 1.0f, m_ea = 0.0f, m_rx = 0.0f, m_ry = 0.0f, m_rz = 0.0f;
        if (lane < 16) {
            int e = e0w + lane;
            if (e < E) {
                int r, c;
                if (is64) { r = (int)ei64[e]; c = (int)ei64[E + e]; }
                else      { r = ei32[e];      c = ei32[E + e]; }
                r = min(max(r, 0), N - 1);
                c = min(max(c, 0), N - 1);
                float dx = pos[r * 3 + 0] - pos[c * 3 + 0];
                float dy = pos[r * 3 + 1] - pos[c * 3 + 1];
                float dz = pos[r * 3 + 2] - pos[c * 3 + 2];
                float nrm = sqrtf(dx * dx + dy * dy + dz * dz);
                float rn = fmaxf(nrm, 1e-8f);
                m_r = r; m_c = c; m_rn = rn; m_irn = 1.0f / rn;
                m_ea = edge_attr[e];
                m_rx = dx; m_ry = dy; m_rz = dz;
            }
        }

        // --- phase1: m = silu(A[row]+B[col]+rn*w_rn+ea*w_ea+eb1) -> hi/lo tile ---
        #pragma unroll
        for (int row = 0; row < 16; row++) {
            int rsrc = __shfl_sync(0xffffffffu, m_r, row);
            int csrc = __shfl_sync(0xffffffffu, m_c, row);
            float rn  = __shfl_sync(0xffffffffu, m_rn, row);
            float eav = __shfl_sync(0xffffffffu, m_ea, row);
            float4 a = *(const float4*)(g_A + rsrc * 128 + lane * 4);
            float4 b = *(const float4*)(g_B + csrc * 128 + lane * 4);
            float v0 = silu(fmaf(eav, we.x, fmaf(rn, wr.x, a.x + b.x)) + bi.x);
            float v1 = silu(fmaf(eav, we.y, fmaf(rn, wr.y, a.y + b.y)) + bi.y);
            float v2 = silu(fmaf(eav, we.z, fmaf(rn, wr.z, a.z + b.z)) + bi.z);
            float v3 = silu(fmaf(eav, we.w, fmaf(rn, wr.w, a.w + b.w)) + bi.w);
            unsigned hp0, hp1, lp0, lp1;
            hilo2h(v0, v1, hp0, lp0); hilo2h(v2, v3, hp1, lp1);
            unsigned off = (unsigned)(row * 272 + lane * 8);
            *(uint2*)(smc + (aHi - sbase) + off) = make_uint2(hp0, hp1);
            *(uint2*)(smc + (aLo - sbase) + off) = make_uint2(lp0, lp1);
        }
        __syncwarp();

        // --- GEMM2: D1 = m @ eW2 ---
        float d[16][4];
        #pragma unroll
        for (int i = 0; i < 16; i++) { d[i][0] = d[i][1] = d[i][2] = d[i][3] = 0.f; }
        warp_gemm(aHi, aLo, bW2h, aoff, boff, d);

        // --- epilogue1: m2 = silu(D1 + eb2) -> tile (overwrite) + agg red.v2 ---
        int ri0 = __shfl_sync(0xffffffffu, m_r, qm);
        int ri8 = __shfl_sync(0xffffffffu, m_r, qm + 8);
        bool ok0 = (e0w + qm) < E, ok8 = (e0w + qm + 8) < E;
        float* ga0 = g_agg + ri0 * 128;
        float* ga8 = g_agg + ri8 * 128;
        #pragma unroll
        for (int nt = 0; nt < 16; nt++) {
            int o0 = nt * 8 + qk * 2;
            float e_0 = sv[384 + o0], e_1 = sv[384 + o0 + 1];
            float v0 = silu(d[nt][0] + e_0);
            float v1 = silu(d[nt][1] + e_1);
            float v2 = silu(d[nt][2] + e_0);
            float v3 = silu(d[nt][3] + e_1);
            unsigned hp, lp;
            hilo2h(v0, v1, hp, lp);
            unsigned off = (unsigned)(qm * 272 + o0 * 2);
            *(unsigned*)(smc + (aHi - sbase) + off) = hp;
            *(unsigned*)(smc + (aLo - sbase) + off) = lp;
            hilo2h(v2, v3, hp, lp);
            off = (unsigned)((qm + 8) * 272 + o0 * 2);
            *(unsigned*)(smc + (aHi - sbase) + off) = hp;
            *(unsigned*)(smc + (aLo - sbase) + off) = lp;
            if (ok0) red2(ga0 + o0, v0, v1);
            if (ok8) red2(ga8 + o0, v2, v3);
        }
        __syncwarp();

        // --- GEMM3: D2 = m2 @ cW1 ---
        #pragma unroll
        for (int i = 0; i < 16; i++) { d[i][0] = d[i][1] = d[i][2] = d[i][3] = 0.f; }
        warp_gemm(aHi, aLo, bC1h, aoff, boff, d);

        // --- epilogue2: coord = silu(D2 + cb1) . cW2; pos atomics ---
        float pA = 0.0f, pB = 0.0f;
        #pragma unroll
        for (int nt = 0; nt < 16; nt++) {
            int o0 = nt * 8 + qk * 2;
            float c_0 = sv[512 + o0], c_1 = sv[512 + o0 + 1];
            float w_0 = sv[640 + o0], w_1 = sv[640 + o0 + 1];
            pA = fmaf(silu(d[nt][0] + c_0), w_0, pA);
            pA = fmaf(silu(d[nt][1] + c_1), w_1, pA);
            pB = fmaf(silu(d[nt][2] + c_0), w_0, pB);
            pB = fmaf(silu(d[nt][3] + c_1), w_1, pB);
        }
        pA += __shfl_xor_sync(0xffffffffu, pA, 1);
        pA += __shfl_xor_sync(0xffffffffu, pA, 2);
        pB += __shfl_xor_sync(0xffffffffu, pB, 1);
        pB += __shfl_xor_sync(0xffffffffu, pB, 2);
        float irn0 = __shfl_sync(0xffffffffu, m_irn, qm);
        float irn8 = __shfl_sync(0xffffffffu, m_irn, qm + 8);
        float rx0 = __shfl_sync(0xffffffffu, m_rx, qm), rx8 = __shfl_sync(0xffffffffu, m_rx, qm + 8);
        float ry0 = __shfl_sync(0xffffffffu, m_ry, qm), ry8 = __shfl_sync(0xffffffffu, m_ry, qm + 8);
        float rz0 = __shfl_sync(0xffffffffu, m_rz, qm), rz8 = __shfl_sync(0xffffffffu, m_rz, qm + 8);
        if (qk == 0) {
            if (ok0) {
                float s = (pA + cb2v) * irn0;
                atomicAdd(&pos_out[ri0 * 3 + 0], s * rx0);
                atomicAdd(&pos_out[ri0 * 3 + 1], s * ry0);
                atomicAdd(&pos_out[ri0 * 3 + 2], s * rz0);
            }
            if (ok8) {
                float s = (pB + cb2v) * irn8;
                atomicAdd(&pos_out[ri8 * 3 + 0], s * rx8);
                atomicAdd(&pos_out[ri8 * 3 + 1], s * ry8);
                atomicAdd(&pos_out[ri8 * 3 + 2], s * rz8);
            }
        }
        __syncwarp();
    }
}

// ---------------------------------------------------------------------------
// node MLP (f32x2): hn = silu([h,agg] @ nW1 + nb1); h_new = h + hn @ nW2 + nb2
// ---------------------------------------------------------------------------
#define NODE_SMEM ((64 * 260 + 128 * 132 + 64 * 132) * 4)
__global__ __launch_bounds__(NTHREADS) void node_kernel(
    const float* __restrict__ h,
    const float* __restrict__ nW1, const float* __restrict__ nb1,
    const float* __restrict__ nW2, const float* __restrict__ nb2,
    float* __restrict__ h_out, int N)
{
    extern __shared__ float sm[];
    float* x_sm  = sm;                       // 64*260 (0..127 h, 128..255 agg)
    float* wt    = sm + 64 * 260;            // 128*132 transposed [out][k]
    float* hn_sm = sm + 64 * 260 + 128 * 132;// 64*132

    int tid = threadIdx.x, wid = tid >> 5, lane = tid & 31, ebase = wid * 8;
    int n0 = blockIdx.x * 64;
    for (int idx = tid; idx < 64 * 256; idx += NTHREADS) {
        int e = idx >> 8, k = idx & 255;
        int node = n0 + e;
        float v = 0.0f;
        if (node < N) v = (k < 128) ? h[node * 128 + k] : g_agg[node * 128 + (k - 128)];
        x_sm[e * 260 + k] = v;
    }
    const ulonglong2* Xu  = (const ulonglong2*)x_sm;   // row stride 65
    const ulonglong2* Wu  = (const ulonglong2*)wt;     // row stride 33
    const ulonglong2* Hnu = (const ulonglong2*)hn_sm;  // row stride 33

    unsigned long long acc[8][4];
    #pragma unroll
    for (int e = 0; e < 8; e++)
        #pragma unroll
        for (int j = 0; j < 4; j++) acc[e][j] = 0ull;

    for (int half = 0; half < 2; half++) {
        __syncthreads();
        for (int i = tid; i < 16384; i += NTHREADS) {
            int k = i >> 7, o = i & 127;
            wt[o * 132 + k] = nW1[half * 16384 + i];
        }
        __syncthreads();
        #pragma unroll 4
        for (int c = 0; c < 32; c++) {
            ulonglong2 w0 = Wu[(0 * 32 + lane) * 33 + c];
            ulonglong2 w1 = Wu[(1 * 32 + lane) * 33 + c];
            ulonglong2 w2 = Wu[(2 * 32 + lane) * 33 + c];
            ulonglong2 w3 = Wu[(3 * 32 + lane) * 33 + c];
            #pragma unroll
            for (int e = 0; e < 8; e++) {
                ulonglong2 mv = Xu[(ebase + e) * 65 + half * 32 + c];
                ffma2(acc[e][0], mv.x, w0.x); ffma2(acc[e][0], mv.y, w0.y);
                ffma2(acc[e][1], mv.x, w1.x); ffma2(acc[e][1], mv.y, w1.y);
                ffma2(acc[e][2], mv.x, w2.x); ffma2(acc[e][2], mv.y, w2.y);
                ffma2(acc[e][3], mv.x, w3.x); ffma2(acc[e][3], mv.y, w3.y);
            }
        }
    }
    #pragma unroll
    for (int e = 0; e < 8; e++)
        #pragma unroll
        for (int j = 0; j < 4; j++)
            hn_sm[(ebase + e) * 132 + j * 32 + lane] = silu(hsum2(acc[e][j]) + nb1[j * 32 + lane]);
    __syncthreads();
    for (int i = tid; i < 16384; i += NTHREADS) {
        int k = i >> 7, o = i & 127;
        wt[o * 132 + k] = nW2[i];
    }
    __syncthreads();

    #pragma unroll
    for (int e = 0; e < 8; e++)
        #pragma unroll
        for (int j = 0; j < 4; j++) acc[e][j] = 0ull;
    #pragma unroll 4
    for (int c = 0; c < 32; c++) {
        ulonglong2 w0 = Wu[(0 * 32 + lane) * 33 + c];
        ulonglong2 w1 = Wu[(1 * 32 + lane) * 33 + c];
        ulonglong2 w2 = Wu[(2 * 32 + lane) * 33 + c];
        ulonglong2 w3 = Wu[(3 * 32 + lane) * 33 + c];
        #pragma unroll
        for (int e = 0; e < 8; e++) {
            ulonglong2 mv = Hnu[(ebase + e) * 33 + c];
            ffma2(acc[e][0], mv.x, w0.x); ffma2(acc[e][0], mv.y, w0.y);
            ffma2(acc[e][1], mv.x, w1.x); ffma2(acc[e][1], mv.y, w1.y);
            ffma2(acc[e][2], mv.x, w2.x); ffma2(acc[e][2], mv.y, w2.y);
            ffma2(acc[e][3], mv.x, w3.x); ffma2(acc[e][3], mv.y, w3.y);
        }
    }
    #pragma unroll
    for (int e = 0; e < 8; e++) {
        int node = n0 + ebase + e;
        if (node < N) {
            #pragma unroll
            for (int j = 0; j < 4; j++) {
                int o = j * 32 + lane;
                float res = x_sm[(ebase + e) * 260 + o];
                h_out[node * 128 + o] = hsum2(acc[e][j]) + nb2[o] + res;
            }
        }
    }
}

// ---------------------------------------------------------------------------
extern "C" void kernel_launch(void* const* d_in, const int* in_sizes, int n_in,
                              void* d_out, int out_size)
{
    const float* h   = (const float*)d_in[0];
    const float* pos = (const float*)d_in[1];
    const float* ea  = (const float*)d_in[2];
    const void*  ei  = d_in[3];
    const float* eW1 = (const float*)d_in[4];
    const float* eb1 = (const float*)d_in[5];
    const float* eW2 = (const float*)d_in[6];
    const float* eb2 = (const float*)d_in[7];
    const float* nW1 = (const float*)d_in[8];
    const float* nb1 = (const float*)d_in[9];
    const float* nW2 = (const float*)d_in[10];
    const float* nb2 = (const float*)d_in[11];
    const float* cW1 = (const float*)d_in[12];
    const float* cb1 = (const float*)d_in[13];
    const float* cW2 = (const float*)d_in[14];
    const float* cb2 = (const float*)d_in[15];

    int N = in_sizes[0] / 128;
    int E = in_sizes[2];
    float* h_out   = (float*)d_out;
    float* pos_out = h_out + (size_t)N * 128;

    cudaFuncSetAttribute(pre_kernel,  cudaFuncAttributeMaxDynamicSharedMemorySize, PRE_SMEM);
    cudaFuncSetAttribute(edge_kernel, cudaFuncAttributeMaxDynamicSharedMemorySize, EDGE_SMEM);
    cudaFuncSetAttribute(node_kernel, cudaFuncAttributeMaxDynamicSharedMemorySize, NODE_SMEM);

    int nsm = 148;
    cudaDeviceGetAttribute(&nsm, cudaDevAttrMultiProcessorCount, 0);

    detect_kernel<<<1, 256>>>(ei, N, E);
    init_kernel<<<(N * 128 + 255) / 256, 256>>>(pos, pos_out, N);
    pre_kernel<<<(N + 63) / 64, NTHREADS, PRE_SMEM>>>(h, eW1, N);
    edge_kernel<<<nsm, ETHREADS, EDGE_SMEM>>>(pos, ea, ei, eW1, eb1, eW2, eb2,
                                              cW1, cb1, cW2, cb2, pos_out, N, E);
    node_kernel<<<(N + 63) / 64, NTHREADS, NODE_SMEM>>>(h, nW1, nb1, nW2, nb2, h_out, N);
}

// round 9
// speedup vs baseline: 5.2358x; 2.6635x over previous
#include <cuda_runtime.h>
#include <cuda_fp16.h>

#define NTHREADS 256
#define ETHREADS 512
#define EWARPS   16
#define TILE_E   (EWARPS * 16)
#define NMAX 50000

// Scratch (device globals: allocation-free rule)
__device__ float g_A[NMAX * 128];    // h @ eW1[0:128]   gathered by row
__device__ float g_B[NMAX * 128];    // h @ eW1[128:256] gathered by col
__device__ float g_agg[NMAX * 128];  // segment_sum(m2, row)
__device__ int   g_is64;             // edge_index dtype flag

__device__ __forceinline__ float tanh_a(float x) {
    float y; asm("tanh.approx.f32 %0, %1;" : "=f"(y) : "f"(x)); return y;
}
// silu(x) = x * sigmoid(x),  sigmoid = 0.5*tanh(x/2)+0.5  (1 MUFU)
__device__ __forceinline__ float silu(float x) {
    return x * fmaf(0.5f, tanh_a(0.5f * x), 0.5f);
}
__device__ __forceinline__ unsigned smem_u32(const void* p) {
    unsigned a;
    asm("{ .reg .u64 t; cvta.to.shared.u64 t, %1; cvt.u32.u64 %0, t; }" : "=r"(a) : "l"(p));
    return a;
}
// packed fp32x2 FMA: d = a*b + d
__device__ __forceinline__ void ffma2(unsigned long long& d,
                                      unsigned long long a, unsigned long long b) {
    asm("fma.rn.f32x2 %0, %1, %2, %0;" : "+l"(d) : "l"(a), "l"(b));
}
__device__ __forceinline__ float hsum2(unsigned long long v) {
    float lo = __uint_as_float((unsigned)(v & 0xffffffffull));
    float hi = __uint_as_float((unsigned)(v >> 32));
    return lo + hi;
}
__device__ __forceinline__ unsigned pack2h(float v0, float v1) {
    __half2 h = __floats2half2_rn(v0, v1);
    return *(unsigned*)&h;
}
__device__ __forceinline__ void ldsm4(unsigned r[4], unsigned addr) {
    asm volatile("ldmatrix.sync.aligned.m8n8.x4.shared.b16 {%0,%1,%2,%3}, [%4];"
                 : "=r"(r[0]), "=r"(r[1]), "=r"(r[2]), "=r"(r[3]) : "r"(addr));
}
__device__ __forceinline__ void mma_f16(float d[4], const unsigned a[4], unsigned b0, unsigned b1) {
    asm volatile("mma.sync.aligned.m16n8k16.row.col.f32.f16.f16.f32 "
                 "{%0,%1,%2,%3}, {%4,%5,%6,%7}, {%8,%9}, {%0,%1,%2,%3};"
                 : "+f"(d[0]), "+f"(d[1]), "+f"(d[2]), "+f"(d[3])
                 : "r"(a[0]), "r"(a[1]), "r"(a[2]), "r"(a[3]), "r"(b0), "r"(b1));
}
__device__ __forceinline__ void red2(float* p, float v0, float v1) {
    asm volatile("red.global.add.v2.f32 [%0], {%1, %2};" :: "l"(p), "f"(v0), "f"(v1) : "memory");
}

// warp-level 16x128x128 plain fp16 GEMM (fp32 accum)
// A tile: 16 rows x 128 cols fp16, row stride 272B. B: 128(out) x 128(k), stride 272B.
__device__ __forceinline__ void warp_gemm(unsigned aT, unsigned bT,
                                          unsigned aoff, unsigned boff, float (*d)[4]) {
    #pragma unroll
    for (int ks = 0; ks < 8; ks++) {
        unsigned ah[4];
        ldsm4(ah, aT + aoff + ks * 32);
        #pragma unroll
        for (int np = 0; np < 8; np++) {
            unsigned bh[4];
            ldsm4(bh, bT + boff + np * 4352 + ks * 32);
            mma_f16(d[np * 2],     ah, bh[0], bh[1]);
            mma_f16(d[np * 2 + 1], ah, bh[2], bh[3]);
        }
    }
}

// SMEM byte layout for edge kernel
#define W2HI_B 4096
#define C1HI_B 38912
#define AT_B   73728      // EWARPS x 4352
#define EDGE_SMEM (AT_B + EWARPS * 4352)   // 143360

// ---------------------------------------------------------------------------
__global__ void detect_kernel(const void* __restrict__ ei, int N, int E) {
    __shared__ int ok;
    if (threadIdx.x == 0) ok = 1;
    __syncthreads();
    int n = (E < 256) ? E : 256;
    if ((int)threadIdx.x < n) {
        long long v = ((const long long*)ei)[threadIdx.x];
        if (v < 0 || v >= (long long)N) atomicExch(&ok, 0);
    }
    __syncthreads();
    if (threadIdx.x == 0) g_is64 = ok;
}

__global__ void init_kernel(const float* __restrict__ pos, float* __restrict__ pos_out, int N) {
    int i = blockIdx.x * blockDim.x + threadIdx.x;
    if (i < N * 128) g_agg[i] = 0.0f;
    if (i < N * 3) pos_out[i] = pos[i];
}

// ---------------------------------------------------------------------------
// precompute: A = h @ eW1[0:128,:], B = h @ eW1[128:256,:]  (f32x2 microkernel)
// ---------------------------------------------------------------------------
#define PRE_SMEM ((64 * 132 + 16896) * 4)
__global__ __launch_bounds__(NTHREADS) void pre_kernel(
    const float* __restrict__ h, const float* __restrict__ eW1, int N)
{
    extern __shared__ float sm[];
    float* h_sm = sm;              // 64 * 132
    float* wt   = sm + 64 * 132;   // 128 * 132 transposed [out][k]

    int tid = threadIdx.x;
    int n0 = blockIdx.x * 64;
    for (int idx = tid; idx < 64 * 128; idx += NTHREADS) {
        int e = idx >> 7, k = idx & 127;
        int node = n0 + e;
        h_sm[e * 132 + k] = (node < N) ? h[node * 128 + k] : 0.0f;
    }
    int wid = tid >> 5, lane = tid & 31, ebase = wid * 8;
    const ulonglong2* Hu = (const ulonglong2*)h_sm;   // row stride 33
    const ulonglong2* Wu = (const ulonglong2*)wt;

    for (int half = 0; half < 2; half++) {
        __syncthreads();
        for (int i = tid; i < 16384; i += NTHREADS) {
            int k = i >> 7, o = i & 127;
            wt[o * 132 + k] = eW1[half * 16384 + i];
        }
        __syncthreads();
        unsigned long long acc[8][4];
        #pragma unroll
        for (int e = 0; e < 8; e++)
            #pragma unroll
            for (int j = 0; j < 4; j++) acc[e][j] = 0ull;
        #pragma unroll 4
        for (int c = 0; c < 32; c++) {
            ulonglong2 w0 = Wu[(0 * 32 + lane) * 33 + c];
            ulonglong2 w1 = Wu[(1 * 32 + lane) * 33 + c];
            ulonglong2 w2 = Wu[(2 * 32 + lane) * 33 + c];
            ulonglong2 w3 = Wu[(3 * 32 + lane) * 33 + c];
            #pragma unroll
            for (int e = 0; e < 8; e++) {
                ulonglong2 mv = Hu[(ebase + e) * 33 + c];
                ffma2(acc[e][0], mv.x, w0.x); ffma2(acc[e][0], mv.y, w0.y);
                ffma2(acc[e][1], mv.x, w1.x); ffma2(acc[e][1], mv.y, w1.y);
                ffma2(acc[e][2], mv.x, w2.x); ffma2(acc[e][2], mv.y, w2.y);
                ffma2(acc[e][3], mv.x, w3.x); ffma2(acc[e][3], mv.y, w3.y);
            }
        }
        float* dst = (half == 0) ? g_A : g_B;
        #pragma unroll
        for (int e = 0; e < 8; e++) {
            int node = n0 + ebase + e;
            if (node < N)
                #pragma unroll
                for (int j = 0; j < 4; j++)
                    dst[node * 128 + j * 32 + lane] = hsum2(acc[e][j]);
        }
    }
}

// ---------------------------------------------------------------------------
// fused edge kernel: warp-private plain-fp16 mma pipeline, 256 edges/tile
// ---------------------------------------------------------------------------
__global__ __launch_bounds__(ETHREADS) void edge_kernel(
    const float* __restrict__ pos, const float* __restrict__ edge_attr,
    const void* __restrict__ ei_raw,
    const float* __restrict__ eW1, const float* __restrict__ eb1,
    const float* __restrict__ eW2, const float* __restrict__ eb2,
    const float* __restrict__ cW1, const float* __restrict__ cb1,
    const float* __restrict__ cW2, const float* __restrict__ cb2,
    float* __restrict__ pos_out, int N, int E)
{
    extern __shared__ float smf[];
    char* smc = (char*)smf;
    unsigned sbase = smem_u32(smf);
    int tid = threadIdx.x, wid = tid >> 5, lane = tid & 31;
    int g = lane >> 3, l = lane & 7;
    int qm = lane >> 2, qk = lane & 3;      // D-frag row / col-pair

    // sv: w_rn 0, w_ea 128, eb1 256, eb2 384, cb1 512, cw2 640, cb2 768
    float* sv = smf;
    for (int i = tid; i < 128; i += ETHREADS) {
        sv[i]       = eW1[256 * 128 + i];
        sv[128 + i] = eW1[257 * 128 + i];
        sv[256 + i] = eb1[i];
        sv[384 + i] = eb2[i];
        sv[512 + i] = cb1[i];
        sv[640 + i] = cW2[i];
    }
    if (tid == 0) sv[768] = cb2[0];

    // weights: B[o][k] = W[k][o], fp16, row stride 272B
    for (int idx = tid; idx < 16384; idx += ETHREADS) {
        int k = idx >> 7, o = idx & 127;
        unsigned off = (unsigned)(o * 272 + k * 2);
        *(__half*)(smc + W2HI_B + off) = __float2half_rn(eW2[idx]);
        *(__half*)(smc + C1HI_B + off) = __float2half_rn(cW1[idx]);
    }
    __syncthreads();

    float cb2v = sv[768];
    int is64 = g_is64;
    const long long* ei64 = (const long long*)ei_raw;
    const int*       ei32 = (const int*)ei_raw;

    // per-lane phase1 constants (cols lane*4 .. +3)
    float4 wr = *(const float4*)&sv[lane * 4];
    float4 we = *(const float4*)&sv[128 + lane * 4];
    float4 bi = *(const float4*)&sv[256 + lane * 4];

    unsigned aT = sbase + AT_B + wid * 4352;
    unsigned bW2h = sbase + W2HI_B;
    unsigned bC1h = sbase + C1HI_B;

    // ldmatrix lane offsets
    unsigned aoff = (unsigned)((l + ((g & 1) << 3)) * 272 + (g >> 1) * 16);
    unsigned boff = (unsigned)((l + ((g >> 1) << 3)) * 272 + (g & 1) * 16);

    int ntiles = (E + TILE_E - 1) / TILE_E;
    for (int t = blockIdx.x; t < ntiles; t += gridDim.x) {
        int e0w = t * TILE_E + wid * 16;     // this warp's first edge

        // --- meta (lanes 0..15 hold edge lane's data) ---
        int m_r = 0, m_c = 0;
        float m_rn = 1.0f, m_irn = 1.0f, m_ea = 0.0f, m_rx = 0.0f, m_ry = 0.0f, m_rz = 0.0f;
        if (lane < 16) {
            int e = e0w + lane;
            if (e < E) {
                int r, c;
                if (is64) { r = (int)ei64[e]; c = (int)ei64[E + e]; }
                else      { r = ei32[e];      c = ei32[E + e]; }
                r = min(max(r, 0), N - 1);
                c = min(max(c, 0), N - 1);
                float dx = pos[r * 3 + 0] - pos[c * 3 + 0];
                float dy = pos[r * 3 + 1] - pos[c * 3 + 1];
                float dz = pos[r * 3 + 2] - pos[c * 3 + 2];
                float nrm = sqrtf(dx * dx + dy * dy + dz * dz);
                float rn = fmaxf(nrm, 1e-8f);
                m_r = r; m_c = c; m_rn = rn; m_irn = 1.0f / rn;
                m_ea = edge_attr[e];
                m_rx = dx; m_ry = dy; m_rz = dz;
            }
        }

        // --- phase1: m = silu(A[row]+B[col]+rn*w_rn+ea*w_ea+eb1) -> fp16 tile ---
        #pragma unroll
        for (int row = 0; row < 16; row++) {
            int rsrc = __shfl_sync(0xffffffffu, m_r, row);
            int csrc = __shfl_sync(0xffffffffu, m_c, row);
            float rn  = __shfl_sync(0xffffffffu, m_rn, row);
            float eav = __shfl_sync(0xffffffffu, m_ea, row);
            float4 a = *(const float4*)(g_A + rsrc * 128 + lane * 4);
            float4 b = *(const float4*)(g_B + csrc * 128 + lane * 4);
            float v0 = silu(fmaf(eav, we.x, fmaf(rn, wr.x, a.x + b.x)) + bi.x);
            float v1 = silu(fmaf(eav, we.y, fmaf(rn, wr.y, a.y + b.y)) + bi.y);
            float v2 = silu(fmaf(eav, we.z, fmaf(rn, wr.z, a.z + b.z)) + bi.z);
            float v3 = silu(fmaf(eav, we.w, fmaf(rn, wr.w, a.w + b.w)) + bi.w);
            *(uint2*)(smc + (AT_B + wid * 4352) + row * 272 + lane * 8) =
                make_uint2(pack2h(v0, v1), pack2h(v2, v3));
        }
        __syncwarp();

        // --- GEMM2: D1 = m @ eW2 ---
        float d[16][4];
        #pragma unroll
        for (int i = 0; i < 16; i++) { d[i][0] = d[i][1] = d[i][2] = d[i][3] = 0.f; }
        warp_gemm(aT, bW2h, aoff, boff, d);

        // --- epilogue1: m2 = silu(D1 + eb2) -> tile (overwrite) + agg red.v2 ---
        int ri0 = __shfl_sync(0xffffffffu, m_r, qm);
        int ri8 = __shfl_sync(0xffffffffu, m_r, qm + 8);
        bool ok0 = (e0w + qm) < E, ok8 = (e0w + qm + 8) < E;
        float* ga0 = g_agg + ri0 * 128;
        float* ga8 = g_agg + ri8 * 128;
        #pragma unroll
        for (int nt = 0; nt < 16; nt++) {
            int o0 = nt * 8 + qk * 2;
            float e_0 = sv[384 + o0], e_1 = sv[384 + o0 + 1];
            float v0 = silu(d[nt][0] + e_0);
            float v1 = silu(d[nt][1] + e_1);
            float v2 = silu(d[nt][2] + e_0);
            float v3 = silu(d[nt][3] + e_1);
            *(unsigned*)(smc + (AT_B + wid * 4352) + qm * 272 + o0 * 2) = pack2h(v0, v1);
            *(unsigned*)(smc + (AT_B + wid * 4352) + (qm + 8) * 272 + o0 * 2) = pack2h(v2, v3);
            if (ok0) red2(ga0 + o0, v0, v1);
            if (ok8) red2(ga8 + o0, v2, v3);
        }
        __syncwarp();

        // --- GEMM3: D2 = m2 @ cW1 ---
        #pragma unroll
        for (int i = 0; i < 16; i++) { d[i][0] = d[i][1] = d[i][2] = d[i][3] = 0.f; }
        warp_gemm(aT, bC1h, aoff, boff, d);

        // --- epilogue2: coord = silu(D2 + cb1) . cW2; pos atomics ---
        float pA = 0.0f, pB = 0.0f;
        #pragma unroll
        for (int nt = 0; nt < 16; nt++) {
            int o0 = nt * 8 + qk * 2;
            float c_0 = sv[512 + o0], c_1 = sv[512 + o0 + 1];
            float w_0 = sv[640 + o0], w_1 = sv[640 + o0 + 1];
            pA = fmaf(silu(d[nt][0] + c_0), w_0, pA);
            pA = fmaf(silu(d[nt][1] + c_1), w_1, pA);
            pB = fmaf(silu(d[nt][2] + c_0), w_0, pB);
            pB = fmaf(silu(d[nt][3] + c_1), w_1, pB);
        }
        pA += __shfl_xor_sync(0xffffffffu, pA, 1);
        pA += __shfl_xor_sync(0xffffffffu, pA, 2);
        pB += __shfl_xor_sync(0xffffffffu, pB, 1);
        pB += __shfl_xor_sync(0xffffffffu, pB, 2);
        float irn0 = __shfl_sync(0xffffffffu, m_irn, qm);
        float irn8 = __shfl_sync(0xffffffffu, m_irn, qm + 8);
        float rx0 = __shfl_sync(0xffffffffu, m_rx, qm), rx8 = __shfl_sync(0xffffffffu, m_rx, qm + 8);
        float ry0 = __shfl_sync(0xffffffffu, m_ry, qm), ry8 = __shfl_sync(0xffffffffu, m_ry, qm + 8);
        float rz0 = __shfl_sync(0xffffffffu, m_rz, qm), rz8 = __shfl_sync(0xffffffffu, m_rz, qm + 8);
        if (qk == 0) {
            if (ok0) {
                float s = (pA + cb2v) * irn0;
                atomicAdd(&pos_out[ri0 * 3 + 0], s * rx0);
                atomicAdd(&pos_out[ri0 * 3 + 1], s * ry0);
                atomicAdd(&pos_out[ri0 * 3 + 2], s * rz0);
            }
            if (ok8) {
                float s = (pB + cb2v) * irn8;
                atomicAdd(&pos_out[ri8 * 3 + 0], s * rx8);
                atomicAdd(&pos_out[ri8 * 3 + 1], s * ry8);
                atomicAdd(&pos_out[ri8 * 3 + 2], s * rz8);
            }
        }
        __syncwarp();
    }
}

// ---------------------------------------------------------------------------
// node MLP (fp16 mma, warp-private): hn = silu([h,agg]@nW1+nb1); h_new = h + hn@nW2+nb2
// ---------------------------------------------------------------------------
#define NODE_W  12
#define NODE_T  384
#define W1A_B   0
#define W1B_B   34816
#define W2N_B   69632
#define XT_B    104448    // per warp: Xh at +wid*8704, Xagg at +wid*8704+4352
#define NB_F    52224     // float idx: nb1[0..127], nb2[128..255]
#define NODE_SMEM 209920
__global__ __launch_bounds__(NODE_T) void node_kernel(
    const float* __restrict__ h,
    const float* __restrict__ nW1, const float* __restrict__ nb1,
    const float* __restrict__ nW2, const float* __restrict__ nb2,
    float* __restrict__ h_out, int N)
{
    extern __shared__ float smf[];
    char* smc = (char*)smf;
    unsigned sbase = smem_u32(smf);
    int tid = threadIdx.x, wid = tid >> 5, lane = tid & 31;
    int g = lane >> 3, l = lane & 7;
    int qm = lane >> 2, qk = lane & 3;

    // weights transposed [o][k] fp16, stride 272B; nW1 split into k-halves
    for (int idx = tid; idx < 32768; idx += NODE_T) {
        int k = idx >> 7, o = idx & 127;
        unsigned off = (unsigned)(o * 272 + (k & 127) * 2);
        *(__half*)(smc + (k < 128 ? W1A_B : W1B_B) + off) = __float2half_rn(nW1[idx]);
    }
    for (int idx = tid; idx < 16384; idx += NODE_T) {
        int k = idx >> 7, o = idx & 127;
        *(__half*)(smc + W2N_B + o * 272 + k * 2) = __float2half_rn(nW2[idx]);
    }
    for (int i = tid; i < 128; i += NODE_T) {
        smf[NB_F + i] = nb1[i];
        smf[NB_F + 128 + i] = nb2[i];
    }
    __syncthreads();

    unsigned xh = sbase + XT_B + wid * 8704, xa = xh + 4352;
    unsigned w1a = sbase + W1A_B, w1b = sbase + W1B_B, w2 = sbase + W2N_B;
    unsigned aoff = (unsigned)((l + ((g & 1) << 3)) * 272 + (g >> 1) * 16);
    unsigned boff = (unsigned)((l + ((g >> 1) << 3)) * 272 + (g & 1) * 16);

    int n0w = blockIdx.x * (NODE_W * 16) + wid * 16;
    if (n0w >= N) return;

    // phase: X tiles (fp16): Xh = h rows, Xagg = agg rows
    #pragma unroll
    for (int row = 0; row < 16; row++) {
        int node = min(n0w + row, N - 1);
        float4 a = *(const float4*)(h + node * 128 + lane * 4);
        float4 b = *(const float4*)(g_agg + node * 128 + lane * 4);
        *(uint2*)(smc + (XT_B + wid * 8704) + row * 272 + lane * 8) =
            make_uint2(pack2h(a.x, a.y), pack2h(a.z, a.w));
        *(uint2*)(smc + (XT_B + wid * 8704 + 4352) + row * 272 + lane * 8) =
            make_uint2(pack2h(b.x, b.y), pack2h(b.z, b.w));
    }
    __syncwarp();

    // GEMM1: D = [h,agg] @ nW1  (two K-halves)
    float d[16][4];
    #pragma unroll
    for (int i = 0; i < 16; i++) { d[i][0] = d[i][1] = d[i][2] = d[i][3] = 0.f; }
    warp_gemm(xh, w1a, aoff, boff, d);
    warp_gemm(xa, w1b, aoff, boff, d);

    // epilogue1: hn = silu(D + nb1) -> Xh tile (overwrite)
    #pragma unroll
    for (int nt = 0; nt < 16; nt++) {
        int o0 = nt * 8 + qk * 2;
        float b0 = smf[NB_F + o0], b1 = smf[NB_F + o0 + 1];
        float v0 = silu(d[nt][0] + b0);
        float v1 = silu(d[nt][1] + b1);
        float v2 = silu(d[nt][2] + b0);
        float v3 = silu(d[nt][3] + b1);
        *(unsigned*)(smc + (XT_B + wid * 8704) + qm * 272 + o0 * 2) = pack2h(v0, v1);
        *(unsigned*)(smc + (XT_B + wid * 8704) + (qm + 8) * 272 + o0 * 2) = pack2h(v2, v3);
    }
    __syncwarp();

    // GEMM2: D = hn @ nW2
    #pragma unroll
    for (int i = 0; i < 16; i++) { d[i][0] = d[i][1] = d[i][2] = d[i][3] = 0.f; }
    warp_gemm(xh, w2, aoff, boff, d);

    // epilogue2: h_out = D + nb2 + h (residual)
    int nd0 = n0w + qm, nd8 = n0w + qm + 8;
    #pragma unroll
    for (int nt = 0; nt < 16; nt++) {
        int o0 = nt * 8 + qk * 2;
        float b0 = smf[NB_F + 128 + o0], b1 = smf[NB_F + 128 + o0 + 1];
        if (nd0 < N) {
            float2 r = *(const float2*)(h + nd0 * 128 + o0);
            *(float2*)(h_out + nd0 * 128 + o0) = make_float2(d[nt][0] + b0 + r.x, d[nt][1] + b1 + r.y);
        }
        if (nd8 < N) {
            float2 r = *(const float2*)(h + nd8 * 128 + o0);
            *(float2*)(h_out + nd8 * 128 + o0) = make_float2(d[nt][2] + b0 + r.x, d[nt][3] + b1 + r.y);
        }
    }
}

// ---------------------------------------------------------------------------
extern "C" void kernel_launch(void* const* d_in, const int* in_sizes, int n_in,
                              void* d_out, int out_size)
{
    const float* h   = (const float*)d_in[0];
    const float* pos = (const float*)d_in[1];
    const float* ea  = (const float*)d_in[2];
    const void*  ei  = d_in[3];
    const float* eW1 = (const float*)d_in[4];
    const float* eb1 = (const float*)d_in[5];
    const float* eW2 = (const float*)d_in[6];
    const float* eb2 = (const float*)d_in[7];
    const float* nW1 = (const float*)d_in[8];
    const float* nb1 = (const float*)d_in[9];
    const float* nW2 = (const float*)d_in[10];
    const float* nb2 = (const float*)d_in[11];
    const float* cW1 = (const float*)d_in[12];
    const float* cb1 = (const float*)d_in[13];
    const float* cW2 = (const float*)d_in[14];
    const float* cb2 = (const float*)d_in[15];

    int N = in_sizes[0] / 128;
    int E = in_sizes[2];
    float* h_out   = (float*)d_out;
    float* pos_out = h_out + (size_t)N * 128;

    cudaFuncSetAttribute(pre_kernel,  cudaFuncAttributeMaxDynamicSharedMemorySize, PRE_SMEM);
    cudaFuncSetAttribute(edge_kernel, cudaFuncAttributeMaxDynamicSharedMemorySize, EDGE_SMEM);
    cudaFuncSetAttribute(node_kernel, cudaFuncAttributeMaxDynamicSharedMemorySize, NODE_SMEM);

    int nsm = 148;
    cudaDeviceGetAttribute(&nsm, cudaDevAttrMultiProcessorCount, 0);

    detect_kernel<<<1, 256>>>(ei, N, E);
    init_kernel<<<(N * 128 + 255) / 256, 256>>>(pos, pos_out, N);
    pre_kernel<<<(N + 63) / 64, NTHREADS, PRE_SMEM>>>(h, eW1, N);
    edge_kernel<<<nsm, ETHREADS, EDGE_SMEM>>>(pos, ea, ei, eW1, eb1, eW2, eb2,
                                              cW1, cb1, cW2, cb2, pos_out, N, E);
    node_kernel<<<(N + NODE_W * 16 - 1) / (NODE_W * 16), NODE_T, NODE_SMEM>>>(
        h, nW1, nb1, nW2, nb2, h_out, N);
}

// round 10
// speedup vs baseline: 5.7981x; 1.1074x over previous
#include <cuda_runtime.h>
#include <cuda_fp16.h>

#define NTHREADS 256
#define ETHREADS 384
#define EWARPS   12
#define TILE_E   (EWARPS * 32)
#define NMAX 50000

// Scratch (device globals: allocation-free rule)
__device__ float g_A[NMAX * 128];    // h @ eW1[0:128]   gathered by row
__device__ float g_B[NMAX * 128];    // h @ eW1[128:256] gathered by col
__device__ float g_agg[NMAX * 128];  // segment_sum(m2, row)
__device__ int   g_is64;             // edge_index dtype flag

__device__ __forceinline__ float tanh_a(float x) {
    float y; asm("tanh.approx.f32 %0, %1;" : "=f"(y) : "f"(x)); return y;
}
__device__ __forceinline__ float silu(float x) {
    return x * fmaf(0.5f, tanh_a(0.5f * x), 0.5f);
}
__device__ __forceinline__ unsigned smem_u32(const void* p) {
    unsigned a;
    asm("{ .reg .u64 t; cvta.to.shared.u64 t, %1; cvt.u32.u64 %0, t; }" : "=r"(a) : "l"(p));
    return a;
}
__device__ __forceinline__ unsigned pack2h(float v0, float v1) {
    __half2 h = __floats2half2_rn(v0, v1);
    return *(unsigned*)&h;
}
__device__ __forceinline__ void ldsm4(unsigned r[4], unsigned addr) {
    asm volatile("ldmatrix.sync.aligned.m8n8.x4.shared.b16 {%0,%1,%2,%3}, [%4];"
                 : "=r"(r[0]), "=r"(r[1]), "=r"(r[2]), "=r"(r[3]) : "r"(addr));
}
__device__ __forceinline__ void mma_f16(float d[4], const unsigned a[4], unsigned b0, unsigned b1) {
    asm volatile("mma.sync.aligned.m16n8k16.row.col.f32.f16.f16.f32 "
                 "{%0,%1,%2,%3}, {%4,%5,%6,%7}, {%8,%9}, {%0,%1,%2,%3};"
                 : "+f"(d[0]), "+f"(d[1]), "+f"(d[2]), "+f"(d[3])
                 : "r"(a[0]), "r"(a[1]), "r"(a[2]), "r"(a[3]), "r"(b0), "r"(b1));
}
__device__ __forceinline__ void red2(float* p, float v0, float v1) {
    asm volatile("red.global.add.v2.f32 [%0], {%1, %2};" :: "l"(p), "f"(v0), "f"(v1) : "memory");
}

// M=16 warp GEMM: 16 x 128 x 128 fp16 (fp32 accum). A row stride 272B.
__device__ __forceinline__ void warp_gemm(unsigned aT, unsigned bT,
                                          unsigned aoff, unsigned boff, float (*d)[4]) {
    #pragma unroll
    for (int ks = 0; ks < 8; ks++) {
        unsigned ah[4];
        ldsm4(ah, aT + aoff + ks * 32);
        #pragma unroll
        for (int np = 0; np < 8; np++) {
            unsigned bh[4];
            ldsm4(bh, bT + boff + np * 4352 + ks * 32);
            mma_f16(d[np * 2],     ah, bh[0], bh[1]);
            mma_f16(d[np * 2 + 1], ah, bh[2], bh[3]);
        }
    }
}

// M=32 warp GEMM, one N-half (64 outs starting at nbase).
// d[0..7]: rows qm,qm+8 ; d[8..15]: rows qm+16,qm+24.
__device__ __forceinline__ void warp_gemm32(unsigned aT, unsigned bT,
                                            unsigned aoff, unsigned boff,
                                            int nbase, float (*d)[4]) {
    #pragma unroll
    for (int ks = 0; ks < 8; ks++) {
        unsigned a0[4], a1[4];
        ldsm4(a0, aT + aoff + ks * 32);
        ldsm4(a1, aT + aoff + 16 * 272 + ks * 32);
        #pragma unroll
        for (int s = 0; s < 4; s++) {
            unsigned bh[4];
            ldsm4(bh, bT + boff + (unsigned)(nbase + s * 16) * 272 + ks * 32);
            mma_f16(d[s * 2],         a0, bh[0], bh[1]);
            mma_f16(d[s * 2 + 1],     a0, bh[2], bh[3]);
            mma_f16(d[8 + s * 2],     a1, bh[0], bh[1]);
            mma_f16(d[8 + s * 2 + 1], a1, bh[2], bh[3]);
        }
    }
}

// SMEM byte layout for edge kernel
#define W2HI_B 4096
#define C1HI_B 38912
#define AT_B   73728      // EWARPS x 8704 (32 rows x 272B)
#define EDGE_SMEM (AT_B + EWARPS * 8704)   // 178176

// ---------------------------------------------------------------------------
__global__ void detect_kernel(const void* __restrict__ ei, int N, int E) {
    __shared__ int ok;
    if (threadIdx.x == 0) ok = 1;
    __syncthreads();
    int n = (E < 256) ? E : 256;
    if ((int)threadIdx.x < n) {
        long long v = ((const long long*)ei)[threadIdx.x];
        if (v < 0 || v >= (long long)N) atomicExch(&ok, 0);
    }
    __syncthreads();
    if (threadIdx.x == 0) g_is64 = ok;
}

__global__ void init_kernel(const float* __restrict__ pos, float* __restrict__ pos_out, int N) {
    int i = blockIdx.x * blockDim.x + threadIdx.x;
    if (i < N * 128) g_agg[i] = 0.0f;
    if (i < N * 3) pos_out[i] = pos[i];
}

// ---------------------------------------------------------------------------
// precompute (fp16 mma): A = h @ eW1[0:128,:], B = h @ eW1[128:256,:]
// 12 warps x 16 nodes = 192 nodes/block
// ---------------------------------------------------------------------------
#define PRE_SMEM2 121856   // W0 34816 | W1 34816 | X tiles 12*4352
__global__ __launch_bounds__(384) void pre_kernel(
    const float* __restrict__ h, const float* __restrict__ eW1, int N)
{
    extern __shared__ float smf[];
    char* smc = (char*)smf;
    unsigned sbase = smem_u32(smf);
    int tid = threadIdx.x, wid = tid >> 5, lane = tid & 31;
    int g = lane >> 3, l = lane & 7;
    int qm = lane >> 2, qk = lane & 3;

    for (int idx = tid; idx < 32768; idx += 384) {
        int k = idx >> 7, o = idx & 127;
        *(__half*)(smc + (k < 128 ? 0 : 34816) + o * 272 + (k & 127) * 2) =
            __float2half_rn(eW1[idx]);
    }
    __syncthreads();

    unsigned xT = sbase + 69632 + wid * 4352;
    unsigned aoff = (unsigned)((l + ((g & 1) << 3)) * 272 + (g >> 1) * 16);
    unsigned boff = (unsigned)((l + ((g >> 1) << 3)) * 272 + (g & 1) * 16);

    int n0w = blockIdx.x * 192 + wid * 16;
    if (n0w >= N) return;

    #pragma unroll
    for (int row = 0; row < 16; row++) {
        int node = min(n0w + row, N - 1);
        float4 a = *(const float4*)(h + node * 128 + lane * 4);
        *(uint2*)(smc + (69632 + wid * 4352) + row * 272 + lane * 8) =
            make_uint2(pack2h(a.x, a.y), pack2h(a.z, a.w));
    }
    __syncwarp();

    int nd0 = n0w + qm, nd8 = n0w + qm + 8;
    float d[16][4];
    #pragma unroll
    for (int i = 0; i < 16; i++) { d[i][0] = d[i][1] = d[i][2] = d[i][3] = 0.f; }
    warp_gemm(xT, sbase + 0, aoff, boff, d);
    #pragma unroll
    for (int nt = 0; nt < 16; nt++) {
        int o0 = nt * 8 + qk * 2;
        if (nd0 < N) *(float2*)(g_A + nd0 * 128 + o0) = make_float2(d[nt][0], d[nt][1]);
        if (nd8 < N) *(float2*)(g_A + nd8 * 128 + o0) = make_float2(d[nt][2], d[nt][3]);
    }
    #pragma unroll
    for (int i = 0; i < 16; i++) { d[i][0] = d[i][1] = d[i][2] = d[i][3] = 0.f; }
    warp_gemm(xT, sbase + 34816, aoff, boff, d);
    #pragma unroll
    for (int nt = 0; nt < 16; nt++) {
        int o0 = nt * 8 + qk * 2;
        if (nd0 < N) *(float2*)(g_B + nd0 * 128 + o0) = make_float2(d[nt][0], d[nt][1]);
        if (nd8 < N) *(float2*)(g_B + nd8 * 128 + o0) = make_float2(d[nt][2], d[nt][3]);
    }
}

// ---------------------------------------------------------------------------
// fused edge kernel: M=32/warp, N-split fp16 mma pipeline, 384 edges/tile
// ---------------------------------------------------------------------------
__global__ __launch_bounds__(ETHREADS) void edge_kernel(
    const float* __restrict__ pos, const float* __restrict__ edge_attr,
    const void* __restrict__ ei_raw,
    const float* __restrict__ eW1, const float* __restrict__ eb1,
    const float* __restrict__ eW2, const float* __restrict__ eb2,
    const float* __restrict__ cW1, const float* __restrict__ cb1,
    const float* __restrict__ cW2, const float* __restrict__ cb2,
    float* __restrict__ pos_out, int N, int E)
{
    extern __shared__ float smf[];
    char* smc = (char*)smf;
    unsigned sbase = smem_u32(smf);
    int tid = threadIdx.x, wid = tid >> 5, lane = tid & 31;
    int g = lane >> 3, l = lane & 7;
    int qm = lane >> 2, qk = lane & 3;

    // sv: w_rn 0, w_ea 128, eb1 256, eb2 384, cb1 512, cw2 640, cb2 768
    float* sv = smf;
    for (int i = tid; i < 128; i += ETHREADS) {
        sv[i]       = eW1[256 * 128 + i];
        sv[128 + i] = eW1[257 * 128 + i];
        sv[256 + i] = eb1[i];
        sv[384 + i] = eb2[i];
        sv[512 + i] = cb1[i];
        sv[640 + i] = cW2[i];
    }
    if (tid == 0) sv[768] = cb2[0];

    for (int idx = tid; idx < 16384; idx += ETHREADS) {
        int k = idx >> 7, o = idx & 127;
        unsigned off = (unsigned)(o * 272 + k * 2);
        *(__half*)(smc + W2HI_B + off) = __float2half_rn(eW2[idx]);
        *(__half*)(smc + C1HI_B + off) = __float2half_rn(cW1[idx]);
    }
    __syncthreads();

    float cb2v = sv[768];
    int is64 = g_is64;
    const long long* ei64 = (const long long*)ei_raw;
    const int*       ei32 = (const int*)ei_raw;

    float4 wr = *(const float4*)&sv[lane * 4];
    float4 we = *(const float4*)&sv[128 + lane * 4];
    float4 bi = *(const float4*)&sv[256 + lane * 4];

    unsigned atb = (unsigned)(AT_B + wid * 8704);
    unsigned aT = sbase + atb;
    unsigned bW2h = sbase + W2HI_B;
    unsigned bC1h = sbase + C1HI_B;
    unsigned aoff = (unsigned)((l + ((g & 1) << 3)) * 272 + (g >> 1) * 16);
    unsigned boff = (unsigned)((l + ((g >> 1) << 3)) * 272 + (g & 1) * 16);

    int ntiles = (E + TILE_E - 1) / TILE_E;
    for (int t = blockIdx.x; t < ntiles; t += gridDim.x) {
        int e0w = t * TILE_E + wid * 32;     // this warp's first edge (32 edges, 1/lane)

        // --- meta: each lane owns one edge ---
        int m_r = 0, m_c = 0;
        float m_rn = 1.0f, m_irn = 1.0f, m_ea = 0.0f, m_rx = 0.0f, m_ry = 0.0f, m_rz = 0.0f;
        {
            int e = e0w + lane;
            if (e < E) {
                int r, c;
                if (is64) { r = (int)ei64[e]; c = (int)ei64[E + e]; }
                else      { r = ei32[e];      c = ei32[E + e]; }
                r = min(max(r, 0), N - 1);
                c = min(max(c, 0), N - 1);
                float dx = pos[r * 3 + 0] - pos[c * 3 + 0];
                float dy = pos[r * 3 + 1] - pos[c * 3 + 1];
                float dz = pos[r * 3 + 2] - pos[c * 3 + 2];
                float nrm = sqrtf(dx * dx + dy * dy + dz * dz);
                float rn = fmaxf(nrm, 1e-8f);
                m_r = r; m_c = c; m_rn = rn; m_irn = 1.0f / rn;
                m_ea = edge_attr[e];
                m_rx = dx; m_ry = dy; m_rz = dz;
            }
        }

        // --- phase1: m = silu(A[row]+B[col]+rn*w_rn+ea*w_ea+eb1) -> fp16 tile (32 rows) ---
        #pragma unroll
        for (int row = 0; row < 32; row++) {
            int rsrc = __shfl_sync(0xffffffffu, m_r, row);
            int csrc = __shfl_sync(0xffffffffu, m_c, row);
            float rn  = __shfl_sync(0xffffffffu, m_rn, row);
            float eav = __shfl_sync(0xffffffffu, m_ea, row);
            float4 a = *(const float4*)(g_A + rsrc * 128 + lane * 4);
            float4 b = *(const float4*)(g_B + csrc * 128 + lane * 4);
            float v0 = silu(fmaf(eav, we.x, fmaf(rn, wr.x, a.x + b.x)) + bi.x);
            float v1 = silu(fmaf(eav, we.y, fmaf(rn, wr.y, a.y + b.y)) + bi.y);
            float v2 = silu(fmaf(eav, we.z, fmaf(rn, wr.z, a.z + b.z)) + bi.z);
            float v3 = silu(fmaf(eav, we.w, fmaf(rn, wr.w, a.w + b.w)) + bi.w);
            *(uint2*)(smc + atb + row * 272 + lane * 8) =
                make_uint2(pack2h(v0, v1), pack2h(v2, v3));
        }
        __syncwarp();

        // row -> agg/pos metadata for epilogues
        int ri0 = __shfl_sync(0xffffffffu, m_r, qm);
        int ri1 = __shfl_sync(0xffffffffu, m_r, qm + 8);
        int ri2 = __shfl_sync(0xffffffffu, m_r, qm + 16);
        int ri3 = __shfl_sync(0xffffffffu, m_r, qm + 24);
        bool ok0 = (e0w + qm) < E, ok1 = (e0w + qm + 8) < E;
        bool ok2 = (e0w + qm + 16) < E, ok3 = (e0w + qm + 24) < E;
        float* ga0 = g_agg + ri0 * 128;
        float* ga1 = g_agg + ri1 * 128;
        float* ga2 = g_agg + ri2 * 128;
        float* ga3 = g_agg + ri3 * 128;

        float d[16][4];
        unsigned m2p0[32];

        // --- GEMM2 pass0 (outs 0..63) ---
        #pragma unroll
        for (int i = 0; i < 16; i++) { d[i][0] = d[i][1] = d[i][2] = d[i][3] = 0.f; }
        warp_gemm32(aT, bW2h, aoff, boff, 0, d);
        #pragma unroll
        for (int s = 0; s < 4; s++)
        #pragma unroll
        for (int hh = 0; hh < 2; hh++) {
            int i = s * 2 + hh;
            int o0 = s * 16 + hh * 8 + qk * 2;
            float e0v = sv[384 + o0], e1v = sv[384 + o0 + 1];
            float v0 = silu(d[i][0] + e0v), v1 = silu(d[i][1] + e1v);
            float v2 = silu(d[i][2] + e0v), v3 = silu(d[i][3] + e1v);
            float u0 = silu(d[8 + i][0] + e0v), u1 = silu(d[8 + i][1] + e1v);
            float u2 = silu(d[8 + i][2] + e0v), u3 = silu(d[8 + i][3] + e1v);
            m2p0[i * 4 + 0] = pack2h(v0, v1);
            m2p0[i * 4 + 1] = pack2h(v2, v3);
            m2p0[i * 4 + 2] = pack2h(u0, u1);
            m2p0[i * 4 + 3] = pack2h(u2, u3);
            if (ok0) red2(ga0 + o0, v0, v1);
            if (ok1) red2(ga1 + o0, v2, v3);
            if (ok2) red2(ga2 + o0, u0, u1);
            if (ok3) red2(ga3 + o0, u2, u3);
        }

        // --- GEMM2 pass1 (outs 64..127) ---
        #pragma unroll
        for (int i = 0; i < 16; i++) { d[i][0] = d[i][1] = d[i][2] = d[i][3] = 0.f; }
        warp_gemm32(aT, bW2h, aoff, boff, 64, d);
        #pragma unroll
        for (int s = 0; s < 4; s++)
        #pragma unroll
        for (int hh = 0; hh < 2; hh++) {
            int i = s * 2 + hh;
            int o0 = 64 + s * 16 + hh * 8 + qk * 2;
            int p0 = o0 - 64;
            float e0v = sv[384 + o0], e1v = sv[384 + o0 + 1];
            float v0 = silu(d[i][0] + e0v), v1 = silu(d[i][1] + e1v);
            float v2 = silu(d[i][2] + e0v), v3 = silu(d[i][3] + e1v);
            float u0 = silu(d[8 + i][0] + e0v), u1 = silu(d[8 + i][1] + e1v);
            float u2 = silu(d[8 + i][2] + e0v), u3 = silu(d[8 + i][3] + e1v);
            // pass1 m2 -> tile
            *(unsigned*)(smc + atb + qm * 272 + o0 * 2) = pack2h(v0, v1);
            *(unsigned*)(smc + atb + (qm + 8) * 272 + o0 * 2) = pack2h(v2, v3);
            *(unsigned*)(smc + atb + (qm + 16) * 272 + o0 * 2) = pack2h(u0, u1);
            *(unsigned*)(smc + atb + (qm + 24) * 272 + o0 * 2) = pack2h(u2, u3);
            // parked pass0 m2 -> tile
            *(unsigned*)(smc + atb + qm * 272 + p0 * 2) = m2p0[i * 4 + 0];
            *(unsigned*)(smc + atb + (qm + 8) * 272 + p0 * 2) = m2p0[i * 4 + 1];
            *(unsigned*)(smc + atb + (qm + 16) * 272 + p0 * 2) = m2p0[i * 4 + 2];
            *(unsigned*)(smc + atb + (qm + 24) * 272 + p0 * 2) = m2p0[i * 4 + 3];
            if (ok0) red2(ga0 + o0, v0, v1);
            if (ok1) red2(ga1 + o0, v2, v3);
            if (ok2) red2(ga2 + o0, u0, u1);
            if (ok3) red2(ga3 + o0, u2, u3);
        }
        __syncwarp();

        // --- GEMM3: D2 = m2 @ cW1, two N-passes; coord partials ---
        float p[4] = {0.f, 0.f, 0.f, 0.f};
        #pragma unroll
        for (int pass = 0; pass < 2; pass++) {
            int nbase = pass * 64;
            #pragma unroll
            for (int i = 0; i < 16; i++) { d[i][0] = d[i][1] = d[i][2] = d[i][3] = 0.f; }
            warp_gemm32(aT, bC1h, aoff, boff, nbase, d);
            #pragma unroll
            for (int s = 0; s < 4; s++)
            #pragma unroll
            for (int hh = 0; hh < 2; hh++) {
                int i = s * 2 + hh;
                int o0 = nbase + s * 16 + hh * 8 + qk * 2;
                float c0 = sv[512 + o0], c1 = sv[512 + o0 + 1];
                float w0 = sv[640 + o0], w1 = sv[640 + o0 + 1];
                p[0] = fmaf(silu(d[i][0] + c0), w0, p[0]);
                p[0] = fmaf(silu(d[i][1] + c1), w1, p[0]);
                p[1] = fmaf(silu(d[i][2] + c0), w0, p[1]);
                p[1] = fmaf(silu(d[i][3] + c1), w1, p[1]);
                p[2] = fmaf(silu(d[8 + i][0] + c0), w0, p[2]);
                p[2] = fmaf(silu(d[8 + i][1] + c1), w1, p[2]);
                p[3] = fmaf(silu(d[8 + i][2] + c0), w0, p[3]);
                p[3] = fmaf(silu(d[8 + i][3] + c1), w1, p[3]);
            }
        }
        #pragma unroll
        for (int j = 0; j < 4; j++) {
            p[j] += __shfl_xor_sync(0xffffffffu, p[j], 1);
            p[j] += __shfl_xor_sync(0xffffffffu, p[j], 2);
        }
        #pragma unroll
        for (int j = 0; j < 4; j++) {
            int rowl = qm + j * 8;
            float irn = __shfl_sync(0xffffffffu, m_irn, rowl);
            float rx = __shfl_sync(0xffffffffu, m_rx, rowl);
            float ry = __shfl_sync(0xffffffffu, m_ry, rowl);
            float rz = __shfl_sync(0xffffffffu, m_rz, rowl);
            int ri = __shfl_sync(0xffffffffu, m_r, rowl);
            if (qk == 0 && (e0w + rowl) < E) {
                float sc = (p[j] + cb2v) * irn;
                atomicAdd(&pos_out[ri * 3 + 0], sc * rx);
                atomicAdd(&pos_out[ri * 3 + 1], sc * ry);
                atomicAdd(&pos_out[ri * 3 + 2], sc * rz);
            }
        }
        __syncwarp();
    }
}

// ---------------------------------------------------------------------------
// node MLP (fp16 mma, warp-private): hn = silu([h,agg]@nW1+nb1); h_new = h + hn@nW2+nb2
// ---------------------------------------------------------------------------
#define NODE_W  12
#define NODE_T  384
#define W1A_B   0
#define W1B_B   34816
#define W2N_B   69632
#define XT_B    104448    // per warp: Xh at +wid*8704, Xagg at +wid*8704+4352
#define NB_F    52224     // float idx: nb1[0..127], nb2[128..255]
#define NODE_SMEM 209920
__global__ __launch_bounds__(NODE_T) void node_kernel(
    const float* __restrict__ h,
    const float* __restrict__ nW1, const float* __restrict__ nb1,
    const float* __restrict__ nW2, const float* __restrict__ nb2,
    float* __restrict__ h_out, int N)
{
    extern __shared__ float smf[];
    char* smc = (char*)smf;
    unsigned sbase = smem_u32(smf);
    int tid = threadIdx.x, wid = tid >> 5, lane = tid & 31;
    int g = lane >> 3, l = lane & 7;
    int qm = lane >> 2, qk = lane & 3;

    for (int idx = tid; idx < 32768; idx += NODE_T) {
        int k = idx >> 7, o = idx & 127;
        unsigned off = (unsigned)(o * 272 + (k & 127) * 2);
        *(__half*)(smc + (k < 128 ? W1A_B : W1B_B) + off) = __float2half_rn(nW1[idx]);
    }
    for (int idx = tid; idx < 16384; idx += NODE_T) {
        int k = idx >> 7, o = idx & 127;
        *(__half*)(smc + W2N_B + o * 272 + k * 2) = __float2half_rn(nW2[idx]);
    }
    for (int i = tid; i < 128; i += NODE_T) {
        smf[NB_F + i] = nb1[i];
        smf[NB_F + 128 + i] = nb2[i];
    }
    __syncthreads();

    unsigned xh = sbase + XT_B + wid * 8704, xa = xh + 4352;
    unsigned w1a = sbase + W1A_B, w1b = sbase + W1B_B, w2 = sbase + W2N_B;
    unsigned aoff = (unsigned)((l + ((g & 1) << 3)) * 272 + (g >> 1) * 16);
    unsigned boff = (unsigned)((l + ((g >> 1) << 3)) * 272 + (g & 1) * 16);

    int n0w = blockIdx.x * (NODE_W * 16) + wid * 16;
    if (n0w >= N) return;

    #pragma unroll
    for (int row = 0; row < 16; row++) {
        int node = min(n0w + row, N - 1);
        float4 a = *(const float4*)(h + node * 128 + lane * 4);
        float4 b = *(const float4*)(g_agg + node * 128 + lane * 4);
        *(uint2*)(smc + (XT_B + wid * 8704) + row * 272 + lane * 8) =
            make_uint2(pack2h(a.x, a.y), pack2h(a.z, a.w));
        *(uint2*)(smc + (XT_B + wid * 8704 + 4352) + row * 272 + lane * 8) =
            make_uint2(pack2h(b.x, b.y), pack2h(b.z, b.w));
    }
    __syncwarp();

    float d[16][4];
    #pragma unroll
    for (int i = 0; i < 16; i++) { d[i][0] = d[i][1] = d[i][2] = d[i][3] = 0.f; }
    warp_gemm(xh, w1a, aoff, boff, d);
    warp_gemm(xa, w1b, aoff, boff, d);

    #pragma unroll
    for (int nt = 0; nt < 16; nt++) {
        int o0 = nt * 8 + qk * 2;
        float b0 = smf[NB_F + o0], b1 = smf[NB_F + o0 + 1];
        float v0 = silu(d[nt][0] + b0);
        float v1 = silu(d[nt][1] + b1);
        float v2 = silu(d[nt][2] + b0);
        float v3 = silu(d[nt][3] + b1);
        *(unsigned*)(smc + (XT_B + wid * 8704) + qm * 272 + o0 * 2) = pack2h(v0, v1);
        *(unsigned*)(smc + (XT_B + wid * 8704) + (qm + 8) * 272 + o0 * 2) = pack2h(v2, v3);
    }
    __syncwarp();

    #pragma unroll
    for (int i = 0; i < 16; i++) { d[i][0] = d[i][1] = d[i][2] = d[i][3] = 0.f; }
    warp_gemm(xh, w2, aoff, boff, d);

    int nd0 = n0w + qm, nd8 = n0w + qm + 8;
    #pragma unroll
    for (int nt = 0; nt < 16; nt++) {
        int o0 = nt * 8 + qk * 2;
        float b0 = smf[NB_F + 128 + o0], b1 = smf[NB_F + 128 + o0 + 1];
        if (nd0 < N) {
            float2 r = *(const float2*)(h + nd0 * 128 + o0);
            *(float2*)(h_out + nd0 * 128 + o0) = make_float2(d[nt][0] + b0 + r.x, d[nt][1] + b1 + r.y);
        }
        if (nd8 < N) {
            float2 r = *(const float2*)(h + nd8 * 128 + o0);
            *(float2*)(h_out + nd8 * 128 + o0) = make_float2(d[nt][2] + b0 + r.x, d[nt][3] + b1 + r.y);
        }
    }
}

// ---------------------------------------------------------------------------
extern "C" void kernel_launch(void* const* d_in, const int* in_sizes, int n_in,
                              void* d_out, int out_size)
{
    const float* h   = (const float*)d_in[0];
    const float* pos = (const float*)d_in[1];
    const float* ea  = (const float*)d_in[2];
    const void*  ei  = d_in[3];
    const float* eW1 = (const float*)d_in[4];
    const float* eb1 = (const float*)d_in[5];
    const float* eW2 = (const float*)d_in[6];
    const float* eb2 = (const float*)d_in[7];
    const float* nW1 = (const float*)d_in[8];
    const float* nb1 = (const float*)d_in[9];
    const float* nW2 = (const float*)d_in[10];
    const float* nb2 = (const float*)d_in[11];
    const float* cW1 = (const float*)d_in[12];
    const float* cb1 = (const float*)d_in[13];
    const float* cW2 = (const float*)d_in[14];
    const float* cb2 = (const float*)d_in[15];

    int N = in_sizes[0] / 128;
    int E = in_sizes[2];
    float* h_out   = (float*)d_out;
    float* pos_out = h_out + (size_t)N * 128;

    cudaFuncSetAttribute(pre_kernel,  cudaFuncAttributeMaxDynamicSharedMemorySize, PRE_SMEM2);
    cudaFuncSetAttribute(edge_kernel, cudaFuncAttributeMaxDynamicSharedMemorySize, EDGE_SMEM);
    cudaFuncSetAttribute(node_kernel, cudaFuncAttributeMaxDynamicSharedMemorySize, NODE_SMEM);

    int nsm = 148;
    cudaDeviceGetAttribute(&nsm, cudaDevAttrMultiProcessorCount, 0);

    detect_kernel<<<1, 256>>>(ei, N, E);
    init_kernel<<<(N * 128 + 255) / 256, 256>>>(pos, pos_out, N);
    pre_kernel<<<(N + 191) / 192, 384, PRE_SMEM2>>>(h, eW1, N);
    edge_kernel<<<nsm, ETHREADS, EDGE_SMEM>>>(pos, ea, ei, eW1, eb1, eW2, eb2,
                                              cW1, cb1, cW2, cb2, pos_out, N, E);
    node_kernel<<<(N + NODE_W * 16 - 1) / (NODE_W * 16), NODE_T, NODE_SMEM>>>(
        h, nW1, nb1, nW2, nb2, h_out, N);
}

// round 11
// speedup vs baseline: 6.3426x; 1.0939x over previous
#include <cuda_runtime.h>
#include <cuda_fp16.h>

#define ETHREADS 512
#define EWARPS   16
#define TILE_E   (EWARPS * 16)
#define NMAX 50000

// Scratch (device globals: allocation-free rule)
__device__ __half g_Ah[NMAX * 128];  // h @ eW1[0:128]   (fp16, gathered by row)
__device__ __half g_Bh[NMAX * 128];  // h @ eW1[128:256] (fp16, gathered by col)
__device__ float  g_agg[NMAX * 128]; // segment_sum(m2, row)
__device__ int    g_is64;            // edge_index dtype flag

__device__ __forceinline__ float tanh_a(float x) {
    float y; asm("tanh.approx.f32 %0, %1;" : "=f"(y) : "f"(x)); return y;
}
__device__ __forceinline__ float silu(float x) {
    return x * fmaf(0.5f, tanh_a(0.5f * x), 0.5f);
}
__device__ __forceinline__ unsigned smem_u32(const void* p) {
    unsigned a;
    asm("{ .reg .u64 t; cvta.to.shared.u64 t, %1; cvt.u32.u64 %0, t; }" : "=r"(a) : "l"(p));
    return a;
}
__device__ __forceinline__ unsigned pack2h(float v0, float v1) {
    __half2 h = __floats2half2_rn(v0, v1);
    return *(unsigned*)&h;
}
__device__ __forceinline__ void ldsm4(unsigned r[4], unsigned addr) {
    asm volatile("ldmatrix.sync.aligned.m8n8.x4.shared.b16 {%0,%1,%2,%3}, [%4];"
                 : "=r"(r[0]), "=r"(r[1]), "=r"(r[2]), "=r"(r[3]) : "r"(addr));
}
__device__ __forceinline__ void mma_f16(float d[4], const unsigned a[4], unsigned b0, unsigned b1) {
    asm volatile("mma.sync.aligned.m16n8k16.row.col.f32.f16.f16.f32 "
                 "{%0,%1,%2,%3}, {%4,%5,%6,%7}, {%8,%9}, {%0,%1,%2,%3};"
                 : "+f"(d[0]), "+f"(d[1]), "+f"(d[2]), "+f"(d[3])
                 : "r"(a[0]), "r"(a[1]), "r"(a[2]), "r"(a[3]), "r"(b0), "r"(b1));
}
__device__ __forceinline__ void red2(float* p, float v0, float v1) {
    asm volatile("red.global.add.v2.f32 [%0], {%1, %2};" :: "l"(p), "f"(v0), "f"(v1) : "memory");
}

// M=16 warp GEMM: 16 x 128 x 128 fp16 (fp32 accum). A row stride 272B.
__device__ __forceinline__ void warp_gemm(unsigned aT, unsigned bT,
                                          unsigned aoff, unsigned boff, float (*d)[4]) {
    #pragma unroll
    for (int ks = 0; ks < 8; ks++) {
        unsigned ah[4];
        ldsm4(ah, aT + aoff + ks * 32);
        #pragma unroll
        for (int np = 0; np < 8; np++) {
            unsigned bh[4];
            ldsm4(bh, bT + boff + np * 4352 + ks * 32);
            mma_f16(d[np * 2],     ah, bh[0], bh[1]);
            mma_f16(d[np * 2 + 1], ah, bh[2], bh[3]);
        }
    }
}

// SMEM byte layout for edge kernel
#define W2HI_B 4096
#define C1HI_B 38912
#define AT_B   73728      // EWARPS x 4352
#define EDGE_SMEM (AT_B + EWARPS * 4352)   // 143360

// ---------------------------------------------------------------------------
__global__ void detect_kernel(const void* __restrict__ ei, int N, int E) {
    __shared__ int ok;
    if (threadIdx.x == 0) ok = 1;
    __syncthreads();
    int n = (E < 256) ? E : 256;
    if ((int)threadIdx.x < n) {
        long long v = ((const long long*)ei)[threadIdx.x];
        if (v < 0 || v >= (long long)N) atomicExch(&ok, 0);
    }
    __syncthreads();
    if (threadIdx.x == 0) g_is64 = ok;
}

__global__ void init_kernel(const float* __restrict__ pos, float* __restrict__ pos_out, int N) {
    int i = blockIdx.x * blockDim.x + threadIdx.x;
    if (i < N * 128) g_agg[i] = 0.0f;
    if (i < N * 3) pos_out[i] = pos[i];
}

// ---------------------------------------------------------------------------
// precompute (fp16 mma): A = h @ eW1[0:128,:], B = h @ eW1[128:256,:] -> fp16
// 12 warps x 16 nodes = 192 nodes/block
// ---------------------------------------------------------------------------
#define PRE_SMEM2 121856   // W0 34816 | W1 34816 | X tiles 12*4352
__global__ __launch_bounds__(384) void pre_kernel(
    const float* __restrict__ h, const float* __restrict__ eW1, int N)
{
    extern __shared__ float smf[];
    char* smc = (char*)smf;
    unsigned sbase = smem_u32(smf);
    int tid = threadIdx.x, wid = tid >> 5, lane = tid & 31;
    int g = lane >> 3, l = lane & 7;
    int qm = lane >> 2, qk = lane & 3;

    for (int idx = tid; idx < 32768; idx += 384) {
        int k = idx >> 7, o = idx & 127;
        *(__half*)(smc + (k < 128 ? 0 : 34816) + o * 272 + (k & 127) * 2) =
            __float2half_rn(eW1[idx]);
    }
    __syncthreads();

    unsigned xT = sbase + 69632 + wid * 4352;
    unsigned aoff = (unsigned)((l + ((g & 1) << 3)) * 272 + (g >> 1) * 16);
    unsigned boff = (unsigned)((l + ((g >> 1) << 3)) * 272 + (g & 1) * 16);

    int n0w = blockIdx.x * 192 + wid * 16;
    if (n0w >= N) return;

    #pragma unroll
    for (int row = 0; row < 16; row++) {
        int node = min(n0w + row, N - 1);
        float4 a = *(const float4*)(h + node * 128 + lane * 4);
        *(uint2*)(smc + (69632 + wid * 4352) + row * 272 + lane * 8) =
            make_uint2(pack2h(a.x, a.y), pack2h(a.z, a.w));
    }
    __syncwarp();

    int nd0 = n0w + qm, nd8 = n0w + qm + 8;
    float d[16][4];
    #pragma unroll
    for (int i = 0; i < 16; i++) { d[i][0] = d[i][1] = d[i][2] = d[i][3] = 0.f; }
    warp_gemm(xT, sbase + 0, aoff, boff, d);
    #pragma unroll
    for (int nt = 0; nt < 16; nt++) {
        int o0 = nt * 8 + qk * 2;
        if (nd0 < N) *(unsigned*)((char*)g_Ah + nd0 * 256 + o0 * 2) = pack2h(d[nt][0], d[nt][1]);
        if (nd8 < N) *(unsigned*)((char*)g_Ah + nd8 * 256 + o0 * 2) = pack2h(d[nt][2], d[nt][3]);
    }
    #pragma unroll
    for (int i = 0; i < 16; i++) { d[i][0] = d[i][1] = d[i][2] = d[i][3] = 0.f; }
    warp_gemm(xT, sbase + 34816, aoff, boff, d);
    #pragma unroll
    for (int nt = 0; nt < 16; nt++) {
        int o0 = nt * 8 + qk * 2;
        if (nd0 < N) *(unsigned*)((char*)g_Bh + nd0 * 256 + o0 * 2) = pack2h(d[nt][0], d[nt][1]);
        if (nd8 < N) *(unsigned*)((char*)g_Bh + nd8 * 256 + o0 * 2) = pack2h(d[nt][2], d[nt][3]);
    }
}

// ---------------------------------------------------------------------------
// fused edge kernel: warp-private fp16 mma pipeline, 256 edges/tile (R9 config)
// ---------------------------------------------------------------------------
__global__ __launch_bounds__(ETHREADS) void edge_kernel(
    const float* __restrict__ pos, const float* __restrict__ edge_attr,
    const void* __restrict__ ei_raw,
    const float* __restrict__ eW1, const float* __restrict__ eb1,
    const float* __restrict__ eW2, const float* __restrict__ eb2,
    const float* __restrict__ cW1, const float* __restrict__ cb1,
    const float* __restrict__ cW2, const float* __restrict__ cb2,
    float* __restrict__ pos_out, int N, int E)
{
    extern __shared__ float smf[];
    char* smc = (char*)smf;
    unsigned sbase = smem_u32(smf);
    int tid = threadIdx.x, wid = tid >> 5, lane = tid & 31;
    int g = lane >> 3, l = lane & 7;
    int qm = lane >> 2, qk = lane & 3;

    // sv: w_rn 0, w_ea 128, eb1 256, eb2 384, cb1 512, cw2 640, cb2 768
    float* sv = smf;
    for (int i = tid; i < 128; i += ETHREADS) {
        sv[i]       = eW1[256 * 128 + i];
        sv[128 + i] = eW1[257 * 128 + i];
        sv[256 + i] = eb1[i];
        sv[384 + i] = eb2[i];
        sv[512 + i] = cb1[i];
        sv[640 + i] = cW2[i];
    }
    if (tid == 0) sv[768] = cb2[0];

    for (int idx = tid; idx < 16384; idx += ETHREADS) {
        int k = idx >> 7, o = idx & 127;
        unsigned off = (unsigned)(o * 272 + k * 2);
        *(__half*)(smc + W2HI_B + off) = __float2half_rn(eW2[idx]);
        *(__half*)(smc + C1HI_B + off) = __float2half_rn(cW1[idx]);
    }
    __syncthreads();

    float cb2v = sv[768];
    int is64 = g_is64;
    const long long* ei64 = (const long long*)ei_raw;
    const int*       ei32 = (const int*)ei_raw;

    float4 wr = *(const float4*)&sv[lane * 4];
    float4 we = *(const float4*)&sv[128 + lane * 4];
    float4 bi = *(const float4*)&sv[256 + lane * 4];

    unsigned atb = (unsigned)(AT_B + wid * 4352);
    unsigned aT = sbase + atb;
    unsigned bW2h = sbase + W2HI_B;
    unsigned bC1h = sbase + C1HI_B;
    unsigned aoff = (unsigned)((l + ((g & 1) << 3)) * 272 + (g >> 1) * 16);
    unsigned boff = (unsigned)((l + ((g >> 1) << 3)) * 272 + (g & 1) * 16);

    int ntiles = (E + TILE_E - 1) / TILE_E;
    for (int t = blockIdx.x; t < ntiles; t += gridDim.x) {
        int e0w = t * TILE_E + wid * 16;     // this warp's first edge

        // --- meta (lanes 0..15 hold edge lane's data) ---
        int m_r = 0, m_c = 0;
        float m_rn = 1.0f, m_irn = 1.0f, m_ea = 0.0f, m_rx = 0.0f, m_ry = 0.0f, m_rz = 0.0f;
        if (lane < 16) {
            int e = e0w + lane;
            if (e < E) {
                int r, c;
                if (is64) { r = (int)ei64[e]; c = (int)ei64[E + e]; }
                else      { r = ei32[e];      c = ei32[E + e]; }
                r = min(max(r, 0), N - 1);
                c = min(max(c, 0), N - 1);
                float dx = pos[r * 3 + 0] - pos[c * 3 + 0];
                float dy = pos[r * 3 + 1] - pos[c * 3 + 1];
                float dz = pos[r * 3 + 2] - pos[c * 3 + 2];
                float nrm = sqrtf(dx * dx + dy * dy + dz * dz);
                float rn = fmaxf(nrm, 1e-8f);
                m_r = r; m_c = c; m_rn = rn; m_irn = 1.0f / rn;
                m_ea = edge_attr[e];
                m_rx = dx; m_ry = dy; m_rz = dz;
            }
        }

        // --- phase1: m = silu(A[row]+B[col]+rn*w_rn+ea*w_ea+eb1) -> fp16 tile ---
        #pragma unroll
        for (int row = 0; row < 16; row++) {
            int rsrc = __shfl_sync(0xffffffffu, m_r, row);
            int csrc = __shfl_sync(0xffffffffu, m_c, row);
            float rn  = __shfl_sync(0xffffffffu, m_rn, row);
            float eav = __shfl_sync(0xffffffffu, m_ea, row);
            uint2 av = *(const uint2*)((const char*)g_Ah + rsrc * 256 + lane * 8);
            uint2 bv = *(const uint2*)((const char*)g_Bh + csrc * 256 + lane * 8);
            float2 a01 = __half22float2(*(__half2*)&av.x);
            float2 a23 = __half22float2(*(__half2*)&av.y);
            float2 b01 = __half22float2(*(__half2*)&bv.x);
            float2 b23 = __half22float2(*(__half2*)&bv.y);
            float v0 = silu(fmaf(eav, we.x, fmaf(rn, wr.x, a01.x + b01.x)) + bi.x);
            float v1 = silu(fmaf(eav, we.y, fmaf(rn, wr.y, a01.y + b01.y)) + bi.y);
            float v2 = silu(fmaf(eav, we.z, fmaf(rn, wr.z, a23.x + b23.x)) + bi.z);
            float v3 = silu(fmaf(eav, we.w, fmaf(rn, wr.w, a23.y + b23.y)) + bi.w);
            *(uint2*)(smc + atb + row * 272 + lane * 8) =
                make_uint2(pack2h(v0, v1), pack2h(v2, v3));
        }
        __syncwarp();

        // --- GEMM2: D1 = m @ eW2 ---
        float d[16][4];
        #pragma unroll
        for (int i = 0; i < 16; i++) { d[i][0] = d[i][1] = d[i][2] = d[i][3] = 0.f; }
        warp_gemm(aT, bW2h, aoff, boff, d);

        // --- epilogue1: m2 = silu(D1 + eb2) -> tile (overwrite) + agg red.v2 ---
        int ri0 = __shfl_sync(0xffffffffu, m_r, qm);
        int ri8 = __shfl_sync(0xffffffffu, m_r, qm + 8);
        bool ok0 = (e0w + qm) < E, ok8 = (e0w + qm + 8) < E;
        float* ga0 = g_agg + ri0 * 128;
        float* ga8 = g_agg + ri8 * 128;
        #pragma unroll
        for (int nt = 0; nt < 16; nt++) {
            int o0 = nt * 8 + qk * 2;
            float e_0 = sv[384 + o0], e_1 = sv[384 + o0 + 1];
            float v0 = silu(d[nt][0] + e_0);
            float v1 = silu(d[nt][1] + e_1);
            float v2 = silu(d[nt][2] + e_0);
            float v3 = silu(d[nt][3] + e_1);
            *(unsigned*)(smc + atb + qm * 272 + o0 * 2) = pack2h(v0, v1);
            *(unsigned*)(smc + atb + (qm + 8) * 272 + o0 * 2) = pack2h(v2, v3);
            if (ok0) red2(ga0 + o0, v0, v1);
            if (ok8) red2(ga8 + o0, v2, v3);
        }
        __syncwarp();

        // --- GEMM3: D2 = m2 @ cW1 ---
        #pragma unroll
        for (int i = 0; i < 16; i++) { d[i][0] = d[i][1] = d[i][2] = d[i][3] = 0.f; }
        warp_gemm(aT, bC1h, aoff, boff, d);

        // --- epilogue2: coord = silu(D2 + cb1) . cW2; pos atomics ---
        float pA = 0.0f, pB = 0.0f;
        #pragma unroll
        for (int nt = 0; nt < 16; nt++) {
            int o0 = nt * 8 + qk * 2;
            float c_0 = sv[512 + o0], c_1 = sv[512 + o0 + 1];
            float w_0 = sv[640 + o0], w_1 = sv[640 + o0 + 1];
            pA = fmaf(silu(d[nt][0] + c_0), w_0, pA);
            pA = fmaf(silu(d[nt][1] + c_1), w_1, pA);
            pB = fmaf(silu(d[nt][2] + c_0), w_0, pB);
            pB = fmaf(silu(d[nt][3] + c_1), w_1, pB);
        }
        pA += __shfl_xor_sync(0xffffffffu, pA, 1);
        pA += __shfl_xor_sync(0xffffffffu, pA, 2);
        pB += __shfl_xor_sync(0xffffffffu, pB, 1);
        pB += __shfl_xor_sync(0xffffffffu, pB, 2);
        float irn0 = __shfl_sync(0xffffffffu, m_irn, qm);
        float irn8 = __shfl_sync(0xffffffffu, m_irn, qm + 8);
        float rx0 = __shfl_sync(0xffffffffu, m_rx, qm), rx8 = __shfl_sync(0xffffffffu, m_rx, qm + 8);
        float ry0 = __shfl_sync(0xffffffffu, m_ry, qm), ry8 = __shfl_sync(0xffffffffu, m_ry, qm + 8);
        float rz0 = __shfl_sync(0xffffffffu, m_rz, qm), rz8 = __shfl_sync(0xffffffffu, m_rz, qm + 8);
        if (qk == 0) {
            if (ok0) {
                float s = (pA + cb2v) * irn0;
                atomicAdd(&pos_out[ri0 * 3 + 0], s * rx0);
                atomicAdd(&pos_out[ri0 * 3 + 1], s * ry0);
                atomicAdd(&pos_out[ri0 * 3 + 2], s * rz0);
            }
            if (ok8) {
                float s = (pB + cb2v) * irn8;
                atomicAdd(&pos_out[ri8 * 3 + 0], s * rx8);
                atomicAdd(&pos_out[ri8 * 3 + 1], s * ry8);
                atomicAdd(&pos_out[ri8 * 3 + 2], s * rz8);
            }
        }
        __syncwarp();
    }
}

// ---------------------------------------------------------------------------
// node MLP (fp16 mma, warp-private): hn = silu([h,agg]@nW1+nb1); h_new = h + hn@nW2+nb2
// ---------------------------------------------------------------------------
#define NODE_W  12
#define NODE_T  384
#define W1A_B   0
#define W1B_B   34816
#define W2N_B   69632
#define XT_B    104448    // per warp: Xh at +wid*8704, Xagg at +wid*8704+4352
#define NB_F    52224     // float idx: nb1[0..127], nb2[128..255]
#define NODE_SMEM 209920
__global__ __launch_bounds__(NODE_T) void node_kernel(
    const float* __restrict__ h,
    const float* __restrict__ nW1, const float* __restrict__ nb1,
    const float* __restrict__ nW2, const float* __restrict__ nb2,
    float* __restrict__ h_out, int N)
{
    extern __shared__ float smf[];
    char* smc = (char*)smf;
    unsigned sbase = smem_u32(smf);
    int tid = threadIdx.x, wid = tid >> 5, lane = tid & 31;
    int g = lane >> 3, l = lane & 7;
    int qm = lane >> 2, qk = lane & 3;

    for (int idx = tid; idx < 32768; idx += NODE_T) {
        int k = idx >> 7, o = idx & 127;
        unsigned off = (unsigned)(o * 272 + (k & 127) * 2);
        *(__half*)(smc + (k < 128 ? W1A_B : W1B_B) + off) = __float2half_rn(nW1[idx]);
    }
    for (int idx = tid; idx < 16384; idx += NODE_T) {
        int k = idx >> 7, o = idx & 127;
        *(__half*)(smc + W2N_B + o * 272 + k * 2) = __float2half_rn(nW2[idx]);
    }
    for (int i = tid; i < 128; i += NODE_T) {
        smf[NB_F + i] = nb1[i];
        smf[NB_F + 128 + i] = nb2[i];
    }
    __syncthreads();

    unsigned xh = sbase + XT_B + wid * 8704, xa = xh + 4352;
    unsigned w1a = sbase + W1A_B, w1b = sbase + W1B_B, w2 = sbase + W2N_B;
    unsigned aoff = (unsigned)((l + ((g & 1) << 3)) * 272 + (g >> 1) * 16);
    unsigned boff = (unsigned)((l + ((g >> 1) << 3)) * 272 + (g & 1) * 16);

    int n0w = blockIdx.x * (NODE_W * 16) + wid * 16;
    if (n0w >= N) return;

    #pragma unroll
    for (int row = 0; row < 16; row++) {
        int node = min(n0w + row, N - 1);
        float4 a = *(const float4*)(h + node * 128 + lane * 4);
        float4 b = *(const float4*)(g_agg + node * 128 + lane * 4);
        *(uint2*)(smc + (XT_B + wid * 8704) + row * 272 + lane * 8) =
            make_uint2(pack2h(a.x, a.y), pack2h(a.z, a.w));
        *(uint2*)(smc + (XT_B + wid * 8704 + 4352) + row * 272 + lane * 8) =
            make_uint2(pack2h(b.x, b.y), pack2h(b.z, b.w));
    }
    __syncwarp();

    float d[16][4];
    #pragma unroll
    for (int i = 0; i < 16; i++) { d[i][0] = d[i][1] = d[i][2] = d[i][3] = 0.f; }
    warp_gemm(xh, w1a, aoff, boff, d);
    warp_gemm(xa, w1b, aoff, boff, d);

    #pragma unroll
    for (int nt = 0; nt < 16; nt++) {
        int o0 = nt * 8 + qk * 2;
        float b0 = smf[NB_F + o0], b1 = smf[NB_F + o0 + 1];
        float v0 = silu(d[nt][0] + b0);
        float v1 = silu(d[nt][1] + b1);
        float v2 = silu(d[nt][2] + b0);
        float v3 = silu(d[nt][3] + b1);
        *(unsigned*)(smc + (XT_B + wid * 8704) + qm * 272 + o0 * 2) = pack2h(v0, v1);
        *(unsigned*)(smc + (XT_B + wid * 8704) + (qm + 8) * 272 + o0 * 2) = pack2h(v2, v3);
    }
    __syncwarp();

    #pragma unroll
    for (int i = 0; i < 16; i++) { d[i][0] = d[i][1] = d[i][2] = d[i][3] = 0.f; }
    warp_gemm(xh, w2, aoff, boff, d);

    int nd0 = n0w + qm, nd8 = n0w + qm + 8;
    #pragma unroll
    for (int nt = 0; nt < 16; nt++) {
        int o0 = nt * 8 + qk * 2;
        float b0 = smf[NB_F + 128 + o0], b1 = smf[NB_F + 128 + o0 + 1];
        if (nd0 < N) {
            float2 r = *(const float2*)(h + nd0 * 128 + o0);
            *(float2*)(h_out + nd0 * 128 + o0) = make_float2(d[nt][0] + b0 + r.x, d[nt][1] + b1 + r.y);
        }
        if (nd8 < N) {
            float2 r = *(const float2*)(h + nd8 * 128 + o0);
            *(float2*)(h_out + nd8 * 128 + o0) = make_float2(d[nt][2] + b0 + r.x, d[nt][3] + b1 + r.y);
        }
    }
}

// ---------------------------------------------------------------------------
extern "C" void kernel_launch(void* const* d_in, const int* in_sizes, int n_in,
                              void* d_out, int out_size)
{
    const float* h   = (const float*)d_in[0];
    const float* pos = (const float*)d_in[1];
    const float* ea  = (const float*)d_in[2];
    const void*  ei  = d_in[3];
    const float* eW1 = (const float*)d_in[4];
    const float* eb1 = (const float*)d_in[5];
    const float* eW2 = (const float*)d_in[6];
    const float* eb2 = (const float*)d_in[7];
    const float* nW1 = (const float*)d_in[8];
    const float* nb1 = (const float*)d_in[9];
    const float* nW2 = (const float*)d_in[10];
    const float* nb2 = (const float*)d_in[11];
    const float* cW1 = (const float*)d_in[12];
    const float* cb1 = (const float*)d_in[13];
    const float* cW2 = (const float*)d_in[14];
    const float* cb2 = (const float*)d_in[15];

    int N = in_sizes[0] / 128;
    int E = in_sizes[2];
    float* h_out   = (float*)d_out;
    float* pos_out = h_out + (size_t)N * 128;

    cudaFuncSetAttribute(pre_kernel,  cudaFuncAttributeMaxDynamicSharedMemorySize, PRE_SMEM2);
    cudaFuncSetAttribute(edge_kernel, cudaFuncAttributeMaxDynamicSharedMemorySize, EDGE_SMEM);
    cudaFuncSetAttribute(node_kernel, cudaFuncAttributeMaxDynamicSharedMemorySize, NODE_SMEM);

    int nsm = 148;
    cudaDeviceGetAttribute(&nsm, cudaDevAttrMultiProcessorCount, 0);

    detect_kernel<<<1, 256>>>(ei, N, E);
    init_kernel<<<(N * 128 + 255) / 256, 256>>>(pos, pos_out, N);
    pre_kernel<<<(N + 191) / 192, 384, PRE_SMEM2>>>(h, eW1, N);
    edge_kernel<<<nsm, ETHREADS, EDGE_SMEM>>>(pos, ea, ei, eW1, eb1, eW2, eb2,
                                              cW1, cb1, cW2, cb2, pos_out, N, E);
    node_kernel<<<(N + NODE_W * 16 - 1) / (NODE_W * 16), NODE_T, NODE_SMEM>>>(
        h, nW1, nb1, nW2, nb2, h_out, N);
}

// round 12
// speedup vs baseline: 6.4796x; 1.0216x over previous
#include <cuda_runtime.h>
#include <cuda_fp16.h>

#define ETHREADS 512
#define EWARPS   16
#define EPAIRS   8
#define TILE_E   (EPAIRS * 32)
#define NMAX 50000

// Scratch (device globals: allocation-free rule)
__device__ __half g_Ah[NMAX * 128];  // h @ eW1[0:128]   (fp16, gathered by row)
__device__ __half g_Bh[NMAX * 128];  // h @ eW1[128:256] (fp16, gathered by col)
__device__ float  g_agg[NMAX * 128]; // segment_sum(m2, row)
__device__ int    g_is64;            // edge_index dtype flag

__device__ __forceinline__ float tanh_a(float x) {
    float y; asm("tanh.approx.f32 %0, %1;" : "=f"(y) : "f"(x)); return y;
}
__device__ __forceinline__ float silu(float x) {
    return x * fmaf(0.5f, tanh_a(0.5f * x), 0.5f);
}
__device__ __forceinline__ unsigned smem_u32(const void* p) {
    unsigned a;
    asm("{ .reg .u64 t; cvta.to.shared.u64 t, %1; cvt.u32.u64 %0, t; }" : "=r"(a) : "l"(p));
    return a;
}
__device__ __forceinline__ unsigned pack2h(float v0, float v1) {
    __half2 h = __floats2half2_rn(v0, v1);
    return *(unsigned*)&h;
}
__device__ __forceinline__ void ldsm4(unsigned r[4], unsigned addr) {
    asm volatile("ldmatrix.sync.aligned.m8n8.x4.shared.b16 {%0,%1,%2,%3}, [%4];"
                 : "=r"(r[0]), "=r"(r[1]), "=r"(r[2]), "=r"(r[3]) : "r"(addr));
}
__device__ __forceinline__ void mma_f16(float d[4], const unsigned a[4], unsigned b0, unsigned b1) {
    asm volatile("mma.sync.aligned.m16n8k16.row.col.f32.f16.f16.f32 "
                 "{%0,%1,%2,%3}, {%4,%5,%6,%7}, {%8,%9}, {%0,%1,%2,%3};"
                 : "+f"(d[0]), "+f"(d[1]), "+f"(d[2]), "+f"(d[3])
                 : "r"(a[0]), "r"(a[1]), "r"(a[2]), "r"(a[3]), "r"(b0), "r"(b1));
}
__device__ __forceinline__ void red2(float* p, float v0, float v1) {
    asm volatile("red.global.add.v2.f32 [%0], {%1, %2};" :: "l"(p), "f"(v0), "f"(v1) : "memory");
}
__device__ __forceinline__ void bar_pair(int id) {
    asm volatile("bar.sync %0, 64;" :: "r"(id) : "memory");
}

// M=16 warp GEMM: 16 x 128 x 128 fp16 (fp32 accum). A row stride 272B. (pre/node)
__device__ __forceinline__ void warp_gemm(unsigned aT, unsigned bT,
                                          unsigned aoff, unsigned boff, float (*d)[4]) {
    #pragma unroll
    for (int ks = 0; ks < 8; ks++) {
        unsigned ah[4];
        ldsm4(ah, aT + aoff + ks * 32);
        #pragma unroll
        for (int np = 0; np < 8; np++) {
            unsigned bh[4];
            ldsm4(bh, bT + boff + np * 4352 + ks * 32);
            mma_f16(d[np * 2],     ah, bh[0], bh[1]);
            mma_f16(d[np * 2 + 1], ah, bh[2], bh[3]);
        }
    }
}

// M=32, N=64 warp GEMM (one N-half starting at nbase).
// d[s*2+hh] rows qm,qm+8 ; d[8+s*2+hh] rows qm+16,qm+24. col = nbase+s*16+hh*8+qk*2
__device__ __forceinline__ void warp_gemm32(unsigned aT, unsigned bT,
                                            unsigned aoff, unsigned boff,
                                            int nbase, float (*d)[4]) {
    #pragma unroll
    for (int ks = 0; ks < 8; ks++) {
        unsigned a0[4], a1[4];
        ldsm4(a0, aT + aoff + ks * 32);
        ldsm4(a1, aT + aoff + 16 * 272 + ks * 32);
        #pragma unroll
        for (int s = 0; s < 4; s++) {
            unsigned bh[4];
            ldsm4(bh, bT + boff + (unsigned)(nbase + s * 16) * 272 + ks * 32);
            mma_f16(d[s * 2],         a0, bh[0], bh[1]);
            mma_f16(d[s * 2 + 1],     a0, bh[2], bh[3]);
            mma_f16(d[8 + s * 2],     a1, bh[0], bh[1]);
            mma_f16(d[8 + s * 2 + 1], a1, bh[2], bh[3]);
        }
    }
}

// SMEM byte layout for edge kernel
#define W2HI_B 4096
#define C1HI_B 38912
#define AT_B   73728                     // EPAIRS x 8704 (32 rows x 272B)
#define META_B (AT_B + EPAIRS * 8704)    // 143360; per pair 1024B:
                                         //   rowi +0, irn +128, rx +256, ry +384, rz +512, part +640
#define EDGE_SMEM (META_B + EPAIRS * 1024)   // 151552

// ---------------------------------------------------------------------------
__global__ void detect_kernel(const void* __restrict__ ei, int N, int E) {
    __shared__ int ok;
    if (threadIdx.x == 0) ok = 1;
    __syncthreads();
    int n = (E < 256) ? E : 256;
    if ((int)threadIdx.x < n) {
        long long v = ((const long long*)ei)[threadIdx.x];
        if (v < 0 || v >= (long long)N) atomicExch(&ok, 0);
    }
    __syncthreads();
    if (threadIdx.x == 0) g_is64 = ok;
}

__global__ void init_kernel(const float* __restrict__ pos, float* __restrict__ pos_out, int N) {
    int i = blockIdx.x * blockDim.x + threadIdx.x;
    if (i < N * 128) g_agg[i] = 0.0f;
    if (i < N * 3) pos_out[i] = pos[i];
}

// ---------------------------------------------------------------------------
// precompute (fp16 mma): A = h @ eW1[0:128,:], B = h @ eW1[128:256,:] -> fp16
// ---------------------------------------------------------------------------
#define PRE_SMEM2 121856   // W0 34816 | W1 34816 | X tiles 12*4352
__global__ __launch_bounds__(384) void pre_kernel(
    const float* __restrict__ h, const float* __restrict__ eW1, int N)
{
    extern __shared__ float smf[];
    char* smc = (char*)smf;
    unsigned sbase = smem_u32(smf);
    int tid = threadIdx.x, wid = tid >> 5, lane = tid & 31;
    int g = lane >> 3, l = lane & 7;
    int qm = lane >> 2, qk = lane & 3;

    for (int idx = tid; idx < 32768; idx += 384) {
        int k = idx >> 7, o = idx & 127;
        *(__half*)(smc + (k < 128 ? 0 : 34816) + o * 272 + (k & 127) * 2) =
            __float2half_rn(eW1[idx]);
    }
    __syncthreads();

    unsigned xT = sbase + 69632 + wid * 4352;
    unsigned aoff = (unsigned)((l + ((g & 1) << 3)) * 272 + (g >> 1) * 16);
    unsigned boff = (unsigned)((l + ((g >> 1) << 3)) * 272 + (g & 1) * 16);

    int n0w = blockIdx.x * 192 + wid * 16;
    if (n0w >= N) return;

    #pragma unroll
    for (int row = 0; row < 16; row++) {
        int node = min(n0w + row, N - 1);
        float4 a = *(const float4*)(h + node * 128 + lane * 4);
        *(uint2*)(smc + (69632 + wid * 4352) + row * 272 + lane * 8) =
            make_uint2(pack2h(a.x, a.y), pack2h(a.z, a.w));
    }
    __syncwarp();

    int nd0 = n0w + qm, nd8 = n0w + qm + 8;
    float d[16][4];
    #pragma unroll
    for (int i = 0; i < 16; i++) { d[i][0] = d[i][1] = d[i][2] = d[i][3] = 0.f; }
    warp_gemm(xT, sbase + 0, aoff, boff, d);
    #pragma unroll
    for (int nt = 0; nt < 16; nt++) {
        int o0 = nt * 8 + qk * 2;
        if (nd0 < N) *(unsigned*)((char*)g_Ah + nd0 * 256 + o0 * 2) = pack2h(d[nt][0], d[nt][1]);
        if (nd8 < N) *(unsigned*)((char*)g_Ah + nd8 * 256 + o0 * 2) = pack2h(d[nt][2], d[nt][3]);
    }
    #pragma unroll
    for (int i = 0; i < 16; i++) { d[i][0] = d[i][1] = d[i][2] = d[i][3] = 0.f; }
    warp_gemm(xT, sbase + 34816, aoff, boff, d);
    #pragma unroll
    for (int nt = 0; nt < 16; nt++) {
        int o0 = nt * 8 + qk * 2;
        if (nd0 < N) *(unsigned*)((char*)g_Bh + nd0 * 256 + o0 * 2) = pack2h(d[nt][0], d[nt][1]);
        if (nd8 < N) *(unsigned*)((char*)g_Bh + nd8 * 256 + o0 * 2) = pack2h(d[nt][2], d[nt][3]);
    }
}

// ---------------------------------------------------------------------------
// fused edge kernel: warp-PAIR M=32/N=64 fp16 mma pipeline, 256 edges/tile
// ---------------------------------------------------------------------------
__global__ __launch_bounds__(ETHREADS) void edge_kernel(
    const float* __restrict__ pos, const float* __restrict__ edge_attr,
    const void* __restrict__ ei_raw,
    const float* __restrict__ eW1, const float* __restrict__ eb1,
    const float* __restrict__ eW2, const float* __restrict__ eb2,
    const float* __restrict__ cW1, const float* __restrict__ cb1,
    const float* __restrict__ cW2, const float* __restrict__ cb2,
    float* __restrict__ pos_out, int N, int E)
{
    extern __shared__ float smf[];
    char* smc = (char*)smf;
    unsigned sbase = smem_u32(smf);
    int tid = threadIdx.x, wid = tid >> 5, lane = tid & 31;
    int g = lane >> 3, l = lane & 7;
    int qm = lane >> 2, qk = lane & 3;
    int pr = wid >> 1, hf = wid & 1;    // pair id, N-half
    int barid = 1 + pr;

    // sv: w_rn 0, w_ea 128, eb1 256, eb2 384, cb1 512, cw2 640, cb2 768
    float* sv = smf;
    for (int i = tid; i < 128; i += ETHREADS) {
        sv[i]       = eW1[256 * 128 + i];
        sv[128 + i] = eW1[257 * 128 + i];
        sv[256 + i] = eb1[i];
        sv[384 + i] = eb2[i];
        sv[512 + i] = cb1[i];
        sv[640 + i] = cW2[i];
    }
    if (tid == 0) sv[768] = cb2[0];

    for (int idx = tid; idx < 16384; idx += ETHREADS) {
        int k = idx >> 7, o = idx & 127;
        unsigned off = (unsigned)(o * 272 + k * 2);
        *(__half*)(smc + W2HI_B + off) = __float2half_rn(eW2[idx]);
        *(__half*)(smc + C1HI_B + off) = __float2half_rn(cW1[idx]);
    }
    __syncthreads();

    float cb2v = sv[768];
    int is64 = g_is64;
    const long long* ei64 = (const long long*)ei_raw;
    const int*       ei32 = (const int*)ei_raw;

    float4 wr = *(const float4*)&sv[lane * 4];
    float4 we = *(const float4*)&sv[128 + lane * 4];
    float4 bi = *(const float4*)&sv[256 + lane * 4];

    unsigned atb = (unsigned)(AT_B + pr * 8704);
    unsigned aT = sbase + atb;
    unsigned bW2h = sbase + W2HI_B;
    unsigned bC1h = sbase + C1HI_B;
    unsigned aoff = (unsigned)((l + ((g & 1) << 3)) * 272 + (g >> 1) * 16);
    unsigned boff = (unsigned)((l + ((g >> 1) << 3)) * 272 + (g & 1) * 16);
    int nbase = hf * 64;

    char* metab = smc + META_B + pr * 1024;
    int*   mrow = (int*)metab;           // [32]
    float* mirn = (float*)(metab + 128);
    float* mrx  = (float*)(metab + 256);
    float* mry  = (float*)(metab + 384);
    float* mrz  = (float*)(metab + 512);
    float* mpart = (float*)(metab + 640); // [2][32]

    int ntiles = (E + TILE_E - 1) / TILE_E;
    for (int t = blockIdx.x; t < ntiles; t += gridDim.x) {
        int e0p = t * TILE_E + pr * 32;       // pair's first edge (32 edges)

        bar_pair(barid);                       // protect meta/tile from prev iter readers

        // --- meta: this warp's 16 rows (hf*16 .. +15); lanes 0..15 ---
        int m_r = 0, m_c = 0;
        float m_rn = 1.0f, m_ea = 0.0f;
        if (lane < 16) {
            int row = hf * 16 + lane;
            int e = e0p + row;
            int r = 0, c = 0;
            float dx = 0.f, dy = 0.f, dz = 0.f, rn = 1.0f, irn = 1.0f, eav = 0.f;
            if (e < E) {
                if (is64) { r = (int)ei64[e]; c = (int)ei64[E + e]; }
                else      { r = ei32[e];      c = ei32[E + e]; }
                r = min(max(r, 0), N - 1);
                c = min(max(c, 0), N - 1);
                dx = pos[r * 3 + 0] - pos[c * 3 + 0];
                dy = pos[r * 3 + 1] - pos[c * 3 + 1];
                dz = pos[r * 3 + 2] - pos[c * 3 + 2];
                float nrm = sqrtf(dx * dx + dy * dy + dz * dz);
                rn = fmaxf(nrm, 1e-8f);
                irn = 1.0f / rn;
                eav = edge_attr[e];
            }
            m_r = r; m_c = c; m_rn = rn; m_ea = eav;
            mrow[row] = r; mirn[row] = irn;
            mrx[row] = dx; mry[row] = dy; mrz[row] = dz;
        }

        // --- phase1: m rows hf*16..+15 -> fp16 tile ---
        #pragma unroll
        for (int rr = 0; rr < 16; rr++) {
            int rsrc = __shfl_sync(0xffffffffu, m_r, rr);
            int csrc = __shfl_sync(0xffffffffu, m_c, rr);
            float rn  = __shfl_sync(0xffffffffu, m_rn, rr);
            float eav = __shfl_sync(0xffffffffu, m_ea, rr);
            uint2 av = *(const uint2*)((const char*)g_Ah + rsrc * 256 + lane * 8);
            uint2 bv = *(const uint2*)((const char*)g_Bh + csrc * 256 + lane * 8);
            float2 a01 = __half22float2(*(__half2*)&av.x);
            float2 a23 = __half22float2(*(__half2*)&av.y);
            float2 b01 = __half22float2(*(__half2*)&bv.x);
            float2 b23 = __half22float2(*(__half2*)&bv.y);
            float v0 = silu(fmaf(eav, we.x, fmaf(rn, wr.x, a01.x + b01.x)) + bi.x);
            float v1 = silu(fmaf(eav, we.y, fmaf(rn, wr.y, a01.y + b01.y)) + bi.y);
            float v2 = silu(fmaf(eav, we.z, fmaf(rn, wr.z, a23.x + b23.x)) + bi.z);
            float v3 = silu(fmaf(eav, we.w, fmaf(rn, wr.w, a23.y + b23.y)) + bi.w);
            *(uint2*)(smc + atb + (hf * 16 + rr) * 272 + lane * 8) =
                make_uint2(pack2h(v0, v1), pack2h(v2, v3));
        }
        bar_pair(barid);                       // m tile + meta visible to pair

        // --- GEMM2: D1 = m @ eW2 (this warp's 64 out-cols, all 32 rows) ---
        float d[16][4];
        #pragma unroll
        for (int i = 0; i < 16; i++) { d[i][0] = d[i][1] = d[i][2] = d[i][3] = 0.f; }
        warp_gemm32(aT, bW2h, aoff, boff, nbase, d);

        bar_pair(barid);                       // both warps done reading m

        // --- epilogue1: m2 = silu(D1+eb2) -> tile cols [nbase,nbase+64) + agg red2 ---
        int r0 = mrow[qm], r1 = mrow[qm + 8], r2 = mrow[qm + 16], r3 = mrow[qm + 24];
        bool k0 = (e0p + qm) < E, k1 = (e0p + qm + 8) < E;
        bool k2 = (e0p + qm + 16) < E, k3 = (e0p + qm + 24) < E;
        #pragma unroll
        for (int s = 0; s < 4; s++)
        #pragma unroll
        for (int hh = 0; hh < 2; hh++) {
            int i = s * 2 + hh;
            int c0 = nbase + s * 16 + hh * 8 + qk * 2;
            float e_0 = sv[384 + c0], e_1 = sv[384 + c0 + 1];
            float v0 = silu(d[i][0] + e_0), v1 = silu(d[i][1] + e_1);
            float v2 = silu(d[i][2] + e_0), v3 = silu(d[i][3] + e_1);
            float u0 = silu(d[8 + i][0] + e_0), u1 = silu(d[8 + i][1] + e_1);
            float u2 = silu(d[8 + i][2] + e_0), u3 = silu(d[8 + i][3] + e_1);
            *(unsigned*)(smc + atb + qm * 272 + c0 * 2) = pack2h(v0, v1);
            *(unsigned*)(smc + atb + (qm + 8) * 272 + c0 * 2) = pack2h(v2, v3);
            *(unsigned*)(smc + atb + (qm + 16) * 272 + c0 * 2) = pack2h(u0, u1);
            *(unsigned*)(smc + atb + (qm + 24) * 272 + c0 * 2) = pack2h(u2, u3);
            if (k0) red2(g_agg + r0 * 128 + c0, v0, v1);
            if (k1) red2(g_agg + r1 * 128 + c0, v2, v3);
            if (k2) red2(g_agg + r2 * 128 + c0, u0, u1);
            if (k3) red2(g_agg + r3 * 128 + c0, u2, u3);
        }
        bar_pair(barid);                       // full m2 tile visible

        // --- GEMM3: D2 = m2 @ cW1 (this warp's 64 cols) ---
        #pragma unroll
        for (int i = 0; i < 16; i++) { d[i][0] = d[i][1] = d[i][2] = d[i][3] = 0.f; }
        warp_gemm32(aT, bC1h, aoff, boff, nbase, d);

        // --- epilogue2: partial coord = silu(D2+cb1) . cW2 over this warp's cols ---
        float p[4] = {0.f, 0.f, 0.f, 0.f};
        #pragma unroll
        for (int s = 0; s < 4; s++)
        #pragma unroll
        for (int hh = 0; hh < 2; hh++) {
            int i = s * 2 + hh;
            int c0 = nbase + s * 16 + hh * 8 + qk * 2;
            float cc0 = sv[512 + c0], cc1 = sv[512 + c0 + 1];
            float w0 = sv[640 + c0], w1 = sv[640 + c0 + 1];
            p[0] = fmaf(silu(d[i][0] + cc0), w0, p[0]);
            p[0] = fmaf(silu(d[i][1] + cc1), w1, p[0]);
            p[1] = fmaf(silu(d[i][2] + cc0), w0, p[1]);
            p[1] = fmaf(silu(d[i][3] + cc1), w1, p[1]);
            p[2] = fmaf(silu(d[8 + i][0] + cc0), w0, p[2]);
            p[2] = fmaf(silu(d[8 + i][1] + cc1), w1, p[2]);
            p[3] = fmaf(silu(d[8 + i][2] + cc0), w0, p[3]);
            p[3] = fmaf(silu(d[8 + i][3] + cc1), w1, p[3]);
        }
        #pragma unroll
        for (int j = 0; j < 4; j++) {
            p[j] += __shfl_xor_sync(0xffffffffu, p[j], 1);
            p[j] += __shfl_xor_sync(0xffffffffu, p[j], 2);
        }
        if (qk == 0) {
            #pragma unroll
            for (int j = 0; j < 4; j++)
                mpart[hf * 32 + qm + j * 8] = p[j];
        }
        bar_pair(barid);                       // partials visible

        if (hf == 0 && qk == 0) {
            #pragma unroll
            for (int j = 0; j < 4; j++) {
                int row = qm + j * 8;
                if ((e0p + row) < E) {
                    float s = (mpart[row] + mpart[32 + row] + cb2v) * mirn[row];
                    int ri = mrow[row];
                    atomicAdd(&pos_out[ri * 3 + 0], s * mrx[row]);
                    atomicAdd(&pos_out[ri * 3 + 1], s * mry[row]);
                    atomicAdd(&pos_out[ri * 3 + 2], s * mrz[row]);
                }
            }
        }
    }
}

// ---------------------------------------------------------------------------
// node MLP (fp16 mma, warp-private): hn = silu([h,agg]@nW1+nb1); h_new = h + hn@nW2+nb2
// ---------------------------------------------------------------------------
#define NODE_W  12
#define NODE_T  384
#define W1A_B   0
#define W1B_B   34816
#define W2N_B   69632
#define XT_B    104448    // per warp: Xh at +wid*8704, Xagg at +wid*8704+4352
#define NB_F    52224     // float idx: nb1[0..127], nb2[128..255]
#define NODE_SMEM 209920
__global__ __launch_bounds__(NODE_T) void node_kernel(
    const float* __restrict__ h,
    const float* __restrict__ nW1, const float* __restrict__ nb1,
    const float* __restrict__ nW2, const float* __restrict__ nb2,
    float* __restrict__ h_out, int N)
{
    extern __shared__ float smf[];
    char* smc = (char*)smf;
    unsigned sbase = smem_u32(smf);
    int tid = threadIdx.x, wid = tid >> 5, lane = tid & 31;
    int g = lane >> 3, l = lane & 7;
    int qm = lane >> 2, qk = lane & 3;

    for (int idx = tid; idx < 32768; idx += NODE_T) {
        int k = idx >> 7, o = idx & 127;
        unsigned off = (unsigned)(o * 272 + (k & 127) * 2);
        *(__half*)(smc + (k < 128 ? W1A_B : W1B_B) + off) = __float2half_rn(nW1[idx]);
    }
    for (int idx = tid; idx < 16384; idx += NODE_T) {
        int k = idx >> 7, o = idx & 127;
        *(__half*)(smc + W2N_B + o * 272 + k * 2) = __float2half_rn(nW2[idx]);
    }
    for (int i = tid; i < 128; i += NODE_T) {
        smf[NB_F + i] = nb1[i];
        smf[NB_F + 128 + i] = nb2[i];
    }
    __syncthreads();

    unsigned xh = sbase + XT_B + wid * 8704, xa = xh + 4352;
    unsigned w1a = sbase + W1A_B, w1b = sbase + W1B_B, w2 = sbase + W2N_B;
    unsigned aoff = (unsigned)((l + ((g & 1) << 3)) * 272 + (g >> 1) * 16);
    unsigned boff = (unsigned)((l + ((g >> 1) << 3)) * 272 + (g & 1) * 16);

    int n0w = blockIdx.x * (NODE_W * 16) + wid * 16;
    if (n0w >= N) return;

    #pragma unroll
    for (int row = 0; row < 16; row++) {
        int node = min(n0w + row, N - 1);
        float4 a = *(const float4*)(h + node * 128 + lane * 4);
        float4 b = *(const float4*)(g_agg + node * 128 + lane * 4);
        *(uint2*)(smc + (XT_B + wid * 8704) + row * 272 + lane * 8) =
            make_uint2(pack2h(a.x, a.y), pack2h(a.z, a.w));
        *(uint2*)(smc + (XT_B + wid * 8704 + 4352) + row * 272 + lane * 8) =
            make_uint2(pack2h(b.x, b.y), pack2h(b.z, b.w));
    }
    __syncwarp();

    float d[16][4];
    #pragma unroll
    for (int i = 0; i < 16; i++) { d[i][0] = d[i][1] = d[i][2] = d[i][3] = 0.f; }
    warp_gemm(xh, w1a, aoff, boff, d);
    warp_gemm(xa, w1b, aoff, boff, d);

    #pragma unroll
    for (int nt = 0; nt < 16; nt++) {
        int o0 = nt * 8 + qk * 2;
        float b0 = smf[NB_F + o0], b1 = smf[NB_F + o0 + 1];
        float v0 = silu(d[nt][0] + b0);
        float v1 = silu(d[nt][1] + b1);
        float v2 = silu(d[nt][2] + b0);
        float v3 = silu(d[nt][3] + b1);
        *(unsigned*)(smc + (XT_B + wid * 8704) + qm * 272 + o0 * 2) = pack2h(v0, v1);
        *(unsigned*)(smc + (XT_B + wid * 8704) + (qm + 8) * 272 + o0 * 2) = pack2h(v2, v3);
    }
    __syncwarp();

    #pragma unroll
    for (int i = 0; i < 16; i++) { d[i][0] = d[i][1] = d[i][2] = d[i][3] = 0.f; }
    warp_gemm(xh, w2, aoff, boff, d);

    int nd0 = n0w + qm, nd8 = n0w + qm + 8;
    #pragma unroll
    for (int nt = 0; nt < 16; nt++) {
        int o0 = nt * 8 + qk * 2;
        float b0 = smf[NB_F + 128 + o0], b1 = smf[NB_F + 128 + o0 + 1];
        if (nd0 < N) {
            float2 r = *(const float2*)(h + nd0 * 128 + o0);
            *(float2*)(h_out + nd0 * 128 + o0) = make_float2(d[nt][0] + b0 + r.x, d[nt][1] + b1 + r.y);
        }
        if (nd8 < N) {
            float2 r = *(const float2*)(h + nd8 * 128 + o0);
            *(float2*)(h_out + nd8 * 128 + o0) = make_float2(d[nt][2] + b0 + r.x, d[nt][3] + b1 + r.y);
        }
    }
}

// ---------------------------------------------------------------------------
extern "C" void kernel_launch(void* const* d_in, const int* in_sizes, int n_in,
                              void* d_out, int out_size)
{
    const float* h   = (const float*)d_in[0];
    const float* pos = (const float*)d_in[1];
    const float* ea  = (const float*)d_in[2];
    const void*  ei  = d_in[3];
    const float* eW1 = (const float*)d_in[4];
    const float* eb1 = (const float*)d_in[5];
    const float* eW2 = (const float*)d_in[6];
    const float* eb2 = (const float*)d_in[7];
    const float* nW1 = (const float*)d_in[8];
    const float* nb1 = (const float*)d_in[9];
    const float* nW2 = (const float*)d_in[10];
    const float* nb2 = (const float*)d_in[11];
    const float* cW1 = (const float*)d_in[12];
    const float* cb1 = (const float*)d_in[13];
    const float* cW2 = (const float*)d_in[14];
    const float* cb2 = (const float*)d_in[15];

    int N = in_sizes[0] / 128;
    int E = in_sizes[2];
    float* h_out   = (float*)d_out;
    float* pos_out = h_out + (size_t)N * 128;

    cudaFuncSetAttribute(pre_kernel,  cudaFuncAttributeMaxDynamicSharedMemorySize, PRE_SMEM2);
    cudaFuncSetAttribute(edge_kernel, cudaFuncAttributeMaxDynamicSharedMemorySize, EDGE_SMEM);
    cudaFuncSetAttribute(node_kernel, cudaFuncAttributeMaxDynamicSharedMemorySize, NODE_SMEM);

    int nsm = 148;
    cudaDeviceGetAttribute(&nsm, cudaDevAttrMultiProcessorCount, 0);

    detect_kernel<<<1, 256>>>(ei, N, E);
    init_kernel<<<(N * 128 + 255) / 256, 256>>>(pos, pos_out, N);
    pre_kernel<<<(N + 191) / 192, 384, PRE_SMEM2>>>(h, eW1, N);
    edge_kernel<<<nsm, ETHREADS, EDGE_SMEM>>>(pos, ea, ei, eW1, eb1, eW2, eb2,
                                              cW1, cb1, cW2, cb2, pos_out, N, E);
    node_kernel<<<(N + NODE_W * 16 - 1) / (NODE_W * 16), NODE_T, NODE_SMEM>>>(
        h, nW1, nb1, nW2, nb2, h_out, N);
}

// round 13
// speedup vs baseline: 6.7073x; 1.0351x over previous
#include <cuda_runtime.h>
#include <cuda_fp16.h>

#define ETHREADS 512
#define EWARPS   16
#define EPAIRS   8
#define TILE_E   (EPAIRS * 32)
#define NMAX 50000

// Scratch (device globals: allocation-free rule)
__device__ __half g_Ah[NMAX * 128];  // h @ eW1[0:128]   (fp16, gathered by row)
__device__ __half g_Bh[NMAX * 128];  // h @ eW1[128:256] (fp16, gathered by col)
__device__ float  g_agg[NMAX * 128]; // segment_sum(m2, row)
__device__ int    g_is64;            // edge_index dtype flag

__device__ __forceinline__ float tanh_a(float x) {
    float y; asm("tanh.approx.f32 %0, %1;" : "=f"(y) : "f"(x)); return y;
}
__device__ __forceinline__ float silu(float x) {
    return x * fmaf(0.5f, tanh_a(0.5f * x), 0.5f);
}
// packed half2 silu: x * (0.5*tanh(0.5x)+0.5), tanh via one f16x2 MUFU
__device__ __forceinline__ __half2 silu2(__half2 x) {
    const __half2 h05 = __float2half2_rn(0.5f);
    __half2 u = __hmul2(x, h05);
    unsigned t;
    asm("tanh.approx.f16x2 %0, %1;" : "=r"(t) : "r"(*(unsigned*)&u));
    return __hmul2(x, __hfma2(*(__half2*)&t, h05, h05));
}
__device__ __forceinline__ unsigned smem_u32(const void* p) {
    unsigned a;
    asm("{ .reg .u64 t; cvta.to.shared.u64 t, %1; cvt.u32.u64 %0, t; }" : "=r"(a) : "l"(p));
    return a;
}
__device__ __forceinline__ unsigned pack2h(float v0, float v1) {
    __half2 h = __floats2half2_rn(v0, v1);
    return *(unsigned*)&h;
}
__device__ __forceinline__ void ldsm4(unsigned r[4], unsigned addr) {
    asm volatile("ldmatrix.sync.aligned.m8n8.x4.shared.b16 {%0,%1,%2,%3}, [%4];"
                 : "=r"(r[0]), "=r"(r[1]), "=r"(r[2]), "=r"(r[3]) : "r"(addr));
}
__device__ __forceinline__ void mma_f16(float d[4], const unsigned a[4], unsigned b0, unsigned b1) {
    asm volatile("mma.sync.aligned.m16n8k16.row.col.f32.f16.f16.f32 "
                 "{%0,%1,%2,%3}, {%4,%5,%6,%7}, {%8,%9}, {%0,%1,%2,%3};"
                 : "+f"(d[0]), "+f"(d[1]), "+f"(d[2]), "+f"(d[3])
                 : "r"(a[0]), "r"(a[1]), "r"(a[2]), "r"(a[3]), "r"(b0), "r"(b1));
}
__device__ __forceinline__ void red2(float* p, float v0, float v1) {
    asm volatile("red.global.add.v2.f32 [%0], {%1, %2};" :: "l"(p), "f"(v0), "f"(v1) : "memory");
}
__device__ __forceinline__ void bar_pair(int id) {
    asm volatile("bar.sync %0, 64;" :: "r"(id) : "memory");
}

// M=16 warp GEMM: 16 x 128 x 128 fp16 (fp32 accum). A row stride 272B. (pre/node)
__device__ __forceinline__ void warp_gemm(unsigned aT, unsigned bT,
                                          unsigned aoff, unsigned boff, float (*d)[4]) {
    #pragma unroll
    for (int ks = 0; ks < 8; ks++) {
        unsigned ah[4];
        ldsm4(ah, aT + aoff + ks * 32);
        #pragma unroll
        for (int np = 0; np < 8; np++) {
            unsigned bh[4];
            ldsm4(bh, bT + boff + np * 4352 + ks * 32);
            mma_f16(d[np * 2],     ah, bh[0], bh[1]);
            mma_f16(d[np * 2 + 1], ah, bh[2], bh[3]);
        }
    }
}

// M=32, N=64 warp GEMM (one N-half starting at nbase).
__device__ __forceinline__ void warp_gemm32(unsigned aT, unsigned bT,
                                            unsigned aoff, unsigned boff,
                                            int nbase, float (*d)[4]) {
    #pragma unroll
    for (int ks = 0; ks < 8; ks++) {
        unsigned a0[4], a1[4];
        ldsm4(a0, aT + aoff + ks * 32);
        ldsm4(a1, aT + aoff + 16 * 272 + ks * 32);
        #pragma unroll
        for (int s = 0; s < 4; s++) {
            unsigned bh[4];
            ldsm4(bh, bT + boff + (unsigned)(nbase + s * 16) * 272 + ks * 32);
            mma_f16(d[s * 2],         a0, bh[0], bh[1]);
            mma_f16(d[s * 2 + 1],     a0, bh[2], bh[3]);
            mma_f16(d[8 + s * 2],     a1, bh[0], bh[1]);
            mma_f16(d[8 + s * 2 + 1], a1, bh[2], bh[3]);
        }
    }
}

// SMEM byte layout for edge kernel
#define EB2H_B 3200                      // eb2 as fp16 [128] (bytes 3200..3456)
#define W2HI_B 4096
#define C1HI_B 38912
#define AT_B   73728                     // EPAIRS x 8704 (32 rows x 272B)
#define META_B (AT_B + EPAIRS * 8704)    // per pair 1024B: rowi/irn/rx/ry/rz/part
#define EDGE_SMEM (META_B + EPAIRS * 1024)   // 151552

// ---------------------------------------------------------------------------
// init (+ edge_index dtype detect in block 0)
// ---------------------------------------------------------------------------
__global__ void init_kernel(const float* __restrict__ pos, float* __restrict__ pos_out,
                            const void* __restrict__ ei, int N, int E) {
    int i = blockIdx.x * blockDim.x + threadIdx.x;
    if (i < N * 128) g_agg[i] = 0.0f;
    if (i < N * 3) pos_out[i] = pos[i];
    if (blockIdx.x == 0) {
        __shared__ int ok;
        if (threadIdx.x == 0) ok = 1;
        __syncthreads();
        int n = (E < 256) ? E : 256;
        if ((int)threadIdx.x < n) {
            long long v = ((const long long*)ei)[threadIdx.x];
            if (v < 0 || v >= (long long)N) atomicExch(&ok, 0);
        }
        __syncthreads();
        if (threadIdx.x == 0) g_is64 = ok;
    }
}

// ---------------------------------------------------------------------------
// precompute (fp16 mma, persistent): A = h @ eW1[0:128,:], B = h @ eW1[128:256,:]
// ---------------------------------------------------------------------------
#define PRE_SMEM2 121856   // W0 34816 | W1 34816 | X tiles 12*4352
__global__ __launch_bounds__(384) void pre_kernel(
    const float* __restrict__ h, const float* __restrict__ eW1, int N)
{
    extern __shared__ float smf[];
    char* smc = (char*)smf;
    unsigned sbase = smem_u32(smf);
    int tid = threadIdx.x, wid = tid >> 5, lane = tid & 31;
    int g = lane >> 3, l = lane & 7;
    int qm = lane >> 2, qk = lane & 3;

    for (int idx = tid; idx < 32768; idx += 384) {
        int k = idx >> 7, o = idx & 127;
        *(__half*)(smc + (k < 128 ? 0 : 34816) + o * 272 + (k & 127) * 2) =
            __float2half_rn(eW1[idx]);
    }
    __syncthreads();

    unsigned xT = sbase + 69632 + wid * 4352;
    unsigned aoff = (unsigned)((l + ((g & 1) << 3)) * 272 + (g >> 1) * 16);
    unsigned boff = (unsigned)((l + ((g >> 1) << 3)) * 272 + (g & 1) * 16);

    int ntiles = (N + 191) / 192;
    for (int tb = blockIdx.x; tb < ntiles; tb += gridDim.x) {
        int n0w = tb * 192 + wid * 16;
        if (n0w >= N) continue;

        #pragma unroll
        for (int row = 0; row < 16; row++) {
            int node = min(n0w + row, N - 1);
            float4 a = *(const float4*)(h + node * 128 + lane * 4);
            *(uint2*)(smc + (69632 + wid * 4352) + row * 272 + lane * 8) =
                make_uint2(pack2h(a.x, a.y), pack2h(a.z, a.w));
        }
        __syncwarp();

        int nd0 = n0w + qm, nd8 = n0w + qm + 8;
        float d[16][4];
        #pragma unroll
        for (int i = 0; i < 16; i++) { d[i][0] = d[i][1] = d[i][2] = d[i][3] = 0.f; }
        warp_gemm(xT, sbase + 0, aoff, boff, d);
        #pragma unroll
        for (int nt = 0; nt < 16; nt++) {
            int o0 = nt * 8 + qk * 2;
            if (nd0 < N) *(unsigned*)((char*)g_Ah + nd0 * 256 + o0 * 2) = pack2h(d[nt][0], d[nt][1]);
            if (nd8 < N) *(unsigned*)((char*)g_Ah + nd8 * 256 + o0 * 2) = pack2h(d[nt][2], d[nt][3]);
        }
        #pragma unroll
        for (int i = 0; i < 16; i++) { d[i][0] = d[i][1] = d[i][2] = d[i][3] = 0.f; }
        warp_gemm(xT, sbase + 34816, aoff, boff, d);
        #pragma unroll
        for (int nt = 0; nt < 16; nt++) {
            int o0 = nt * 8 + qk * 2;
            if (nd0 < N) *(unsigned*)((char*)g_Bh + nd0 * 256 + o0 * 2) = pack2h(d[nt][0], d[nt][1]);
            if (nd8 < N) *(unsigned*)((char*)g_Bh + nd8 * 256 + o0 * 2) = pack2h(d[nt][2], d[nt][3]);
        }
        __syncwarp();
    }
}

// ---------------------------------------------------------------------------
// fused edge kernel: warp-PAIR M=32/N=64 fp16 mma + half2 scalar pipeline
// ---------------------------------------------------------------------------
__global__ __launch_bounds__(ETHREADS) void edge_kernel(
    const float* __restrict__ pos, const float* __restrict__ edge_attr,
    const void* __restrict__ ei_raw,
    const float* __restrict__ eW1, const float* __restrict__ eb1,
    const float* __restrict__ eW2, const float* __restrict__ eb2,
    const float* __restrict__ cW1, const float* __restrict__ cb1,
    const float* __restrict__ cW2, const float* __restrict__ cb2,
    float* __restrict__ pos_out, int N, int E)
{
    extern __shared__ float smf[];
    char* smc = (char*)smf;
    unsigned sbase = smem_u32(smf);
    int tid = threadIdx.x, wid = tid >> 5, lane = tid & 31;
    int g = lane >> 3, l = lane & 7;
    int qm = lane >> 2, qk = lane & 3;
    int pr = wid >> 1, hf = wid & 1;
    int barid = 1 + pr;

    // sv: w_rn 0, w_ea 128, eb1 256, eb2 384, cb1 512, cw2 640, cb2 768
    float* sv = smf;
    for (int i = tid; i < 128; i += ETHREADS) {
        sv[i]       = eW1[256 * 128 + i];
        sv[128 + i] = eW1[257 * 128 + i];
        sv[256 + i] = eb1[i];
        float e2 = eb2[i];
        sv[384 + i] = e2;
        sv[512 + i] = cb1[i];
        sv[640 + i] = cW2[i];
        *(__half*)(smc + EB2H_B + i * 2) = __float2half_rn(e2);
    }
    if (tid == 0) sv[768] = cb2[0];

    for (int idx = tid; idx < 16384; idx += ETHREADS) {
        int k = idx >> 7, o = idx & 127;
        unsigned off = (unsigned)(o * 272 + k * 2);
        *(__half*)(smc + W2HI_B + off) = __float2half_rn(eW2[idx]);
        *(__half*)(smc + C1HI_B + off) = __float2half_rn(cW1[idx]);
    }
    __syncthreads();

    float cb2v = sv[768];
    int is64 = g_is64;
    const long long* ei64 = (const long long*)ei_raw;
    const int*       ei32 = (const int*)ei_raw;

    // per-lane phase1 constants as half2 (cols lane*4 .. +3)
    __half2 wr01 = __floats2half2_rn(sv[lane * 4 + 0], sv[lane * 4 + 1]);
    __half2 wr23 = __floats2half2_rn(sv[lane * 4 + 2], sv[lane * 4 + 3]);
    __half2 we01 = __floats2half2_rn(sv[128 + lane * 4 + 0], sv[128 + lane * 4 + 1]);
    __half2 we23 = __floats2half2_rn(sv[128 + lane * 4 + 2], sv[128 + lane * 4 + 3]);
    __half2 bi01 = __floats2half2_rn(sv[256 + lane * 4 + 0], sv[256 + lane * 4 + 1]);
    __half2 bi23 = __floats2half2_rn(sv[256 + lane * 4 + 2], sv[256 + lane * 4 + 3]);

    unsigned atb = (unsigned)(AT_B + pr * 8704);
    unsigned aT = sbase + atb;
    unsigned bW2h = sbase + W2HI_B;
    unsigned bC1h = sbase + C1HI_B;
    unsigned aoff = (unsigned)((l + ((g & 1) << 3)) * 272 + (g >> 1) * 16);
    unsigned boff = (unsigned)((l + ((g >> 1) << 3)) * 272 + (g & 1) * 16);
    int nbase = hf * 64;

    char* metab = smc + META_B + pr * 1024;
    int*   mrow = (int*)metab;
    float* mirn = (float*)(metab + 128);
    float* mrx  = (float*)(metab + 256);
    float* mry  = (float*)(metab + 384);
    float* mrz  = (float*)(metab + 512);
    float* mpart = (float*)(metab + 640);

    int ntiles = (E + TILE_E - 1) / TILE_E;
    for (int t = blockIdx.x; t < ntiles; t += gridDim.x) {
        int e0p = t * TILE_E + pr * 32;

        bar_pair(barid);

        // --- meta: this warp's 16 rows (hf*16 .. +15); lanes 0..15 ---
        int m_r = 0, m_c = 0;
        float m_rn = 1.0f, m_ea = 0.0f;
        if (lane < 16) {
            int row = hf * 16 + lane;
            int e = e0p + row;
            int r = 0, c = 0;
            float dx = 0.f, dy = 0.f, dz = 0.f, rn = 1.0f, irn = 1.0f, eav = 0.f;
            if (e < E) {
                if (is64) { r = (int)ei64[e]; c = (int)ei64[E + e]; }
                else      { r = ei32[e];      c = ei32[E + e]; }
                r = min(max(r, 0), N - 1);
                c = min(max(c, 0), N - 1);
                dx = pos[r * 3 + 0] - pos[c * 3 + 0];
                dy = pos[r * 3 + 1] - pos[c * 3 + 1];
                dz = pos[r * 3 + 2] - pos[c * 3 + 2];
                float nrm = sqrtf(dx * dx + dy * dy + dz * dz);
                rn = fmaxf(nrm, 1e-8f);
                irn = 1.0f / rn;
                eav = edge_attr[e];
            }
            m_r = r; m_c = c; m_rn = rn; m_ea = eav;
            mrow[row] = r; mirn[row] = irn;
            mrx[row] = dx; mry[row] = dy; mrz[row] = dz;
        }

        // --- phase1 (half2): m = silu(A[row]+B[col]+rn*w_rn+ea*w_ea+eb1) ---
        #pragma unroll
        for (int rr = 0; rr < 16; rr++) {
            int rsrc = __shfl_sync(0xffffffffu, m_r, rr);
            int csrc = __shfl_sync(0xffffffffu, m_c, rr);
            float rnf = __shfl_sync(0xffffffffu, m_rn, rr);
            float eaf = __shfl_sync(0xffffffffu, m_ea, rr);
            __half2 rn2 = __float2half2_rn(rnf);
            __half2 ea2 = __float2half2_rn(eaf);
            uint2 av = *(const uint2*)((const char*)g_Ah + rsrc * 256 + lane * 8);
            uint2 bv = *(const uint2*)((const char*)g_Bh + csrc * 256 + lane * 8);
            __half2 x01 = __hadd2(__hfma2(rn2, wr01, __hadd2(*(__half2*)&av.x, *(__half2*)&bv.x)),
                                  __hfma2(ea2, we01, bi01));
            __half2 x23 = __hadd2(__hfma2(rn2, wr23, __hadd2(*(__half2*)&av.y, *(__half2*)&bv.y)),
                                  __hfma2(ea2, we23, bi23));
            __half2 v01 = silu2(x01), v23 = silu2(x23);
            *(uint2*)(smc + atb + (hf * 16 + rr) * 272 + lane * 8) =
                make_uint2(*(unsigned*)&v01, *(unsigned*)&v23);
        }
        bar_pair(barid);

        // --- GEMM2: D1 = m @ eW2 (this warp's 64 cols, 32 rows) ---
        float d[16][4];
        #pragma unroll
        for (int i = 0; i < 16; i++) { d[i][0] = d[i][1] = d[i][2] = d[i][3] = 0.f; }
        warp_gemm32(aT, bW2h, aoff, boff, nbase, d);

        bar_pair(barid);

        // --- epilogue1 (half2 silu): m2 -> tile + agg red2(fp32) ---
        int r0 = mrow[qm], r1 = mrow[qm + 8], r2 = mrow[qm + 16], r3 = mrow[qm + 24];
        bool k0 = (e0p + qm) < E, k1 = (e0p + qm + 8) < E;
        bool k2 = (e0p + qm + 16) < E, k3 = (e0p + qm + 24) < E;
        #pragma unroll
        for (int s = 0; s < 4; s++)
        #pragma unroll
        for (int hh = 0; hh < 2; hh++) {
            int i = s * 2 + hh;
            int c0 = nbase + s * 16 + hh * 8 + qk * 2;
            __half2 eb = *(__half2*)(smc + EB2H_B + c0 * 2);
            __half2 v01 = silu2(__hadd2(__floats2half2_rn(d[i][0], d[i][1]), eb));
            __half2 v23 = silu2(__hadd2(__floats2half2_rn(d[i][2], d[i][3]), eb));
            __half2 u01 = silu2(__hadd2(__floats2half2_rn(d[8 + i][0], d[8 + i][1]), eb));
            __half2 u23 = silu2(__hadd2(__floats2half2_rn(d[8 + i][2], d[8 + i][3]), eb));
            *(unsigned*)(smc + atb + qm * 272 + c0 * 2) = *(unsigned*)&v01;
            *(unsigned*)(smc + atb + (qm + 8) * 272 + c0 * 2) = *(unsigned*)&v23;
            *(unsigned*)(smc + atb + (qm + 16) * 272 + c0 * 2) = *(unsigned*)&u01;
            *(unsigned*)(smc + atb + (qm + 24) * 272 + c0 * 2) = *(unsigned*)&u23;
            if (k0) { float2 f = __half22float2(v01); red2(g_agg + r0 * 128 + c0, f.x, f.y); }
            if (k1) { float2 f = __half22float2(v23); red2(g_agg + r1 * 128 + c0, f.x, f.y); }
            if (k2) { float2 f = __half22float2(u01); red2(g_agg + r2 * 128 + c0, f.x, f.y); }
            if (k3) { float2 f = __half22float2(u23); red2(g_agg + r3 * 128 + c0, f.x, f.y); }
        }
        bar_pair(barid);

        // --- GEMM3: D2 = m2 @ cW1 (this warp's 64 cols) ---
        #pragma unroll
        for (int i = 0; i < 16; i++) { d[i][0] = d[i][1] = d[i][2] = d[i][3] = 0.f; }
        warp_gemm32(aT, bC1h, aoff, boff, nbase, d);

        // --- epilogue2: partial coord = silu(D2+cb1) . cW2 (h2 silu, fp32 dot) ---
        float p[4] = {0.f, 0.f, 0.f, 0.f};
        #pragma unroll
        for (int s = 0; s < 4; s++)
        #pragma unroll
        for (int hh = 0; hh < 2; hh++) {
            int i = s * 2 + hh;
            int c0 = nbase + s * 16 + hh * 8 + qk * 2;
            __half2 cb = __floats2half2_rn(sv[512 + c0], sv[512 + c0 + 1]);
            float w0 = sv[640 + c0], w1 = sv[640 + c0 + 1];
            float2 f;
            f = __half22float2(silu2(__hadd2(__floats2half2_rn(d[i][0], d[i][1]), cb)));
            p[0] = fmaf(f.x, w0, p[0]); p[0] = fmaf(f.y, w1, p[0]);
            f = __half22float2(silu2(__hadd2(__floats2half2_rn(d[i][2], d[i][3]), cb)));
            p[1] = fmaf(f.x, w0, p[1]); p[1] = fmaf(f.y, w1, p[1]);
            f = __half22float2(silu2(__hadd2(__floats2half2_rn(d[8 + i][0], d[8 + i][1]), cb)));
            p[2] = fmaf(f.x, w0, p[2]); p[2] = fmaf(f.y, w1, p[2]);
            f = __half22float2(silu2(__hadd2(__floats2half2_rn(d[8 + i][2], d[8 + i][3]), cb)));
            p[3] = fmaf(f.x, w0, p[3]); p[3] = fmaf(f.y, w1, p[3]);
        }
        #pragma unroll
        for (int j = 0; j < 4; j++) {
            p[j] += __shfl_xor_sync(0xffffffffu, p[j], 1);
            p[j] += __shfl_xor_sync(0xffffffffu, p[j], 2);
        }
        if (qk == 0) {
            #pragma unroll
            for (int j = 0; j < 4; j++)
                mpart[hf * 32 + qm + j * 8] = p[j];
        }
        bar_pair(barid);

        if (hf == 0 && qk == 0) {
            #pragma unroll
            for (int j = 0; j < 4; j++) {
                int row = qm + j * 8;
                if ((e0p + row) < E) {
                    float s = (mpart[row] + mpart[32 + row] + cb2v) * mirn[row];
                    int ri = mrow[row];
                    atomicAdd(&pos_out[ri * 3 + 0], s * mrx[row]);
                    atomicAdd(&pos_out[ri * 3 + 1], s * mry[row]);
                    atomicAdd(&pos_out[ri * 3 + 2], s * mrz[row]);
                }
            }
        }
    }
}

// ---------------------------------------------------------------------------
// node MLP (fp16 mma, persistent): hn = silu([h,agg]@nW1+nb1); h_new = h + hn@nW2+nb2
// ---------------------------------------------------------------------------
#define NODE_W  12
#define NODE_T  384
#define W1A_B   0
#define W1B_B   34816
#define W2N_B   69632
#define XT_B    104448
#define NB_F    52224
#define NODE_SMEM 209920
__global__ __launch_bounds__(NODE_T) void node_kernel(
    const float* __restrict__ h,
    const float* __restrict__ nW1, const float* __restrict__ nb1,
    const float* __restrict__ nW2, const float* __restrict__ nb2,
    float* __restrict__ h_out, int N)
{
    extern __shared__ float smf[];
    char* smc = (char*)smf;
    unsigned sbase = smem_u32(smf);
    int tid = threadIdx.x, wid = tid >> 5, lane = tid & 31;
    int g = lane >> 3, l = lane & 7;
    int qm = lane >> 2, qk = lane & 3;

    for (int idx = tid; idx < 32768; idx += NODE_T) {
        int k = idx >> 7, o = idx & 127;
        unsigned off = (unsigned)(o * 272 + (k & 127) * 2);
        *(__half*)(smc + (k < 128 ? W1A_B : W1B_B) + off) = __float2half_rn(nW1[idx]);
    }
    for (int idx = tid; idx < 16384; idx += NODE_T) {
        int k = idx >> 7, o = idx & 127;
        *(__half*)(smc + W2N_B + o * 272 + k * 2) = __float2half_rn(nW2[idx]);
    }
    for (int i = tid; i < 128; i += NODE_T) {
        smf[NB_F + i] = nb1[i];
        smf[NB_F + 128 + i] = nb2[i];
    }
    __syncthreads();

    unsigned xh = sbase + XT_B + wid * 8704, xa = xh + 4352;
    unsigned w1a = sbase + W1A_B, w1b = sbase + W1B_B, w2 = sbase + W2N_B;
    unsigned aoff = (unsigned)((l + ((g & 1) << 3)) * 272 + (g >> 1) * 16);
    unsigned boff = (unsigned)((l + ((g >> 1) << 3)) * 272 + (g & 1) * 16);

    int ntiles = (N + NODE_W * 16 - 1) / (NODE_W * 16);
    for (int tb = blockIdx.x; tb < ntiles; tb += gridDim.x) {
        int n0w = tb * (NODE_W * 16) + wid * 16;
        if (n0w >= N) continue;

        #pragma unroll
        for (int row = 0; row < 16; row++) {
            int node = min(n0w + row, N - 1);
            float4 a = *(const float4*)(h + node * 128 + lane * 4);
            float4 b = *(const float4*)(g_agg + node * 128 + lane * 4);
            *(uint2*)(smc + (XT_B + wid * 8704) + row * 272 + lane * 8) =
                make_uint2(pack2h(a.x, a.y), pack2h(a.z, a.w));
            *(uint2*)(smc + (XT_B + wid * 8704 + 4352) + row * 272 + lane * 8) =
                make_uint2(pack2h(b.x, b.y), pack2h(b.z, b.w));
        }
        __syncwarp();

        float d[16][4];
        #pragma unroll
        for (int i = 0; i < 16; i++) { d[i][0] = d[i][1] = d[i][2] = d[i][3] = 0.f; }
        warp_gemm(xh, w1a, aoff, boff, d);
        warp_gemm(xa, w1b, aoff, boff, d);

        #pragma unroll
        for (int nt = 0; nt < 16; nt++) {
            int o0 = nt * 8 + qk * 2;
            float b0 = smf[NB_F + o0], b1 = smf[NB_F + o0 + 1];
            float v0 = silu(d[nt][0] + b0);
            float v1 = silu(d[nt][1] + b1);
            float v2 = silu(d[nt][2] + b0);
            float v3 = silu(d[nt][3] + b1);
            *(unsigned*)(smc + (XT_B + wid * 8704) + qm * 272 + o0 * 2) = pack2h(v0, v1);
            *(unsigned*)(smc + (XT_B + wid * 8704) + (qm + 8) * 272 + o0 * 2) = pack2h(v2, v3);
        }
        __syncwarp();

        #pragma unroll
        for (int i = 0; i < 16; i++) { d[i][0] = d[i][1] = d[i][2] = d[i][3] = 0.f; }
        warp_gemm(xh, w2, aoff, boff, d);

        int nd0 = n0w + qm, nd8 = n0w + qm + 8;
        #pragma unroll
        for (int nt = 0; nt < 16; nt++) {
            int o0 = nt * 8 + qk * 2;
            float b0 = smf[NB_F + 128 + o0], b1 = smf[NB_F + 128 + o0 + 1];
            if (nd0 < N) {
                float2 r = *(const float2*)(h + nd0 * 128 + o0);
                *(float2*)(h_out + nd0 * 128 + o0) = make_float2(d[nt][0] + b0 + r.x, d[nt][1] + b1 + r.y);
            }
            if (nd8 < N) {
                float2 r = *(const float2*)(h + nd8 * 128 + o0);
                *(float2*)(h_out + nd8 * 128 + o0) = make_float2(d[nt][2] + b0 + r.x, d[nt][3] + b1 + r.y);
            }
        }
        __syncwarp();
    }
}

// ---------------------------------------------------------------------------
extern "C" void kernel_launch(void* const* d_in, const int* in_sizes, int n_in,
                              void* d_out, int out_size)
{
    const float* h   = (const float*)d_in[0];
    const float* pos = (const float*)d_in[1];
    const float* ea  = (const float*)d_in[2];
    const void*  ei  = d_in[3];
    const float* eW1 = (const float*)d_in[4];
    const float* eb1 = (const float*)d_in[5];
    const float* eW2 = (const float*)d_in[6];
    const float* eb2 = (const float*)d_in[7];
    const float* nW1 = (const float*)d_in[8];
    const float* nb1 = (const float*)d_in[9];
    const float* nW2 = (const float*)d_in[10];
    const float* nb2 = (const float*)d_in[11];
    const float* cW1 = (const float*)d_in[12];
    const float* cb1 = (const float*)d_in[13];
    const float* cW2 = (const float*)d_in[14];
    const float* cb2 = (const float*)d_in[15];

    int N = in_sizes[0] / 128;
    int E = in_sizes[2];
    float* h_out   = (float*)d_out;
    float* pos_out = h_out + (size_t)N * 128;

    cudaFuncSetAttribute(pre_kernel,  cudaFuncAttributeMaxDynamicSharedMemorySize, PRE_SMEM2);
    cudaFuncSetAttribute(edge_kernel, cudaFuncAttributeMaxDynamicSharedMemorySize, EDGE_SMEM);
    cudaFuncSetAttribute(node_kernel, cudaFuncAttributeMaxDynamicSharedMemorySize, NODE_SMEM);

    int nsm = 148;
    cudaDeviceGetAttribute(&nsm, cudaDevAttrMultiProcessorCount, 0);

    int pre_tiles  = (N + 191) / 192;
    int node_tiles = (N + NODE_W * 16 - 1) / (NODE_W * 16);

    init_kernel<<<(N * 128 + 255) / 256, 256>>>(pos, pos_out, ei, N, E);
    pre_kernel<<<min(nsm, pre_tiles), 384, PRE_SMEM2>>>(h, eW1, N);
    edge_kernel<<<nsm, ETHREADS, EDGE_SMEM>>>(pos, ea, ei, eW1, eb1, eW2, eb2,
                                              cW1, cb1, cW2, cb2, pos_out, N, E);
    node_kernel<<<min(nsm, node_tiles), NODE_T, NODE_SMEM>>>(
        h, nW1, nb1, nW2, nb2, h_out, N);
}

// round 14
// speedup vs baseline: 7.1214x; 1.0617x over previous
#include <cuda_runtime.h>
#include <cuda_fp16.h>

#define ETHREADS 640
#define EWARPS   20
#define EPAIRS   10
#define TILE_E   (EPAIRS * 32)
#define NMAX 50000

// Scratch (device globals: allocation-free rule)
__device__ __half g_Ah[NMAX * 128];  // h @ eW1[0:128]   (fp16, gathered by row)
__device__ __half g_Bh[NMAX * 128];  // h @ eW1[128:256] (fp16, gathered by col)
__device__ float  g_agg[NMAX * 128]; // segment_sum(m2, row)
__device__ int    g_is64;            // edge_index dtype flag

__device__ __forceinline__ float tanh_a(float x) {
    float y; asm("tanh.approx.f32 %0, %1;" : "=f"(y) : "f"(x)); return y;
}
__device__ __forceinline__ float silu(float x) {
    return x * fmaf(0.5f, tanh_a(0.5f * x), 0.5f);
}
// packed half2 silu: x * (0.5*tanh(0.5x)+0.5), tanh via one f16x2 MUFU
__device__ __forceinline__ __half2 silu2(__half2 x) {
    const __half2 h05 = __float2half2_rn(0.5f);
    __half2 u = __hmul2(x, h05);
    unsigned t;
    asm("tanh.approx.f16x2 %0, %1;" : "=r"(t) : "r"(*(unsigned*)&u));
    return __hmul2(x, __hfma2(*(__half2*)&t, h05, h05));
}
__device__ __forceinline__ unsigned smem_u32(const void* p) {
    unsigned a;
    asm("{ .reg .u64 t; cvta.to.shared.u64 t, %1; cvt.u32.u64 %0, t; }" : "=r"(a) : "l"(p));
    return a;
}
__device__ __forceinline__ unsigned pack2h(float v0, float v1) {
    __half2 h = __floats2half2_rn(v0, v1);
    return *(unsigned*)&h;
}
__device__ __forceinline__ void ldsm4(unsigned r[4], unsigned addr) {
    asm volatile("ldmatrix.sync.aligned.m8n8.x4.shared.b16 {%0,%1,%2,%3}, [%4];"
                 : "=r"(r[0]), "=r"(r[1]), "=r"(r[2]), "=r"(r[3]) : "r"(addr));
}
__device__ __forceinline__ void mma_f16(float d[4], const unsigned a[4], unsigned b0, unsigned b1) {
    asm volatile("mma.sync.aligned.m16n8k16.row.col.f32.f16.f16.f32 "
                 "{%0,%1,%2,%3}, {%4,%5,%6,%7}, {%8,%9}, {%0,%1,%2,%3};"
                 : "+f"(d[0]), "+f"(d[1]), "+f"(d[2]), "+f"(d[3])
                 : "r"(a[0]), "r"(a[1]), "r"(a[2]), "r"(a[3]), "r"(b0), "r"(b1));
}
__device__ __forceinline__ void red2(float* p, float v0, float v1) {
    asm volatile("red.global.add.v2.f32 [%0], {%1, %2};" :: "l"(p), "f"(v0), "f"(v1) : "memory");
}
__device__ __forceinline__ void bar_pair(int id) {
    asm volatile("bar.sync %0, 64;" :: "r"(id) : "memory");
}

// M=16 warp GEMM: 16 x 128 x 128 fp16 (fp32 accum). A row stride 272B. (pre/node)
__device__ __forceinline__ void warp_gemm(unsigned aT, unsigned bT,
                                          unsigned aoff, unsigned boff, float (*d)[4]) {
    #pragma unroll
    for (int ks = 0; ks < 8; ks++) {
        unsigned ah[4];
        ldsm4(ah, aT + aoff + ks * 32);
        #pragma unroll
        for (int np = 0; np < 8; np++) {
            unsigned bh[4];
            ldsm4(bh, bT + boff + np * 4352 + ks * 32);
            mma_f16(d[np * 2],     ah, bh[0], bh[1]);
            mma_f16(d[np * 2 + 1], ah, bh[2], bh[3]);
        }
    }
}

// M=32, N=64 warp GEMM (one N-half starting at nbase).
__device__ __forceinline__ void warp_gemm32(unsigned aT, unsigned bT,
                                            unsigned aoff, unsigned boff,
                                            int nbase, float (*d)[4]) {
    #pragma unroll
    for (int ks = 0; ks < 8; ks++) {
        unsigned a0[4], a1[4];
        ldsm4(a0, aT + aoff + ks * 32);
        ldsm4(a1, aT + aoff + 16 * 272 + ks * 32);
        #pragma unroll
        for (int s = 0; s < 4; s++) {
            unsigned bh[4];
            ldsm4(bh, bT + boff + (unsigned)(nbase + s * 16) * 272 + ks * 32);
            mma_f16(d[s * 2],         a0, bh[0], bh[1]);
            mma_f16(d[s * 2 + 1],     a0, bh[2], bh[3]);
            mma_f16(d[8 + s * 2],     a1, bh[0], bh[1]);
            mma_f16(d[8 + s * 2 + 1], a1, bh[2], bh[3]);
        }
    }
}

// SMEM byte layout for edge kernel
#define EB2H_B 3200                      // eb2 as fp16 [128]
#define W2HI_B 4096
#define C1HI_B 38912
#define AT_B   73728                     // EPAIRS x 8704 (32 rows x 272B)
#define META_B (AT_B + EPAIRS * 8704)    // per pair 1024B: rowi/irn/rx/ry/rz/part
#define EDGE_SMEM (META_B + EPAIRS * 1024)   // 171008

// ---------------------------------------------------------------------------
// init (+ edge_index dtype detect in block 0)
// ---------------------------------------------------------------------------
__global__ void init_kernel(const float* __restrict__ pos, float* __restrict__ pos_out,
                            const void* __restrict__ ei, int N, int E) {
    int i = blockIdx.x * blockDim.x + threadIdx.x;
    if (i < N * 128) g_agg[i] = 0.0f;
    if (i < N * 3) pos_out[i] = pos[i];
    if (blockIdx.x == 0) {
        __shared__ int ok;
        if (threadIdx.x == 0) ok = 1;
        __syncthreads();
        int n = (E < 256) ? E : 256;
        if ((int)threadIdx.x < n) {
            long long v = ((const long long*)ei)[threadIdx.x];
            if (v < 0 || v >= (long long)N) atomicExch(&ok, 0);
        }
        __syncthreads();
        if (threadIdx.x == 0) g_is64 = ok;
    }
}

// ---------------------------------------------------------------------------
// precompute (fp16 mma, persistent): A = h @ eW1[0:128,:], B = h @ eW1[128:256,:]
// ---------------------------------------------------------------------------
#define PRE_SMEM2 121856   // W0 34816 | W1 34816 | X tiles 12*4352
__global__ __launch_bounds__(384) void pre_kernel(
    const float* __restrict__ h, const float* __restrict__ eW1, int N)
{
    extern __shared__ float smf[];
    char* smc = (char*)smf;
    unsigned sbase = smem_u32(smf);
    int tid = threadIdx.x, wid = tid >> 5, lane = tid & 31;
    int g = lane >> 3, l = lane & 7;
    int qm = lane >> 2, qk = lane & 3;

    for (int idx = tid; idx < 32768; idx += 384) {
        int k = idx >> 7, o = idx & 127;
        *(__half*)(smc + (k < 128 ? 0 : 34816) + o * 272 + (k & 127) * 2) =
            __float2half_rn(eW1[idx]);
    }
    __syncthreads();

    unsigned xT = sbase + 69632 + wid * 4352;
    unsigned aoff = (unsigned)((l + ((g & 1) << 3)) * 272 + (g >> 1) * 16);
    unsigned boff = (unsigned)((l + ((g >> 1) << 3)) * 272 + (g & 1) * 16);

    int ntiles = (N + 191) / 192;
    for (int tb = blockIdx.x; tb < ntiles; tb += gridDim.x) {
        int n0w = tb * 192 + wid * 16;
        if (n0w >= N) continue;

        #pragma unroll
        for (int row = 0; row < 16; row++) {
            int node = min(n0w + row, N - 1);
            float4 a = *(const float4*)(h + node * 128 + lane * 4);
            *(uint2*)(smc + (69632 + wid * 4352) + row * 272 + lane * 8) =
                make_uint2(pack2h(a.x, a.y), pack2h(a.z, a.w));
        }
        __syncwarp();

        int nd0 = n0w + qm, nd8 = n0w + qm + 8;
        float d[16][4];
        #pragma unroll
        for (int i = 0; i < 16; i++) { d[i][0] = d[i][1] = d[i][2] = d[i][3] = 0.f; }
        warp_gemm(xT, sbase + 0, aoff, boff, d);
        #pragma unroll
        for (int nt = 0; nt < 16; nt++) {
            int o0 = nt * 8 + qk * 2;
            if (nd0 < N) *(unsigned*)((char*)g_Ah + nd0 * 256 + o0 * 2) = pack2h(d[nt][0], d[nt][1]);
            if (nd8 < N) *(unsigned*)((char*)g_Ah + nd8 * 256 + o0 * 2) = pack2h(d[nt][2], d[nt][3]);
        }
        #pragma unroll
        for (int i = 0; i < 16; i++) { d[i][0] = d[i][1] = d[i][2] = d[i][3] = 0.f; }
        warp_gemm(xT, sbase + 34816, aoff, boff, d);
        #pragma unroll
        for (int nt = 0; nt < 16; nt++) {
            int o0 = nt * 8 + qk * 2;
            if (nd0 < N) *(unsigned*)((char*)g_Bh + nd0 * 256 + o0 * 2) = pack2h(d[nt][0], d[nt][1]);
            if (nd8 < N) *(unsigned*)((char*)g_Bh + nd8 * 256 + o0 * 2) = pack2h(d[nt][2], d[nt][3]);
        }
        __syncwarp();
    }
}

// ---------------------------------------------------------------------------
// fused edge kernel: warp-PAIR M=32/N=64 fp16 mma + half2 scalar pipeline
// ---------------------------------------------------------------------------
__global__ __launch_bounds__(ETHREADS) void edge_kernel(
    const float* __restrict__ pos, const float* __restrict__ edge_attr,
    const void* __restrict__ ei_raw,
    const float* __restrict__ eW1, const float* __restrict__ eb1,
    const float* __restrict__ eW2, const float* __restrict__ eb2,
    const float* __restrict__ cW1, const float* __restrict__ cb1,
    const float* __restrict__ cW2, const float* __restrict__ cb2,
    float* __restrict__ pos_out, int N, int E)
{
    extern __shared__ float smf[];
    char* smc = (char*)smf;
    unsigned sbase = smem_u32(smf);
    int tid = threadIdx.x, wid = tid >> 5, lane = tid & 31;
    int g = lane >> 3, l = lane & 7;
    int qm = lane >> 2, qk = lane & 3;
    int pr = wid >> 1, hf = wid & 1;
    int barid = 1 + pr;

    // sv: w_rn 0, w_ea 128, eb1 256, eb2 384, cb1 512, cw2 640, cb2 768
    float* sv = smf;
    for (int i = tid; i < 128; i += ETHREADS) {
        sv[i]       = eW1[256 * 128 + i];
        sv[128 + i] = eW1[257 * 128 + i];
        sv[256 + i] = eb1[i];
        float e2 = eb2[i];
        sv[384 + i] = e2;
        sv[512 + i] = cb1[i];
        sv[640 + i] = cW2[i];
        *(__half*)(smc + EB2H_B + i * 2) = __float2half_rn(e2);
    }
    if (tid == 0) sv[768] = cb2[0];

    for (int idx = tid; idx < 16384; idx += ETHREADS) {
        int k = idx >> 7, o = idx & 127;
        unsigned off = (unsigned)(o * 272 + k * 2);
        *(__half*)(smc + W2HI_B + off) = __float2half_rn(eW2[idx]);
        *(__half*)(smc + C1HI_B + off) = __float2half_rn(cW1[idx]);
    }
    __syncthreads();

    float cb2v = sv[768];
    int is64 = g_is64;
    const long long* ei64 = (const long long*)ei_raw;
    const int*       ei32 = (const int*)ei_raw;

    // per-lane phase1 constants as half2 (cols lane*4 .. +3)
    __half2 wr01 = __floats2half2_rn(sv[lane * 4 + 0], sv[lane * 4 + 1]);
    __half2 wr23 = __floats2half2_rn(sv[lane * 4 + 2], sv[lane * 4 + 3]);
    __half2 we01 = __floats2half2_rn(sv[128 + lane * 4 + 0], sv[128 + lane * 4 + 1]);
    __half2 we23 = __floats2half2_rn(sv[128 + lane * 4 + 2], sv[128 + lane * 4 + 3]);
    __half2 bi01 = __floats2half2_rn(sv[256 + lane * 4 + 0], sv[256 + lane * 4 + 1]);
    __half2 bi23 = __floats2half2_rn(sv[256 + lane * 4 + 2], sv[256 + lane * 4 + 3]);

    unsigned atb = (unsigned)(AT_B + pr * 8704);
    unsigned aT = sbase + atb;
    unsigned bW2h = sbase + W2HI_B;
    unsigned bC1h = sbase + C1HI_B;
    unsigned aoff = (unsigned)((l + ((g & 1) << 3)) * 272 + (g >> 1) * 16);
    unsigned boff = (unsigned)((l + ((g >> 1) << 3)) * 272 + (g & 1) * 16);
    int nbase = hf * 64;

    char* metab = smc + META_B + pr * 1024;
    int*   mrow = (int*)metab;
    float* mirn = (float*)(metab + 128);
    float* mrx  = (float*)(metab + 256);
    float* mry  = (float*)(metab + 384);
    float* mrz  = (float*)(metab + 512);
    float* mpart = (float*)(metab + 640);

    int ntiles = (E + TILE_E - 1) / TILE_E;
    for (int t = blockIdx.x; t < ntiles; t += gridDim.x) {
        int e0p = t * TILE_E + pr * 32;

        bar_pair(barid);

        // --- meta: this warp's 16 rows (hf*16 .. +15); lanes 0..15 ---
        int m_r = 0, m_c = 0;
        float m_rn = 1.0f, m_ea = 0.0f;
        if (lane < 16) {
            int row = hf * 16 + lane;
            int e = e0p + row;
            int r = 0, c = 0;
            float dx = 0.f, dy = 0.f, dz = 0.f, rn = 1.0f, irn = 1.0f, eav = 0.f;
            if (e < E) {
                if (is64) { r = (int)ei64[e]; c = (int)ei64[E + e]; }
                else      { r = ei32[e];      c = ei32[E + e]; }
                r = min(max(r, 0), N - 1);
                c = min(max(c, 0), N - 1);
                dx = pos[r * 3 + 0] - pos[c * 3 + 0];
                dy = pos[r * 3 + 1] - pos[c * 3 + 1];
                dz = pos[r * 3 + 2] - pos[c * 3 + 2];
                float nrm = sqrtf(dx * dx + dy * dy + dz * dz);
                rn = fmaxf(nrm, 1e-8f);
                irn = 1.0f / rn;
                eav = edge_attr[e];
            }
            m_r = r; m_c = c; m_rn = rn; m_ea = eav;
            mrow[row] = r; mirn[row] = irn;
            mrx[row] = dx; mry[row] = dy; mrz[row] = dz;
        }

        // --- phase1 (half2): m = silu(A[row]+B[col]+rn*w_rn+ea*w_ea+eb1) ---
        #pragma unroll
        for (int rr = 0; rr < 16; rr++) {
            int rsrc = __shfl_sync(0xffffffffu, m_r, rr);
            int csrc = __shfl_sync(0xffffffffu, m_c, rr);
            float rnf = __shfl_sync(0xffffffffu, m_rn, rr);
            float eaf = __shfl_sync(0xffffffffu, m_ea, rr);
            __half2 rn2 = __float2half2_rn(rnf);
            __half2 ea2 = __float2half2_rn(eaf);
            uint2 av = *(const uint2*)((const char*)g_Ah + rsrc * 256 + lane * 8);
            uint2 bv = *(const uint2*)((const char*)g_Bh + csrc * 256 + lane * 8);
            __half2 x01 = __hadd2(__hfma2(rn2, wr01, __hadd2(*(__half2*)&av.x, *(__half2*)&bv.x)),
                                  __hfma2(ea2, we01, bi01));
            __half2 x23 = __hadd2(__hfma2(rn2, wr23, __hadd2(*(__half2*)&av.y, *(__half2*)&bv.y)),
                                  __hfma2(ea2, we23, bi23));
            __half2 v01 = silu2(x01), v23 = silu2(x23);
            *(uint2*)(smc + atb + (hf * 16 + rr) * 272 + lane * 8) =
                make_uint2(*(unsigned*)&v01, *(unsigned*)&v23);
        }
        bar_pair(barid);

        // --- GEMM2: D1 = m @ eW2 (this warp's 64 cols, 32 rows) ---
        float d[16][4];
        #pragma unroll
        for (int i = 0; i < 16; i++) { d[i][0] = d[i][1] = d[i][2] = d[i][3] = 0.f; }
        warp_gemm32(aT, bW2h, aoff, boff, nbase, d);

        bar_pair(barid);

        // --- epilogue1 (half2 silu): m2 -> tile + agg red2(fp32) ---
        int r0 = mrow[qm], r1 = mrow[qm + 8], r2 = mrow[qm + 16], r3 = mrow[qm + 24];
        bool k0 = (e0p + qm) < E, k1 = (e0p + qm + 8) < E;
        bool k2 = (e0p + qm + 16) < E, k3 = (e0p + qm + 24) < E;
        #pragma unroll
        for (int s = 0; s < 4; s++)
        #pragma unroll
        for (int hh = 0; hh < 2; hh++) {
            int i = s * 2 + hh;
            int c0 = nbase + s * 16 + hh * 8 + qk * 2;
            __half2 eb = *(__half2*)(smc + EB2H_B + c0 * 2);
            __half2 v01 = silu2(__hadd2(__floats2half2_rn(d[i][0], d[i][1]), eb));
            __half2 v23 = silu2(__hadd2(__floats2half2_rn(d[i][2], d[i][3]), eb));
            __half2 u01 = silu2(__hadd2(__floats2half2_rn(d[8 + i][0], d[8 + i][1]), eb));
            __half2 u23 = silu2(__hadd2(__floats2half2_rn(d[8 + i][2], d[8 + i][3]), eb));
            *(unsigned*)(smc + atb + qm * 272 + c0 * 2) = *(unsigned*)&v01;
            *(unsigned*)(smc + atb + (qm + 8) * 272 + c0 * 2) = *(unsigned*)&v23;
            *(unsigned*)(smc + atb + (qm + 16) * 272 + c0 * 2) = *(unsigned*)&u01;
            *(unsigned*)(smc + atb + (qm + 24) * 272 + c0 * 2) = *(unsigned*)&u23;
            if (k0) { float2 f = __half22float2(v01); red2(g_agg + r0 * 128 + c0, f.x, f.y); }
            if (k1) { float2 f = __half22float2(v23); red2(g_agg + r1 * 128 + c0, f.x, f.y); }
            if (k2) { float2 f = __half22float2(u01); red2(g_agg + r2 * 128 + c0, f.x, f.y); }
            if (k3) { float2 f = __half22float2(u23); red2(g_agg + r3 * 128 + c0, f.x, f.y); }
        }
        bar_pair(barid);

        // --- GEMM3: D2 = m2 @ cW1 (this warp's 64 cols) ---
        #pragma unroll
        for (int i = 0; i < 16; i++) { d[i][0] = d[i][1] = d[i][2] = d[i][3] = 0.f; }
        warp_gemm32(aT, bC1h, aoff, boff, nbase, d);

        // --- epilogue2: partial coord = silu(D2+cb1) . cW2 (h2 silu, fp32 dot) ---
        float p[4] = {0.f, 0.f, 0.f, 0.f};
        #pragma unroll
        for (int s = 0; s < 4; s++)
        #pragma unroll
        for (int hh = 0; hh < 2; hh++) {
            int i = s * 2 + hh;
            int c0 = nbase + s * 16 + hh * 8 + qk * 2;
            __half2 cb = __floats2half2_rn(sv[512 + c0], sv[512 + c0 + 1]);
            float w0 = sv[640 + c0], w1 = sv[640 + c0 + 1];
            float2 f;
            f = __half22float2(silu2(__hadd2(__floats2half2_rn(d[i][0], d[i][1]), cb)));
            p[0] = fmaf(f.x, w0, p[0]); p[0] = fmaf(f.y, w1, p[0]);
            f = __half22float2(silu2(__hadd2(__floats2half2_rn(d[i][2], d[i][3]), cb)));
            p[1] = fmaf(f.x, w0, p[1]); p[1] = fmaf(f.y, w1, p[1]);
            f = __half22float2(silu2(__hadd2(__floats2half2_rn(d[8 + i][0], d[8 + i][1]), cb)));
            p[2] = fmaf(f.x, w0, p[2]); p[2] = fmaf(f.y, w1, p[2]);
            f = __half22float2(silu2(__hadd2(__floats2half2_rn(d[8 + i][2], d[8 + i][3]), cb)));
            p[3] = fmaf(f.x, w0, p[3]); p[3] = fmaf(f.y, w1, p[3]);
        }
        #pragma unroll
        for (int j = 0; j < 4; j++) {
            p[j] += __shfl_xor_sync(0xffffffffu, p[j], 1);
            p[j] += __shfl_xor_sync(0xffffffffu, p[j], 2);
        }
        if (qk == 0) {
            #pragma unroll
            for (int j = 0; j < 4; j++)
                mpart[hf * 32 + qm + j * 8] = p[j];
        }
        bar_pair(barid);

        if (hf == 0 && qk == 0) {
            #pragma unroll
            for (int j = 0; j < 4; j++) {
                int row = qm + j * 8;
                if ((e0p + row) < E) {
                    float s = (mpart[row] + mpart[32 + row] + cb2v) * mirn[row];
                    int ri = mrow[row];
                    atomicAdd(&pos_out[ri * 3 + 0], s * mrx[row]);
                    atomicAdd(&pos_out[ri * 3 + 1], s * mry[row]);
                    atomicAdd(&pos_out[ri * 3 + 2], s * mrz[row]);
                }
            }
        }
    }
}

// ---------------------------------------------------------------------------
// node MLP (fp16 mma, persistent, 14 warps)
// ---------------------------------------------------------------------------
#define NODE_W  14
#define NODE_T  448
#define W1A_B   0
#define W1B_B   34816
#define W2N_B   69632
#define XT_B    104448                  // per warp: Xh +wid*8704, Xagg +wid*8704+4352
#define NB_B    (XT_B + NODE_W * 8704)  // 226304: nb1[128] f32, nb2[128] f32
#define NODE_SMEM (NB_B + 1024)         // 227328
__global__ __launch_bounds__(NODE_T) void node_kernel(
    const float* __restrict__ h,
    const float* __restrict__ nW1, const float* __restrict__ nb1,
    const float* __restrict__ nW2, const float* __restrict__ nb2,
    float* __restrict__ h_out, int N)
{
    extern __shared__ float smf[];
    char* smc = (char*)smf;
    unsigned sbase = smem_u32(smf);
    int tid = threadIdx.x, wid = tid >> 5, lane = tid & 31;
    int g = lane >> 3, l = lane & 7;
    int qm = lane >> 2, qk = lane & 3;
    float* nbf = (float*)(smc + NB_B);

    for (int idx = tid; idx < 32768; idx += NODE_T) {
        int k = idx >> 7, o = idx & 127;
        unsigned off = (unsigned)(o * 272 + (k & 127) * 2);
        *(__half*)(smc + (k < 128 ? W1A_B : W1B_B) + off) = __float2half_rn(nW1[idx]);
    }
    for (int idx = tid; idx < 16384; idx += NODE_T) {
        int k = idx >> 7, o = idx & 127;
        *(__half*)(smc + W2N_B + o * 272 + k * 2) = __float2half_rn(nW2[idx]);
    }
    for (int i = tid; i < 128; i += NODE_T) {
        nbf[i] = nb1[i];
        nbf[128 + i] = nb2[i];
    }
    __syncthreads();

    unsigned xh = sbase + XT_B + wid * 8704, xa = xh + 4352;
    unsigned w1a = sbase + W1A_B, w1b = sbase + W1B_B, w2 = sbase + W2N_B;
    unsigned aoff = (unsigned)((l + ((g & 1) << 3)) * 272 + (g >> 1) * 16);
    unsigned boff = (unsigned)((l + ((g >> 1) << 3)) * 272 + (g & 1) * 16);

    int ntiles = (N + NODE_W * 16 - 1) / (NODE_W * 16);
    for (int tb = blockIdx.x; tb < ntiles; tb += gridDim.x) {
        int n0w = tb * (NODE_W * 16) + wid * 16;
        if (n0w >= N) continue;

        #pragma unroll
        for (int row = 0; row < 16; row++) {
            int node = min(n0w + row, N - 1);
            float4 a = *(const float4*)(h + node * 128 + lane * 4);
            float4 b = *(const float4*)(g_agg + node * 128 + lane * 4);
            *(uint2*)(smc + (XT_B + wid * 8704) + row * 272 + lane * 8) =
                make_uint2(pack2h(a.x, a.y), pack2h(a.z, a.w));
            *(uint2*)(smc + (XT_B + wid * 8704 + 4352) + row * 272 + lane * 8) =
                make_uint2(pack2h(b.x, b.y), pack2h(b.z, b.w));
        }
        __syncwarp();

        float d[16][4];
        #pragma unroll
        for (int i = 0; i < 16; i++) { d[i][0] = d[i][1] = d[i][2] = d[i][3] = 0.f; }
        warp_gemm(xh, w1a, aoff, boff, d);
        warp_gemm(xa, w1b, aoff, boff, d);

        #pragma unroll
        for (int nt = 0; nt < 16; nt++) {
            int o0 = nt * 8 + qk * 2;
            float b0 = nbf[o0], b1 = nbf[o0 + 1];
            float v0 = silu(d[nt][0] + b0);
            float v1 = silu(d[nt][1] + b1);
            float v2 = silu(d[nt][2] + b0);
            float v3 = silu(d[nt][3] + b1);
            *(unsigned*)(smc + (XT_B + wid * 8704) + qm * 272 + o0 * 2) = pack2h(v0, v1);
            *(unsigned*)(smc + (XT_B + wid * 8704) + (qm + 8) * 272 + o0 * 2) = pack2h(v2, v3);
        }
        __syncwarp();

        #pragma unroll
        for (int i = 0; i < 16; i++) { d[i][0] = d[i][1] = d[i][2] = d[i][3] = 0.f; }
        warp_gemm(xh, w2, aoff, boff, d);

        int nd0 = n0w + qm, nd8 = n0w + qm + 8;
        #pragma unroll
        for (int nt = 0; nt < 16; nt++) {
            int o0 = nt * 8 + qk * 2;
            float b0 = nbf[128 + o0], b1 = nbf[128 + o0 + 1];
            if (nd0 < N) {
                float2 r = *(const float2*)(h + nd0 * 128 + o0);
                *(float2*)(h_out + nd0 * 128 + o0) = make_float2(d[nt][0] + b0 + r.x, d[nt][1] + b1 + r.y);
            }
            if (nd8 < N) {
                float2 r = *(const float2*)(h + nd8 * 128 + o0);
                *(float2*)(h_out + nd8 * 128 + o0) = make_float2(d[nt][2] + b0 + r.x, d[nt][3] + b1 + r.y);
            }
        }
        __syncwarp();
    }
}

// ---------------------------------------------------------------------------
extern "C" void kernel_launch(void* const* d_in, const int* in_sizes, int n_in,
                              void* d_out, int out_size)
{
    const float* h   = (const float*)d_in[0];
    const float* pos = (const float*)d_in[1];
    const float* ea  = (const float*)d_in[2];
    const void*  ei  = d_in[3];
    const float* eW1 = (const float*)d_in[4];
    const float* eb1 = (const float*)d_in[5];
    const float* eW2 = (const float*)d_in[6];
    const float* eb2 = (const float*)d_in[7];
    const float* nW1 = (const float*)d_in[8];
    const float* nb1 = (const float*)d_in[9];
    const float* nW2 = (const float*)d_in[10];
    const float* nb2 = (const float*)d_in[11];
    const float* cW1 = (const float*)d_in[12];
    const float* cb1 = (const float*)d_in[13];
    const float* cW2 = (const float*)d_in[14];
    const float* cb2 = (const float*)d_in[15];

    int N = in_sizes[0] / 128;
    int E = in_sizes[2];
    float* h_out   = (float*)d_out;
    float* pos_out = h_out + (size_t)N * 128;

    cudaFuncSetAttribute(pre_kernel,  cudaFuncAttributeMaxDynamicSharedMemorySize, PRE_SMEM2);
    cudaFuncSetAttribute(edge_kernel, cudaFuncAttributeMaxDynamicSharedMemorySize, EDGE_SMEM);
    cudaFuncSetAttribute(node_kernel, cudaFuncAttributeMaxDynamicSharedMemorySize, NODE_SMEM);

    int nsm = 148;
    cudaDeviceGetAttribute(&nsm, cudaDevAttrMultiProcessorCount, 0);

    int pre_tiles  = (N + 191) / 192;
    int node_tiles = (N + NODE_W * 16 - 1) / (NODE_W * 16);

    init_kernel<<<(N * 128 + 255) / 256, 256>>>(pos, pos_out, ei, N, E);
    pre_kernel<<<min(nsm, pre_tiles), 384, PRE_SMEM2>>>(h, eW1, N);
    edge_kernel<<<nsm, ETHREADS, EDGE_SMEM>>>(pos, ea, ei, eW1, eb1, eW2, eb2,
                                              cW1, cb1, cW2, cb2, pos_out, N, E);
    node_kernel<<<min(nsm, node_tiles), NODE_T, NODE_SMEM>>>(
        h, nW1, nb1, nW2, nb2, h_out, N);
}

// round 16
// speedup vs baseline: 7.1429x; 1.0030x over previous
#include <cuda_runtime.h>
#include <cuda_fp16.h>

#define ETHREADS 640
#define EWARPS   20
#define EPAIRS   10
#define TILE_E   (EPAIRS * 32)
#define NMAX 50000

// Scratch (device globals: allocation-free rule)
__device__ __half g_Ah[NMAX * 128];  // h @ eW1[0:128]   (fp16, gathered by row)
__device__ __half g_Bh[NMAX * 128];  // h @ eW1[128:256] (fp16, gathered by col)
__device__ float  g_agg[NMAX * 128]; // segment_sum(m2, row)
__device__ int    g_is64;            // edge_index dtype flag

__device__ __forceinline__ float tanh_a(float x) {
    float y; asm("tanh.approx.f32 %0, %1;" : "=f"(y) : "f"(x)); return y;
}
__device__ __forceinline__ float silu(float x) {
    return x * fmaf(0.5f, tanh_a(0.5f * x), 0.5f);
}
// packed half2 silu: x * (0.5*tanh(0.5x)+0.5), tanh via one f16x2 MUFU
__device__ __forceinline__ __half2 silu2(__half2 x) {
    const __half2 h05 = __float2half2_rn(0.5f);
    __half2 u = __hmul2(x, h05);
    unsigned t;
    asm("tanh.approx.f16x2 %0, %1;" : "=r"(t) : "r"(*(unsigned*)&u));
    return __hmul2(x, __hfma2(*(__half2*)&t, h05, h05));
}
__device__ __forceinline__ unsigned smem_u32(const void* p) {
    unsigned a;
    asm("{ .reg .u64 t; cvta.to.shared.u64 t, %1; cvt.u32.u64 %0, t; }" : "=r"(a) : "l"(p));
    return a;
}
__device__ __forceinline__ unsigned pack2h(float v0, float v1) {
    __half2 h = __floats2half2_rn(v0, v1);
    return *(unsigned*)&h;
}
__device__ __forceinline__ void ldsm4(unsigned r[4], unsigned addr) {
    asm volatile("ldmatrix.sync.aligned.m8n8.x4.shared.b16 {%0,%1,%2,%3}, [%4];"
                 : "=r"(r[0]), "=r"(r[1]), "=r"(r[2]), "=r"(r[3]) : "r"(addr));
}
__device__ __forceinline__ void mma_f16(float d[4], const unsigned a[4], unsigned b0, unsigned b1) {
    asm volatile("mma.sync.aligned.m16n8k16.row.col.f32.f16.f16.f32 "
                 "{%0,%1,%2,%3}, {%4,%5,%6,%7}, {%8,%9}, {%0,%1,%2,%3};"
                 : "+f"(d[0]), "+f"(d[1]), "+f"(d[2]), "+f"(d[3])
                 : "r"(a[0]), "r"(a[1]), "r"(a[2]), "r"(a[3]), "r"(b0), "r"(b1));
}
__device__ __forceinline__ void red2(float* p, float v0, float v1) {
    asm volatile("red.global.add.v2.f32 [%0], {%1, %2};" :: "l"(p), "f"(v0), "f"(v1) : "memory");
}
__device__ __forceinline__ void bar_pair(int id) {
    asm volatile("bar.sync %0, 64;" :: "r"(id) : "memory");
}

// M=16 warp GEMM: 16 x 128 x 128 fp16 (fp32 accum). A row stride 272B. (pre)
__device__ __forceinline__ void warp_gemm(unsigned aT, unsigned bT,
                                          unsigned aoff, unsigned boff, float (*d)[4]) {
    #pragma unroll
    for (int ks = 0; ks < 8; ks++) {
        unsigned ah[4];
        ldsm4(ah, aT + aoff + ks * 32);
        #pragma unroll
        for (int np = 0; np < 8; np++) {
            unsigned bh[4];
            ldsm4(bh, bT + boff + np * 4352 + ks * 32);
            mma_f16(d[np * 2],     ah, bh[0], bh[1]);
            mma_f16(d[np * 2 + 1], ah, bh[2], bh[3]);
        }
    }
}

// M=32, N=64 warp GEMM (one N-half starting at nbase). A tile: 32 rows x 272B.
__device__ __forceinline__ void warp_gemm32(unsigned aT, unsigned bT,
                                            unsigned aoff, unsigned boff,
                                            int nbase, float (*d)[4]) {
    #pragma unroll
    for (int ks = 0; ks < 8; ks++) {
        unsigned a0[4], a1[4];
        ldsm4(a0, aT + aoff + ks * 32);
        ldsm4(a1, aT + aoff + 16 * 272 + ks * 32);
        #pragma unroll
        for (int s = 0; s < 4; s++) {
            unsigned bh[4];
            ldsm4(bh, bT + boff + (unsigned)(nbase + s * 16) * 272 + ks * 32);
            mma_f16(d[s * 2],         a0, bh[0], bh[1]);
            mma_f16(d[s * 2 + 1],     a0, bh[2], bh[3]);
            mma_f16(d[8 + s * 2],     a1, bh[0], bh[1]);
            mma_f16(d[8 + s * 2 + 1], a1, bh[2], bh[3]);
        }
    }
}

// SMEM byte layout for edge kernel
#define EB2H_B 3200                      // eb2 as fp16 [128]
#define W2HI_B 4096
#define C1HI_B 38912
#define AT_B   73728                     // EPAIRS x 8704 (32 rows x 272B)
#define META_B (AT_B + EPAIRS * 8704)    // per pair 1024B: rowi/irn/rx/ry/rz/part
#define EDGE_SMEM (META_B + EPAIRS * 1024)   // 171008

// ---------------------------------------------------------------------------
// init (+ edge_index dtype detect in block 0)
// ---------------------------------------------------------------------------
__global__ void init_kernel(const float* __restrict__ pos, float* __restrict__ pos_out,
                            const void* __restrict__ ei, int N, int E) {
    int i = blockIdx.x * blockDim.x + threadIdx.x;
    if (i < N * 128) g_agg[i] = 0.0f;
    if (i < N * 3) pos_out[i] = pos[i];
    if (blockIdx.x == 0) {
        __shared__ int ok;
        if (threadIdx.x == 0) ok = 1;
        __syncthreads();
        int n = (E < 256) ? E : 256;
        if ((int)threadIdx.x < n) {
            long long v = ((const long long*)ei)[threadIdx.x];
            if (v < 0 || v >= (long long)N) atomicExch(&ok, 0);
        }
        __syncthreads();
        if (threadIdx.x == 0) g_is64 = ok;
    }
}

// ---------------------------------------------------------------------------
// precompute (fp16 mma, persistent): A = h @ eW1[0:128,:], B = h @ eW1[128:256,:]
// ---------------------------------------------------------------------------
#define PRE_SMEM2 121856   // W0 34816 | W1 34816 | X tiles 12*4352
__global__ __launch_bounds__(384) void pre_kernel(
    const float* __restrict__ h, const float* __restrict__ eW1, int N)
{
    extern __shared__ float smf[];
    char* smc = (char*)smf;
    unsigned sbase = smem_u32(smf);
    int tid = threadIdx.x, wid = tid >> 5, lane = tid & 31;
    int g = lane >> 3, l = lane & 7;
    int qm = lane >> 2, qk = lane & 3;

    for (int idx = tid; idx < 32768; idx += 384) {
        int k = idx >> 7, o = idx & 127;
        *(__half*)(smc + (k < 128 ? 0 : 34816) + o * 272 + (k & 127) * 2) =
            __float2half_rn(eW1[idx]);
    }
    __syncthreads();

    unsigned xT = sbase + 69632 + wid * 4352;
    unsigned aoff = (unsigned)((l + ((g & 1) << 3)) * 272 + (g >> 1) * 16);
    unsigned boff = (unsigned)((l + ((g >> 1) << 3)) * 272 + (g & 1) * 16);

    int ntiles = (N + 191) / 192;
    for (int tb = blockIdx.x; tb < ntiles; tb += gridDim.x) {
        int n0w = tb * 192 + wid * 16;
        if (n0w >= N) continue;

        #pragma unroll
        for (int row = 0; row < 16; row++) {
            int node = min(n0w + row, N - 1);
            float4 a = *(const float4*)(h + node * 128 + lane * 4);
            *(uint2*)(smc + (69632 + wid * 4352) + row * 272 + lane * 8) =
                make_uint2(pack2h(a.x, a.y), pack2h(a.z, a.w));
        }
        __syncwarp();

        int nd0 = n0w + qm, nd8 = n0w + qm + 8;
        float d[16][4];
        #pragma unroll
        for (int i = 0; i < 16; i++) { d[i][0] = d[i][1] = d[i][2] = d[i][3] = 0.f; }
        warp_gemm(xT, sbase + 0, aoff, boff, d);
        #pragma unroll
        for (int nt = 0; nt < 16; nt++) {
            int o0 = nt * 8 + qk * 2;
            if (nd0 < N) *(unsigned*)((char*)g_Ah + nd0 * 256 + o0 * 2) = pack2h(d[nt][0], d[nt][1]);
            if (nd8 < N) *(unsigned*)((char*)g_Ah + nd8 * 256 + o0 * 2) = pack2h(d[nt][2], d[nt][3]);
        }
        #pragma unroll
        for (int i = 0; i < 16; i++) { d[i][0] = d[i][1] = d[i][2] = d[i][3] = 0.f; }
        warp_gemm(xT, sbase + 34816, aoff, boff, d);
        #pragma unroll
        for (int nt = 0; nt < 16; nt++) {
            int o0 = nt * 8 + qk * 2;
            if (nd0 < N) *(unsigned*)((char*)g_Bh + nd0 * 256 + o0 * 2) = pack2h(d[nt][0], d[nt][1]);
            if (nd8 < N) *(unsigned*)((char*)g_Bh + nd8 * 256 + o0 * 2) = pack2h(d[nt][2], d[nt][3]);
        }
        __syncwarp();
    }
}

// ---------------------------------------------------------------------------
// fused edge kernel: warp-PAIR M=32/N=64 fp16 mma + half2 scalar pipeline
// ---------------------------------------------------------------------------
__global__ __launch_bounds__(ETHREADS) void edge_kernel(
    const float* __restrict__ pos, const float* __restrict__ edge_attr,
    const void* __restrict__ ei_raw,
    const float* __restrict__ eW1, const float* __restrict__ eb1,
    const float* __restrict__ eW2, const float* __restrict__ eb2,
    const float* __restrict__ cW1, const float* __restrict__ cb1,
    const float* __restrict__ cW2, const float* __restrict__ cb2,
    float* __restrict__ pos_out, int N, int E)
{
    extern __shared__ float smf[];
    char* smc = (char*)smf;
    unsigned sbase = smem_u32(smf);
    int tid = threadIdx.x, wid = tid >> 5, lane = tid & 31;
    int g = lane >> 3, l = lane & 7;
    int qm = lane >> 2, qk = lane & 3;
    int pr = wid >> 1, hf = wid & 1;
    int barid = 1 + pr;

    // sv: w_rn 0, w_ea 128, eb1 256, eb2 384, cb1 512, cw2 640, cb2 768
    float* sv = smf;
    for (int i = tid; i < 128; i += ETHREADS) {
        sv[i]       = eW1[256 * 128 + i];
        sv[128 + i] = eW1[257 * 128 + i];
        sv[256 + i] = eb1[i];
        float e2 = eb2[i];
        sv[384 + i] = e2;
        sv[512 + i] = cb1[i];
        sv[640 + i] = cW2[i];
        *(__half*)(smc + EB2H_B + i * 2) = __float2half_rn(e2);
    }
    if (tid == 0) sv[768] = cb2[0];

    for (int idx = tid; idx < 16384; idx += ETHREADS) {
        int k = idx >> 7, o = idx & 127;
        unsigned off = (unsigned)(o * 272 + k * 2);
        *(__half*)(smc + W2HI_B + off) = __float2half_rn(eW2[idx]);
        *(__half*)(smc + C1HI_B + off) = __float2half_rn(cW1[idx]);
    }
    __syncthreads();

    float cb2v = sv[768];
    int is64 = g_is64;
    const long long* ei64 = (const long long*)ei_raw;
    const int*       ei32 = (const int*)ei_raw;

    __half2 wr01 = __floats2half2_rn(sv[lane * 4 + 0], sv[lane * 4 + 1]);
    __half2 wr23 = __floats2half2_rn(sv[lane * 4 + 2], sv[lane * 4 + 3]);
    __half2 we01 = __floats2half2_rn(sv[128 + lane * 4 + 0], sv[128 + lane * 4 + 1]);
    __half2 we23 = __floats2half2_rn(sv[128 + lane * 4 + 2], sv[128 + lane * 4 + 3]);
    __half2 bi01 = __floats2half2_rn(sv[256 + lane * 4 + 0], sv[256 + lane * 4 + 1]);
    __half2 bi23 = __floats2half2_rn(sv[256 + lane * 4 + 2], sv[256 + lane * 4 + 3]);

    unsigned atb = (unsigned)(AT_B + pr * 8704);
    unsigned aT = sbase + atb;
    unsigned bW2h = sbase + W2HI_B;
    unsigned bC1h = sbase + C1HI_B;
    unsigned aoff = (unsigned)((l + ((g & 1) << 3)) * 272 + (g >> 1) * 16);
    unsigned boff = (unsigned)((l + ((g >> 1) << 3)) * 272 + (g & 1) * 16);
    int nbase = hf * 64;

    char* metab = smc + META_B + pr * 1024;
    int*   mrow = (int*)metab;
    float* mirn = (float*)(metab + 128);
    float* mrx  = (float*)(metab + 256);
    float* mry  = (float*)(metab + 384);
    float* mrz  = (float*)(metab + 512);
    float* mpart = (float*)(metab + 640);

    int ntiles = (E + TILE_E - 1) / TILE_E;
    for (int t = blockIdx.x; t < ntiles; t += gridDim.x) {
        int e0p = t * TILE_E + pr * 32;

        bar_pair(barid);

        int m_r = 0, m_c = 0;
        float m_rn = 1.0f, m_ea = 0.0f;
        if (lane < 16) {
            int row = hf * 16 + lane;
            int e = e0p + row;
            int r = 0, c = 0;
            float dx = 0.f, dy = 0.f, dz = 0.f, rn = 1.0f, irn = 1.0f, eav = 0.f;
            if (e < E) {
                if (is64) { r = (int)ei64[e]; c = (int)ei64[E + e]; }
                else      { r = ei32[e];      c = ei32[E + e]; }
                r = min(max(r, 0), N - 1);
                c = min(max(c, 0), N - 1);
                dx = pos[r * 3 + 0] - pos[c * 3 + 0];
                dy = pos[r * 3 + 1] - pos[c * 3 + 1];
                dz = pos[r * 3 + 2] - pos[c * 3 + 2];
                float nrm = sqrtf(dx * dx + dy * dy + dz * dz);
                rn = fmaxf(nrm, 1e-8f);
                irn = 1.0f / rn;
                eav = edge_attr[e];
            }
            m_r = r; m_c = c; m_rn = rn; m_ea = eav;
            mrow[row] = r; mirn[row] = irn;
            mrx[row] = dx; mry[row] = dy; mrz[row] = dz;
        }

        #pragma unroll
        for (int rr = 0; rr < 16; rr++) {
            int rsrc = __shfl_sync(0xffffffffu, m_r, rr);
            int csrc = __shfl_sync(0xffffffffu, m_c, rr);
            float rnf = __shfl_sync(0xffffffffu, m_rn, rr);
            float eaf = __shfl_sync(0xffffffffu, m_ea, rr);
            __half2 rn2 = __float2half2_rn(rnf);
            __half2 ea2 = __float2half2_rn(eaf);
            uint2 av = *(const uint2*)((const char*)g_Ah + rsrc * 256 + lane * 8);
            uint2 bv = *(const uint2*)((const char*)g_Bh + csrc * 256 + lane * 8);
            __half2 x01 = __hadd2(__hfma2(rn2, wr01, __hadd2(*(__half2*)&av.x, *(__half2*)&bv.x)),
                                  __hfma2(ea2, we01, bi01));
            __half2 x23 = __hadd2(__hfma2(rn2, wr23, __hadd2(*(__half2*)&av.y, *(__half2*)&bv.y)),
                                  __hfma2(ea2, we23, bi23));
            __half2 v01 = silu2(x01), v23 = silu2(x23);
            *(uint2*)(smc + atb + (hf * 16 + rr) * 272 + lane * 8) =
                make_uint2(*(unsigned*)&v01, *(unsigned*)&v23);
        }
        bar_pair(barid);

        float d[16][4];
        #pragma unroll
        for (int i = 0; i < 16; i++) { d[i][0] = d[i][1] = d[i][2] = d[i][3] = 0.f; }
        warp_gemm32(aT, bW2h, aoff, boff, nbase, d);

        bar_pair(barid);

        int r0 = mrow[qm], r1 = mrow[qm + 8], r2 = mrow[qm + 16], r3 = mrow[qm + 24];
        bool k0 = (e0p + qm) < E, k1 = (e0p + qm + 8) < E;
        bool k2 = (e0p + qm + 16) < E, k3 = (e0p + qm + 24) < E;
        #pragma unroll
        for (int s = 0; s < 4; s++)
        #pragma unroll
        for (int hh = 0; hh < 2; hh++) {
            int i = s * 2 + hh;
            int c0 = nbase + s * 16 + hh * 8 + qk * 2;
            __half2 eb = *(__half2*)(smc + EB2H_B + c0 * 2);
            __half2 v01 = silu2(__hadd2(__floats2half2_rn(d[i][0], d[i][1]), eb));
            __half2 v23 = silu2(__hadd2(__floats2half2_rn(d[i][2], d[i][3]), eb));
            __half2 u01 = silu2(__hadd2(__floats2half2_rn(d[8 + i][0], d[8 + i][1]), eb));
            __half2 u23 = silu2(__hadd2(__floats2half2_rn(d[8 + i][2], d[8 + i][3]), eb));
            *(unsigned*)(smc + atb + qm * 272 + c0 * 2) = *(unsigned*)&v01;
            *(unsigned*)(smc + atb + (qm + 8) * 272 + c0 * 2) = *(unsigned*)&v23;
            *(unsigned*)(smc + atb + (qm + 16) * 272 + c0 * 2) = *(unsigned*)&u01;
            *(unsigned*)(smc + atb + (qm + 24) * 272 + c0 * 2) = *(unsigned*)&u23;
            if (k0) { float2 f = __half22float2(v01); red2(g_agg + r0 * 128 + c0, f.x, f.y); }
            if (k1) { float2 f = __half22float2(v23); red2(g_agg + r1 * 128 + c0, f.x, f.y); }
            if (k2) { float2 f = __half22float2(u01); red2(g_agg + r2 * 128 + c0, f.x, f.y); }
            if (k3) { float2 f = __half22float2(u23); red2(g_agg + r3 * 128 + c0, f.x, f.y); }
        }
        bar_pair(barid);

        #pragma unroll
        for (int i = 0; i < 16; i++) { d[i][0] = d[i][1] = d[i][2] = d[i][3] = 0.f; }
        warp_gemm32(aT, bC1h, aoff, boff, nbase, d);

        float p[4] = {0.f, 0.f, 0.f, 0.f};
        #pragma unroll
        for (int s = 0; s < 4; s++)
        #pragma unroll
        for (int hh = 0; hh < 2; hh++) {
            int i = s * 2 + hh;
            int c0 = nbase + s * 16 + hh * 8 + qk * 2;
            __half2 cb = __floats2half2_rn(sv[512 + c0], sv[512 + c0 + 1]);
            float w0 = sv[640 + c0], w1 = sv[640 + c0 + 1];
            float2 f;
            f = __half22float2(silu2(__hadd2(__floats2half2_rn(d[i][0], d[i][1]), cb)));
            p[0] = fmaf(f.x, w0, p[0]); p[0] = fmaf(f.y, w1, p[0]);
            f = __half22float2(silu2(__hadd2(__floats2half2_rn(d[i][2], d[i][3]), cb)));
            p[1] = fmaf(f.x, w0, p[1]); p[1] = fmaf(f.y, w1, p[1]);
            f = __half22float2(silu2(__hadd2(__floats2half2_rn(d[8 + i][0], d[8 + i][1]), cb)));
            p[2] = fmaf(f.x, w0, p[2]); p[2] = fmaf(f.y, w1, p[2]);
            f = __half22float2(silu2(__hadd2(__floats2half2_rn(d[8 + i][2], d[8 + i][3]), cb)));
            p[3] = fmaf(f.x, w0, p[3]); p[3] = fmaf(f.y, w1, p[3]);
        }
        #pragma unroll
        for (int j = 0; j < 4; j++) {
            p[j] += __shfl_xor_sync(0xffffffffu, p[j], 1);
            p[j] += __shfl_xor_sync(0xffffffffu, p[j], 2);
        }
        if (qk == 0) {
            #pragma unroll
            for (int j = 0; j < 4; j++)
                mpart[hf * 32 + qm + j * 8] = p[j];
        }
        bar_pair(barid);

        if (hf == 0 && qk == 0) {
            #pragma unroll
            for (int j = 0; j < 4; j++) {
                int row = qm + j * 8;
                if ((e0p + row) < E) {
                    float s = (mpart[row] + mpart[32 + row] + cb2v) * mirn[row];
                    int ri = mrow[row];
                    atomicAdd(&pos_out[ri * 3 + 0], s * mrx[row]);
                    atomicAdd(&pos_out[ri * 3 + 1], s * mry[row]);
                    atomicAdd(&pos_out[ri * 3 + 2], s * mrz[row]);
                }
            }
        }
    }
}

// ---------------------------------------------------------------------------
// node MLP (fp16 mma, warp-PAIR M=32/N=64, persistent)
// hn = silu([h,agg]@nW1+nb1); h_new = h + hn@nW2+nb2
// ---------------------------------------------------------------------------
#define NODE_W  14
#define NODE_T  448
#define NODE_P  7
#define W1A_B   0
#define W1B_B   34816
#define W2N_B   69632
#define XT_B    104448                  // per pair: Xh +pr*17408, Xagg +pr*17408+8704
#define NB_B    (XT_B + NODE_P * 17408) // 226304: nb1[128] f32, nb2[128] f32
#define NODE_SMEM (NB_B + 1024)         // 227328
__global__ __launch_bounds__(NODE_T) void node_kernel(
    const float* __restrict__ h,
    const float* __restrict__ nW1, const float* __restrict__ nb1,
    const float* __restrict__ nW2, const float* __restrict__ nb2,
    float* __restrict__ h_out, int N)
{
    extern __shared__ float smf[];
    char* smc = (char*)smf;
    unsigned sbase = smem_u32(smf);
    int tid = threadIdx.x, wid = tid >> 5, lane = tid & 31;
    int g = lane >> 3, l = lane & 7;
    int qm = lane >> 2, qk = lane & 3;
    int pr = wid >> 1, hf = wid & 1;
    int barid = 1 + pr;
    float* nbf = (float*)(smc + NB_B);

    for (int idx = tid; idx < 32768; idx += NODE_T) {
        int k = idx >> 7, o = idx & 127;
        unsigned off = (unsigned)(o * 272 + (k & 127) * 2);
        *(__half*)(smc + (k < 128 ? W1A_B : W1B_B) + off) = __float2half_rn(nW1[idx]);
    }
    for (int idx = tid; idx < 16384; idx += NODE_T) {
        int k = idx >> 7, o = idx & 127;
        *(__half*)(smc + W2N_B + o * 272 + k * 2) = __float2half_rn(nW2[idx]);
    }
    for (int i = tid; i < 128; i += NODE_T) {
        nbf[i] = nb1[i];
        nbf[128 + i] = nb2[i];
    }
    __syncthreads();

    unsigned xh = sbase + XT_B + pr * 17408, xa = xh + 8704;
    unsigned w1a = sbase + W1A_B, w1b = sbase + W1B_B, w2 = sbase + W2N_B;
    unsigned aoff = (unsigned)((l + ((g & 1) << 3)) * 272 + (g >> 1) * 16);
    unsigned boff = (unsigned)((l + ((g >> 1) << 3)) * 272 + (g & 1) * 16);
    int nbase = hf * 64;

    int ntiles = (N + NODE_P * 32 - 1) / (NODE_P * 32);
    for (int tb = blockIdx.x; tb < ntiles; tb += gridDim.x) {
        int n0p = tb * (NODE_P * 32) + pr * 32;
        if (n0p >= N) continue;      // pair-uniform

        bar_pair(barid);             // protect tiles from prev-iter readers

        // load this warp's 16 rows (hf*16..+15) of h and agg -> fp16 tiles
        #pragma unroll
        for (int rr = 0; rr < 16; rr++) {
            int row = hf * 16 + rr;
            int node = min(n0p + row, N - 1);
            float4 a = *(const float4*)(h + node * 128 + lane * 4);
            float4 b = *(const float4*)(g_agg + node * 128 + lane * 4);
            *(uint2*)(smc + (XT_B + pr * 17408) + row * 272 + lane * 8) =
                make_uint2(pack2h(a.x, a.y), pack2h(a.z, a.w));
            *(uint2*)(smc + (XT_B + pr * 17408 + 8704) + row * 272 + lane * 8) =
                make_uint2(pack2h(b.x, b.y), pack2h(b.z, b.w));
        }
        bar_pair(barid);             // both halves of X visible

        // GEMM1: D = h@nW1a + agg@nW1b  (this warp's 64 cols, 32 rows)
        float d[16][4];
        #pragma unroll
        for (int i = 0; i < 16; i++) { d[i][0] = d[i][1] = d[i][2] = d[i][3] = 0.f; }
        warp_gemm32(xh, w1a, aoff, boff, nbase, d);
        warp_gemm32(xa, w1b, aoff, boff, nbase, d);

        bar_pair(barid);             // both warps done reading X

        // epilogue1: hn = silu(D + nb1) -> Xh cols [nbase, nbase+64)
        #pragma unroll
        for (int s = 0; s < 4; s++)
        #pragma unroll
        for (int hh = 0; hh < 2; hh++) {
            int i = s * 2 + hh;
            int c0 = nbase + s * 16 + hh * 8 + qk * 2;
            float b0 = nbf[c0], b1 = nbf[c0 + 1];
            *(unsigned*)(smc + (XT_B + pr * 17408) + qm * 272 + c0 * 2) =
                pack2h(silu(d[i][0] + b0), silu(d[i][1] + b1));
            *(unsigned*)(smc + (XT_B + pr * 17408) + (qm + 8) * 272 + c0 * 2) =
                pack2h(silu(d[i][2] + b0), silu(d[i][3] + b1));
            *(unsigned*)(smc + (XT_B + pr * 17408) + (qm + 16) * 272 + c0 * 2) =
                pack2h(silu(d[8 + i][0] + b0), silu(d[8 + i][1] + b1));
            *(unsigned*)(smc + (XT_B + pr * 17408) + (qm + 24) * 272 + c0 * 2) =
                pack2h(silu(d[8 + i][2] + b0), silu(d[8 + i][3] + b1));
        }
        bar_pair(barid);             // full hn tile visible

        // GEMM2: D = hn @ nW2 (this warp's 64 cols)
        #pragma unroll
        for (int i = 0; i < 16; i++) { d[i][0] = d[i][1] = d[i][2] = d[i][3] = 0.f; }
        warp_gemm32(xh, w2, aoff, boff, nbase, d);

        // epilogue2: h_out = D + nb2 + h (residual), this warp's 64 cols
        int n0 = n0p + qm, n1 = n0p + qm + 8, n2 = n0p + qm + 16, n3 = n0p + qm + 24;
        #pragma unroll
        for (int s = 0; s < 4; s++)
        #pragma unroll
        for (int hh = 0; hh < 2; hh++) {
            int i = s * 2 + hh;
            int c0 = nbase + s * 16 + hh * 8 + qk * 2;
            float b0 = nbf[128 + c0], b1 = nbf[128 + c0 + 1];
            if (n0 < N) {
                float2 r = *(const float2*)(h + n0 * 128 + c0);
                *(float2*)(h_out + n0 * 128 + c0) = make_float2(d[i][0] + b0 + r.x, d[i][1] + b1 + r.y);
            }
            if (n1 < N) {
                float2 r = *(const float2*)(h + n1 * 128 + c0);
                *(float2*)(h_out + n1 * 128 + c0) = make_float2(d[i][2] + b0 + r.x, d[i][3] + b1 + r.y);
            }
            if (n2 < N) {
                float2 r = *(const float2*)(h + n2 * 128 + c0);
                *(float2*)(h_out + n2 * 128 + c0) = make_float2(d[8 + i][0] + b0 + r.x, d[8 + i][1] + b1 + r.y);
            }
            if (n3 < N) {
                float2 r = *(const float2*)(h + n3 * 128 + c0);
                *(float2*)(h_out + n3 * 128 + c0) = make_float2(d[8 + i][2] + b0 + r.x, d[8 + i][3] + b1 + r.y);
            }
        }
    }
}

// ---------------------------------------------------------------------------
extern "C" void kernel_launch(void* const* d_in, const int* in_sizes, int n_in,
                              void* d_out, int out_size)
{
    const float* h   = (const float*)d_in[0];
    const float* pos = (const float*)d_in[1];
    const float* ea  = (const float*)d_in[2];
    const void*  ei  = d_in[3];
    const float* eW1 = (const float*)d_in[4];
    const float* eb1 = (const float*)d_in[5];
    const float* eW2 = (const float*)d_in[6];
    const float* eb2 = (const float*)d_in[7];
    const float* nW1 = (const float*)d_in[8];
    const float* nb1 = (const float*)d_in[9];
    const float* nW2 = (const float*)d_in[10];
    const float* nb2 = (const float*)d_in[11];
    const float* cW1 = (const float*)d_in[12];
    const float* cb1 = (const float*)d_in[13];
    const float* cW2 = (const float*)d_in[14];
    const float* cb2 = (const float*)d_in[15];

    int N = in_sizes[0] / 128;
    int E = in_sizes[2];
    float* h_out   = (float*)d_out;
    float* pos_out = h_out + (size_t)N * 128;

    cudaFuncSetAttribute(pre_kernel,  cudaFuncAttributeMaxDynamicSharedMemorySize, PRE_SMEM2);
    cudaFuncSetAttribute(edge_kernel, cudaFuncAttributeMaxDynamicSharedMemorySize, EDGE_SMEM);
    cudaFuncSetAttribute(node_kernel, cudaFuncAttributeMaxDynamicSharedMemorySize, NODE_SMEM);

    int nsm = 148;
    cudaDeviceGetAttribute(&nsm, cudaDevAttrMultiProcessorCount, 0);

    int pre_tiles  = (N + 191) / 192;
    int node_tiles = (N + NODE_P * 32 - 1) / (NODE_P * 32);

    init_kernel<<<(N * 128 + 255) / 256, 256>>>(pos, pos_out, ei, N, E);
    pre_kernel<<<min(nsm, pre_tiles), 384, PRE_SMEM2>>>(h, eW1, N);
    edge_kernel<<<nsm, ETHREADS, EDGE_SMEM>>>(pos, ea, ei, eW1, eb1, eW2, eb2,
                                              cW1, cb1, cW2, cb2, pos_out, N, E);
    node_kernel<<<min(nsm, node_tiles), NODE_T, NODE_SMEM>>>(
        h, nW1, nb1, nW2, nb2, h_out, N);
}